// round 10
// baseline (speedup 1.0000x reference)
#include <cuda_runtime.h>
#include <cuda_bf16.h>
#include <cstdint>
#include <math.h>

#define NN 10000
#define EE 320000
#define DD 128
#define NTILE_N 79      /* (NN+127)/128 */
#define NTILE_E 2500    /* EE/128 */
#define GRID_P 296      /* persistent grid: 148 SMs x 2 CTAs */

// ================= static device scratch =================
__device__ float g_proj[9][NN * DD];     // V1h V2h P1h P2h P3h D1h D2h ThA ThB
__device__ float g_enew[(size_t)EE * DD];
__device__ float g_enorm[EE];
__device__ float g_facc[NN * DD];
__device__ int   g_cnt0[NN];
__device__ int   g_mlist[EE];
__device__ int   g_mcount;
__device__ float g_bzero[DD];            // stays zero (module-load init)
// pre-split weight tiles in swizzled layout (32KB each):
// slots 0..6 node W (V1,V2,P1,P2,P3,D1,D2), 7 E1, 8 V, 9/10 = W_T halves
__device__ __align__(16) unsigned char g_wbh[11 * 32768];
__device__ __align__(16) unsigned char g_wbl[11 * 32768];

__device__ __forceinline__ float lrelu(float x) { return x > 0.f ? x : 0.01f * x; }
__device__ __forceinline__ float relu_(float x) { return x > 0.f ? x : 0.f; }

__device__ __forceinline__ uint32_t smem_u32(const void* p) {
    uint32_t a;
    asm("{ .reg .u64 t; cvta.to.shared.u64 t, %1; cvt.u32.u64 %0, t; }" : "=r"(a) : "l"(p));
    return a;
}
__device__ __forceinline__ uint32_t pack2(__nv_bfloat16 a, __nv_bfloat16 b) {
    __nv_bfloat162 t; t.x = a; t.y = b;
    return *reinterpret_cast<uint32_t*>(&t);
}

// swizzled byte offset inside a 128x128 bf16 tile (B tiles): row stride 256B
__device__ __forceinline__ uint32_t soff(int r, int c) {
    return (uint32_t)((r << 8) + ((((c >> 3) ^ (r & 7)) << 4) | ((c & 7) << 1)));
}
// swizzled byte offset inside a 128x64 bf16 tile (A half-tiles): row stride 128B
__device__ __forceinline__ uint32_t soff64(int r, int c) {
    return (uint32_t)((r << 7) + (((((c >> 3) ^ (r & 7)) & 7) << 4) | ((c & 7) << 1)));
}

__device__ __forceinline__ void ldsm4(uint32_t* r, uint32_t addr) {
    asm volatile("ldmatrix.sync.aligned.m8n8.x4.shared.b16 {%0,%1,%2,%3}, [%4];"
                 : "=r"(r[0]), "=r"(r[1]), "=r"(r[2]), "=r"(r[3]) : "r"(addr));
}
__device__ __forceinline__ void mma16816(float* d, const uint32_t* a,
                                         uint32_t b0, uint32_t b1) {
    asm volatile(
        "mma.sync.aligned.m16n8k16.row.col.f32.bf16.bf16.f32 "
        "{%0,%1,%2,%3}, {%4,%5,%6,%7}, {%8,%9}, {%0,%1,%2,%3};"
        : "+f"(d[0]), "+f"(d[1]), "+f"(d[2]), "+f"(d[3])
        : "r"(a[0]), "r"(a[1]), "r"(a[2]), "r"(a[3]), "r"(b0), "r"(b1));
}

// split 8 fp32 -> hi/lo bf16x2 quads
__device__ __forceinline__ void cvt8(float4 v0, float4 v1, uint4& hi, uint4& lo) {
    __nv_bfloat16 a0 = __float2bfloat16(v0.x), a1 = __float2bfloat16(v0.y);
    __nv_bfloat16 a2 = __float2bfloat16(v0.z), a3 = __float2bfloat16(v0.w);
    __nv_bfloat16 a4 = __float2bfloat16(v1.x), a5 = __float2bfloat16(v1.y);
    __nv_bfloat16 a6 = __float2bfloat16(v1.z), a7 = __float2bfloat16(v1.w);
    hi.x = pack2(a0, a1); hi.y = pack2(a2, a3);
    hi.z = pack2(a4, a5); hi.w = pack2(a6, a7);
    lo.x = pack2(__float2bfloat16(v0.x - __bfloat162float(a0)),
                 __float2bfloat16(v0.y - __bfloat162float(a1)));
    lo.y = pack2(__float2bfloat16(v0.z - __bfloat162float(a2)),
                 __float2bfloat16(v0.w - __bfloat162float(a3)));
    lo.z = pack2(__float2bfloat16(v1.x - __bfloat162float(a4)),
                 __float2bfloat16(v1.y - __bfloat162float(a5)));
    lo.w = pack2(__float2bfloat16(v1.z - __bfloat162float(a6)),
                 __float2bfloat16(v1.w - __bfloat162float(a7)));
}

// shared memory layout (102400 bytes -> 2 CTAs/SM)
#define SM_BIAS 0
#define SM_ROWA 512
#define SM_ROWB 1024
#define SM_ROWC 1536
#define SM_SV   2048
#define SM_AH   4096                 /* 128x64 bf16 hi (16KB) */
#define SM_AL   (4096 + 16384)       /* 128x64 bf16 lo (16KB) */
#define SM_BH   (4096 + 32768)       /* 128x128 bf16 hi (32KB) RESIDENT */
#define SM_BL   (4096 + 65536)       /* 128x128 bf16 lo (32KB) RESIDENT */
#define SM_C    4096                 /* fp32 C 64rows x 512B, overlays A only */
#define SM_TOTAL (4096 + 98304)

// C chunk-swizzled offset: local row r (0..63), float4-chunk c4 (0..31)
__device__ __forceinline__ uint32_t coff(int r, int c4) {
    return (uint32_t)(SM_C + r * 512 + (((c4 ^ (r & 7)) & 31) << 4));
}

// ---- 3-term split GEMM over one K-half, warp tile 32(M) x 64(N), 8 warps ----
__device__ __forceinline__ void gemm_half(uint32_t smb, int lane, int wm, int wn,
                                          int kh, float (&acc)[2][8][4]) {
    const int fr = lane & 15;
    const int fc = (lane >> 4) << 3;
    const int m0 = wm * 32;
    const int n0 = wn * 64;
#pragma unroll
    for (int ks = 0; ks < 4; ks++) {
        const int kc = kh * 64 + ks * 16 + fc;
        uint32_t aH[2][4], aL[2][4];
        uint32_t bH[2][4], bL[2][4];
        ldsm4(aH[0], smb + SM_AH + soff64(m0 + fr, ks * 16 + fc));
        ldsm4(aH[1], smb + SM_AH + soff64(m0 + 16 + fr, ks * 16 + fc));
        ldsm4(bH[0], smb + SM_BH + soff(n0 + fr, kc));
        ldsm4(bL[0], smb + SM_BL + soff(n0 + fr, kc));
        ldsm4(aL[0], smb + SM_AL + soff64(m0 + fr, ks * 16 + fc));
        ldsm4(aL[1], smb + SM_AL + soff64(m0 + 16 + fr, ks * 16 + fc));
        int cur = 0;
#pragma unroll
        for (int bn = 0; bn < 4; bn++) {
            int nxt = cur ^ 1;
            if (bn < 3) {
                ldsm4(bH[nxt], smb + SM_BH + soff(n0 + (bn + 1) * 16 + fr, kc));
                ldsm4(bL[nxt], smb + SM_BL + soff(n0 + (bn + 1) * 16 + fr, kc));
            }
#pragma unroll
            for (int mf = 0; mf < 2; mf++) {
                mma16816(acc[mf][2 * bn],     aH[mf], bH[cur][0], bH[cur][2]);
                mma16816(acc[mf][2 * bn + 1], aH[mf], bH[cur][1], bH[cur][3]);
                mma16816(acc[mf][2 * bn],     aL[mf], bH[cur][0], bH[cur][2]);
                mma16816(acc[mf][2 * bn + 1], aL[mf], bH[cur][1], bH[cur][3]);
                mma16816(acc[mf][2 * bn],     aH[mf], bL[cur][0], bL[cur][2]);
                mma16816(acc[mf][2 * bn + 1], aH[mf], bL[cur][1], bL[cur][3]);
            }
            cur = nxt;
        }
    }
}

__device__ __forceinline__ void copy_B(char* sm, int slot, int tid) {
    const uint4* gh = (const uint4*)(g_wbh + slot * 32768);
    const uint4* gl = (const uint4*)(g_wbl + slot * 32768);
    uint4* bh = (uint4*)(sm + SM_BH);
    uint4* bl = (uint4*)(sm + SM_BL);
    for (int i = tid; i < 2048; i += 256) { bh[i] = gh[i]; bl[i] = gl[i]; }
}

// store prefetched regs (one K-half of A) into swizzled smem
__device__ __forceinline__ void stage_sts(char* sm, int tid, const float4 (&s)[4][2]) {
#pragma unroll
    for (int i = 0; i < 4; i++) {
        int u = tid + i * 256;
        int row = u >> 3, ch = u & 7;
        uint4 hi, lo; cvt8(s[i][0], s[i][1], hi, lo);
        uint32_t off = soff64(row, ch * 8);
        *(uint4*)(sm + SM_AH + off) = hi;
        *(uint4*)(sm + SM_AL + off) = lo;
    }
}

// ================= prep: zero scratch + weight split/swizzle =================
__global__ void k_prep(const float* W0, const float* W1, const float* W2, const float* W3,
                       const float* W4, const float* W5, const float* W6, const float* W7,
                       const float* W8, const float* WT) {
    const float* Wp[9] = {W0, W1, W2, W3, W4, W5, W6, W7, W8};
    int i = blockIdx.x * blockDim.x + threadIdx.x;
    int stride = gridDim.x * blockDim.x;
    for (int t = i; t < NN * DD; t += stride) g_facc[t] = 0.f;
    for (int t = i; t < NN; t += stride) g_cnt0[t] = 0;
    if (i == 0) g_mcount = 0;
    for (int t = i; t < 11 * 2048; t += stride) {
        int slot = t >> 11, r = t & 2047;
        int n = r >> 4, k8 = r & 15;
        const float* srcp;
        if (slot < 9) srcp = Wp[slot] + n * 128 + k8 * 8;
        else if (slot == 9) srcp = WT + n * 256 + k8 * 8;
        else srcp = WT + n * 256 + 128 + k8 * 8;
        float4 v0 = ((const float4*)srcp)[0];
        float4 v1 = ((const float4*)srcp)[1];
        uint4 hi, lo; cvt8(v0, v1, hi, lo);
        uint32_t off = (uint32_t)slot * 32768u + soff(n, k8 * 8);
        *reinterpret_cast<uint4*>(g_wbh + off) = hi;
        *reinterpret_cast<uint4*>(g_wbl + off) = lo;
    }
}

__global__ void k_count(const int* __restrict__ smask, const int* __restrict__ dst) {
    int e = blockIdx.x * 256 + threadIdx.x;
    int lane = threadIdx.x & 31;
    int sm_ = smask[e];
    int d_ = dst[e];
    unsigned bal = __ballot_sync(0xffffffffu, sm_ == 1);
    if (sm_ == 0) atomicAdd(&g_cnt0[d_], 1);
    int lead = bal ? (__ffs(bal) - 1) : 0;
    int basec = 0;
    if (bal && lane == lead) basec = atomicAdd(&g_mcount, __popc(bal));
    basec = __shfl_sync(0xffffffffu, basec, lead);
    if (sm_ == 1) g_mlist[basec + __popc(bal & ((1u << lane) - 1u))] = e;
}

// load one K-half of node rows into regs (guarded)
__device__ __forceinline__ void load_half_rows(float4 (&s)[4][2], const float* X,
                                               int r0, int kh, int tid, int limit) {
#pragma unroll
    for (int i = 0; i < 4; i++) {
        int u = tid + i * 256;
        int row = u >> 3, ch = u & 7;
        int g = r0 + row;
        s[i][0] = make_float4(0.f, 0.f, 0.f, 0.f);
        s[i][1] = s[i][0];
        if (g < limit) {
            s[i][0] = ((const float4*)X)[(size_t)g * 32 + kh * 16 + ch * 2];
            s[i][1] = ((const float4*)X)[(size_t)g * 32 + kh * 16 + ch * 2 + 1];
        }
    }
}

// ================= node GEMMs: persistent, 9 uniform jobs, cross-tile pipeline ====
__global__ void __launch_bounds__(256, 2)
k_nodeg(const float* __restrict__ h, const float* __restrict__ p,
        const float* __restrict__ dv,
        const float* bV1, const float* bV2, const float* bP1,
        const float* bP2, const float* bP3, const float* bD1,
        const float* bD2, const float* bT) {
    extern __shared__ char sm[];
    uint32_t smb = smem_u32(sm);
    int tid = threadIdx.x, lane = tid & 31, wid = tid >> 5;
    int wm = wid & 3, wn = wid >> 2;
    int pidx = blockIdx.x % 9;
    int nct = (gridDim.x - 1 - pidx) / 9 + 1;

    const float* X;
    const float* bias;
    int slot;
    switch (pidx) {
        case 0: X = h;  slot = 0;  bias = bV1; break;
        case 1: X = h;  slot = 1;  bias = bV2; break;
        case 2: X = p;  slot = 2;  bias = bP1; break;
        case 3: X = p;  slot = 3;  bias = bP2; break;
        case 4: X = p;  slot = 4;  bias = bP3; break;
        case 5: X = dv; slot = 5;  bias = bD1; break;
        case 6: X = dv; slot = 6;  bias = bD2; break;
        case 7: X = h;  slot = 9;  bias = bT; break;
        default: X = dv; slot = 10; bias = g_bzero; break;
    }
    if (tid < 128) ((float*)(sm + SM_BIAS))[tid] = bias[tid];
    copy_B(sm, slot, tid);
    float* outp = g_proj[pidx];
    int q = lane >> 2, m = lane & 3;

    int t = blockIdx.x / 9;
    float4 s[4][2];
    if (t < NTILE_N) load_half_rows(s, X, t * 128, 0, tid, NN);

    for (; t < NTILE_N; t += nct) {
        int r0 = t * 128;
        __syncthreads();

        float acc[2][8][4];
#pragma unroll
        for (int mf = 0; mf < 2; mf++)
#pragma unroll
            for (int j = 0; j < 8; j++)
#pragma unroll
                for (int i = 0; i < 4; i++) acc[mf][j][i] = 0.f;

        stage_sts(sm, tid, s);
        __syncthreads();
        load_half_rows(s, X, r0, 1, tid, NN);          // kh1 prefetch
        gemm_half(smb, lane, wm, wn, 0, acc);
        __syncthreads();
        stage_sts(sm, tid, s);
        __syncthreads();
        int t2 = t + nct;
        if (t2 < NTILE_N) load_half_rows(s, X, t2 * 128, 0, tid, NN);  // next-tile prefetch
        gemm_half(smb, lane, wm, wn, 1, acc);

        // register epilogue
        const float* bias_s = (const float*)(sm + SM_BIAS);
#pragma unroll
        for (int mf = 0; mf < 2; mf++) {
            int r1 = r0 + wm * 32 + mf * 16 + q;
            int r2 = r1 + 8;
#pragma unroll
            for (int j = 0; j < 8; j++) {
                int col = wn * 64 + j * 8 + m * 2;
                float b0 = bias_s[col], b1 = bias_s[col + 1];
                if (r1 < NN)
                    *(float2*)&outp[(size_t)r1 * DD + col] =
                        make_float2(acc[mf][j][0] + b0, acc[mf][j][1] + b1);
                if (r2 < NN)
                    *(float2*)&outp[(size_t)r2 * DD + col] =
                        make_float2(acc[mf][j][2] + b0, acc[mf][j][3] + b1);
            }
        }
    }
}

// ================= edge pass A: persistent, resident B, cross-tile pipeline ======
__global__ void __launch_bounds__(256, 2)
k_edgeA(const float* __restrict__ e_in, const int* __restrict__ src,
        const int* __restrict__ dst, const int* __restrict__ smask,
        const float* __restrict__ bE1, float* __restrict__ e_out) {
    extern __shared__ char sm[];
    uint32_t smb = smem_u32(sm);
    int tid = threadIdx.x, lane = tid & 31, wid = tid >> 5;
    int wm = wid & 3, wn = wid >> 2;
    int q = lane >> 2, m = lane & 3;

    if (tid < 128) ((float*)(sm + SM_BIAS))[tid] = bE1[tid];
    copy_B(sm, 7, tid);
    const float* P1 = g_proj[2];
    const float* P2 = g_proj[3];

    int t = blockIdx.x;
    float4 s[4][2];
    int nsrc = 0, ndst = 0, nmsk = 0;
    if (t < NTILE_E) {
        if (tid < 128) {
            int eg = t * 128 + tid;
            nsrc = src[eg]; ndst = dst[eg]; nmsk = smask[eg];
        }
        load_half_rows(s, e_in, t * 128, 0, tid, EE);
    }

    for (; t < NTILE_E; t += gridDim.x) {
        int e0 = t * 128;
        __syncthreads();
        if (tid < 128) {
            ((int*)(sm + SM_ROWA))[tid] = nsrc;
            ((int*)(sm + SM_ROWB))[tid] = ndst;
            ((int*)(sm + SM_ROWC))[tid] = nmsk;
        }
        stage_sts(sm, tid, s);
        __syncthreads();
        load_half_rows(s, e_in, e0, 1, tid, EE);       // kh1 prefetch

        float acc[2][8][4];
#pragma unroll
        for (int mf = 0; mf < 2; mf++)
#pragma unroll
            for (int j = 0; j < 8; j++)
#pragma unroll
                for (int i = 0; i < 4; i++) acc[mf][j][i] = 0.f;

        gemm_half(smb, lane, wm, wn, 0, acc);
        __syncthreads();
        stage_sts(sm, tid, s);
        __syncthreads();
        int t2 = t + gridDim.x;
        if (t2 < NTILE_E) {                             // next-tile prefetch
            if (tid < 128) {
                int eg = t2 * 128 + tid;
                nsrc = src[eg]; ndst = dst[eg]; nmsk = smask[eg];
            }
            load_half_rows(s, e_in, t2 * 128, 0, tid, EE);
        }
        gemm_half(smb, lane, wm, wn, 1, acc);

        // epilogue: 2 passes of 64 rows through swizzled C in the A region
        const float* bias_s = (const float*)(sm + SM_BIAS);
        const int* ssrc = (const int*)(sm + SM_ROWA);
        const int* sdst = (const int*)(sm + SM_ROWB);
        const int* smsk = (const int*)(sm + SM_ROWC);
#pragma unroll
        for (int ph = 0; ph < 2; ph++) {
            __syncthreads();
            if ((wm >> 1) == ph) {
                int wml = wm & 1;
#pragma unroll
                for (int mf = 0; mf < 2; mf++) {
                    int rb = wml * 32 + mf * 16 + q;
#pragma unroll
                    for (int j = 0; j < 8; j++) {
                        int col = wn * 64 + j * 8 + m * 2;
                        int c4 = col >> 2;
                        uint32_t inoff = (uint32_t)((m & 1) * 8);
                        *(float2*)(sm + coff(rb, c4) + inoff) =
                            make_float2(acc[mf][j][0], acc[mf][j][1]);
                        *(float2*)(sm + coff(rb + 8, c4) + inoff) =
                            make_float2(acc[mf][j][2], acc[mf][j][3]);
                    }
                }
            }
            __syncthreads();
            for (int u = tid; u < 2048; u += 256) {
                int r = u >> 5, c4 = u & 31;   // c4 == lane
                int lr = ph * 64 + r;
                int eg = e0 + lr;
                int si = ssrc[lr], di = sdst[lr], msk = smsk[lr];
                float4 cC = *(float4*)(sm + coff(r, c4));
                float4 bv = *(const float4*)&bias_s[c4 * 4];
                float4 p1 = *(const float4*)&P1[(size_t)di * DD + c4 * 4];
                float4 p2 = *(const float4*)&P2[(size_t)si * DD + c4 * 4];
                float4 ev = *(const float4*)&e_in[(size_t)eg * DD + c4 * 4];
                float4 en;
                en.x = 0.5f * (p1.x - p2.x + cC.x + bv.x);
                en.y = 0.5f * (p1.y - p2.y + cC.y + bv.y);
                en.z = 0.5f * (p1.z - p2.z + cC.z + bv.z);
                en.w = 0.5f * (p1.w - p2.w + cC.w + bv.w);
                float4 o;
                o.x = ev.x + lrelu(en.x);
                o.y = ev.y + lrelu(en.y);
                o.z = ev.z + lrelu(en.z);
                o.w = ev.w + lrelu(en.w);
                *(float4*)&e_out[(size_t)eg * DD + c4 * 4] = o;
                if (msk) *(float4*)&g_enew[(size_t)eg * DD + c4 * 4] = en;
                float sq = en.x * en.x + en.y * en.y + en.z * en.z + en.w * en.w;
#pragma unroll
                for (int off = 16; off > 0; off >>= 1)
                    sq += __shfl_xor_sync(0xffffffffu, sq, off);
                if (c4 == 0 && msk) g_enorm[eg] = sqrtf(sq);
            }
        }
    }
}

// ================= edge pass B: persistent, resident B, masked V GEMM =============
__global__ void __launch_bounds__(256, 2)
k_edgeB(const float* __restrict__ h, const float* __restrict__ bV,
        const int* __restrict__ src, const int* __restrict__ dst) {
    extern __shared__ char sm[];
    uint32_t smb = smem_u32(sm);
    int tid = threadIdx.x, lane = tid & 31, wid = tid >> 5;
    int wm = wid & 3, wn = wid >> 2;
    int q = lane >> 2, m = lane & 3;
    int mc = g_mcount;
    int ntiles = (mc + 127) >> 7;

    if (tid < 128) ((float*)(sm + SM_BIAS))[tid] = bV[tid];
    copy_B(sm, 8, tid);
    int* seid = (int*)(sm + SM_ROWC);
    int* ssrc = (int*)(sm + SM_ROWA);
    int* sdst = (int*)(sm + SM_ROWB);
    const float* bias_s = (const float*)(sm + SM_BIAS);
    float* svb = (float*)(sm + SM_SV);

    int t = blockIdx.x;
    int neid = -1, nsrc = 0, ndst = 0;
    if (t < ntiles && tid < 128) {
        int base = t * 128;
        neid = (base + tid < mc) ? g_mlist[base + tid] : -1;
        nsrc = (neid >= 0) ? src[neid] : 0;
        ndst = (neid >= 0) ? dst[neid] : 0;
    }

    for (; t < ntiles; t += gridDim.x) {
        int base = t * 128;
        int nt = min(128, mc - base);
        __syncthreads();
        if (tid < 128) {
            seid[tid] = neid;
            ssrc[tid] = nsrc;
            sdst[tid] = ndst;
        }
        __syncthreads();

        float acc[2][8][4];
#pragma unroll
        for (int mf = 0; mf < 2; mf++)
#pragma unroll
            for (int j = 0; j < 8; j++)
#pragma unroll
                for (int i = 0; i < 4; i++) acc[mf][j][i] = 0.f;

        for (int kh = 0; kh < 2; kh++) {
            for (int u = tid; u < 1024; u += 256) {
                int row = u >> 3, ch = u & 7;
                float4 v0 = make_float4(0.f, 0.f, 0.f, 0.f), v1 = v0;
                if (row < nt) {
                    float4 hs0 = ((const float4*)h)[(size_t)ssrc[row] * 32 + kh * 16 + ch * 2];
                    float4 hs1 = ((const float4*)h)[(size_t)ssrc[row] * 32 + kh * 16 + ch * 2 + 1];
                    float4 hd0 = ((const float4*)h)[(size_t)sdst[row] * 32 + kh * 16 + ch * 2];
                    float4 hd1 = ((const float4*)h)[(size_t)sdst[row] * 32 + kh * 16 + ch * 2 + 1];
                    v0.x = hs0.x * hd0.x; v0.y = hs0.y * hd0.y;
                    v0.z = hs0.z * hd0.z; v0.w = hs0.w * hd0.w;
                    v1.x = hs1.x * hd1.x; v1.y = hs1.y * hd1.y;
                    v1.z = hs1.z * hd1.z; v1.w = hs1.w * hd1.w;
                }
                uint4 hi, lo; cvt8(v0, v1, hi, lo);
                uint32_t off = soff64(row, ch * 8);
                *(uint4*)(sm + SM_AH + off) = hi;
                *(uint4*)(sm + SM_AL + off) = lo;
            }
            __syncthreads();
            if (kh == 1) {
                // prefetch next tile's two-level index chain under gemm kh1
                int t2 = t + gridDim.x;
                if (t2 < ntiles && tid < 128) {
                    int b2 = t2 * 128;
                    neid = (b2 + tid < mc) ? g_mlist[b2 + tid] : -1;
                    nsrc = (neid >= 0) ? src[neid] : 0;
                    ndst = (neid >= 0) ? dst[neid] : 0;
                }
            }
            gemm_half(smb, lane, wm, wn, kh, acc);
            __syncthreads();
        }

        float s0[2] = {0.f, 0.f}, s1[2] = {0.f, 0.f};
#pragma unroll
        for (int mf = 0; mf < 2; mf++)
#pragma unroll
            for (int j = 0; j < 8; j++) {
                float b0 = bias_s[wn * 64 + j * 8 + m * 2];
                float b1 = bias_s[wn * 64 + j * 8 + m * 2 + 1];
                s0[mf] += relu_(acc[mf][j][0] + b0) + relu_(acc[mf][j][1] + b1);
                s1[mf] += relu_(acc[mf][j][2] + b0) + relu_(acc[mf][j][3] + b1);
            }
#pragma unroll
        for (int mf = 0; mf < 2; mf++) {
            s0[mf] += __shfl_xor_sync(0xffffffffu, s0[mf], 1);
            s0[mf] += __shfl_xor_sync(0xffffffffu, s0[mf], 2);
            s1[mf] += __shfl_xor_sync(0xffffffffu, s1[mf], 1);
            s1[mf] += __shfl_xor_sync(0xffffffffu, s1[mf], 2);
        }
        if (m == 0) {
#pragma unroll
            for (int mf = 0; mf < 2; mf++) {
                svb[wn * 128 + wm * 32 + mf * 16 + q] = s0[mf];
                svb[wn * 128 + wm * 32 + mf * 16 + q + 8] = s1[mf];
            }
        }
        __syncthreads();

        // per-edge coefficient into smem
        if (tid < 128) {
            float cf = 0.f;
            if (tid < nt) {
                float sv = svb[tid] + svb[128 + tid];
                float L = g_enorm[seid[tid]];
                if (L > 1e-9f && sv > 0.f) {
                    float r = 0.5f * sqrtf(L);
                    cf = sv * expf(-r / 0.3f) / (1.2f * L * sqrtf(L));
                }
            }
            svb[256 + tid] = cf;
        }
        __syncthreads();

        // cooperative scatter: 256 threads, one float4 chunk each, v4 reductions
        const float* scf = svb + 256;
        for (int u = tid; u < 4096; u += 256) {
            int e = u >> 5, c4 = u & 31;
            float cf = scf[e];
            if (cf != 0.f) {
                int eid = seid[e];
                float4 en = ((const float4*)g_enew)[(size_t)eid * 32 + c4];
                float* fp = &g_facc[(size_t)sdst[e] * DD + c4 * 4];
                asm volatile(
                    "red.global.add.v4.f32 [%0], {%1, %2, %3, %4};"
                    :: "l"(fp), "f"(cf * en.x), "f"(cf * en.y),
                       "f"(cf * en.z), "f"(cf * en.w)
                    : "memory");
            }
        }
    }
}

// ================= node finalize =================
__global__ void k_final(const float* __restrict__ h, const float* __restrict__ p,
                        const float* __restrict__ dv, const float* __restrict__ dt,
                        float* __restrict__ out) {
    int w = threadIdx.x >> 5, l = threadIdx.x & 31;
    int n = blockIdx.x * 8 + w;
    int ix = n * 32 + l;
    const float4* V1 = (const float4*)g_proj[0];
    const float4* V2 = (const float4*)g_proj[1];
    const float4* P3 = (const float4*)g_proj[4];
    const float4* D1 = (const float4*)g_proj[5];
    const float4* D2 = (const float4*)g_proj[6];
    const float4* TA = (const float4*)g_proj[7];
    const float4* TB = (const float4*)g_proj[8];
    const float4* FA = (const float4*)g_facc;

    float4 v1 = V1[ix], v2 = V2[ix], p3 = P3[ix], d1 = D1[ix], d2 = D2[ix];
    float4 ta = TA[ix], tb = TB[ix], fa = FA[ix];
    float cnt = (float)g_cnt0[n];

    float4 th;
    th.x = ta.x + tb.x; th.y = ta.y + tb.y;
    th.z = ta.z + tb.z; th.w = ta.w + tb.w;

    float4 f;
    f.x = (d1.x - v1.x) * (cnt * relu_(th.x)) + fa.x;
    f.y = (d1.y - v1.y) * (cnt * relu_(th.y)) + fa.y;
    f.z = (d1.z - v1.z) * (cnt * relu_(th.z)) + fa.z;
    f.w = (d1.w - v1.w) * (cnt * relu_(th.w)) + fa.w;

    float sq = f.x * f.x + f.y * f.y + f.z * f.z + f.w * f.w;
#pragma unroll
    for (int off = 16; off > 0; off >>= 1) sq += __shfl_xor_sync(0xffffffffu, sq, off);
    float inv = 1.f / (sqrtf(sq) + 1e-9f);

    float dtv = dt[n];
    float dtp = dtv + 0.5f * dtv * dtv;

    float4 hv = ((const float4*)h)[ix];
    float4 pv = ((const float4*)p)[ix];
    float4 dvv = ((const float4*)dv)[ix];

    float4 ho, po, dq;
    ho.x = hv.x + lrelu(v2.x + f.x * dtv);
    ho.y = hv.y + lrelu(v2.y + f.y * dtv);
    ho.z = hv.z + lrelu(v2.z + f.z * dtv);
    ho.w = hv.w + lrelu(v2.w + f.w * dtv);
    po.x = pv.x + lrelu(p3.x + f.x * dtp);
    po.y = pv.y + lrelu(p3.y + f.y * dtp);
    po.z = pv.z + lrelu(p3.z + f.z * dtp);
    po.w = pv.w + lrelu(p3.w + f.w * dtp);
    dq.x = dvv.x + lrelu(d2.x + f.x * inv);
    dq.y = dvv.y + lrelu(d2.y + f.y * inv);
    dq.z = dvv.z + lrelu(d2.z + f.z * inv);
    dq.w = dvv.w + lrelu(d2.w + f.w * inv);

    float4* outH = (float4*)out;
    float4* outP = (float4*)(out + (size_t)NN * DD + (size_t)EE * DD);
    float4* outD = (float4*)(out + 2 * (size_t)NN * DD + (size_t)EE * DD);
    outH[ix] = ho;
    outP[ix] = po;
    outD[ix] = dq;
}

// ================= launch =================
extern "C" void kernel_launch(void* const* d_in, const int* in_sizes, int n_in,
                              void* d_out, int out_size) {
    const float* h   = (const float*)d_in[0];
    const float* e   = (const float*)d_in[1];
    const float* p   = (const float*)d_in[2];
    const float* dv  = (const float*)d_in[3];
    const float* dt  = (const float*)d_in[4];
    const int* smask = (const int*)d_in[5];
    const int* src   = (const int*)d_in[6];
    const int* dst   = (const int*)d_in[7];
    const float* W_V1 = (const float*)d_in[8],  *b_V1 = (const float*)d_in[9];
    const float* W_V2 = (const float*)d_in[10], *b_V2 = (const float*)d_in[11];
    const float* W_E1 = (const float*)d_in[12], *b_E1 = (const float*)d_in[13];
    const float* W_P1 = (const float*)d_in[14], *b_P1 = (const float*)d_in[15];
    const float* W_P2 = (const float*)d_in[16], *b_P2 = (const float*)d_in[17];
    const float* W_P3 = (const float*)d_in[18], *b_P3 = (const float*)d_in[19];
    const float* W_D1 = (const float*)d_in[20], *b_D1 = (const float*)d_in[21];
    const float* W_D2 = (const float*)d_in[22], *b_D2 = (const float*)d_in[23];
    const float* W_V  = (const float*)d_in[24], *b_V  = (const float*)d_in[25];
    const float* W_T  = (const float*)d_in[26], *b_T  = (const float*)d_in[27];
    float* out = (float*)d_out;

    cudaFuncSetAttribute(k_nodeg, cudaFuncAttributeMaxDynamicSharedMemorySize, SM_TOTAL);
    cudaFuncSetAttribute(k_edgeA, cudaFuncAttributeMaxDynamicSharedMemorySize, SM_TOTAL);
    cudaFuncSetAttribute(k_edgeB, cudaFuncAttributeMaxDynamicSharedMemorySize, SM_TOTAL);

    k_prep<<<640, 256>>>(W_V1, W_V2, W_P1, W_P2, W_P3, W_D1, W_D2, W_E1, W_V, W_T);
    k_count<<<EE / 256, 256>>>(smask, dst);
    k_nodeg<<<GRID_P, 256, SM_TOTAL>>>(h, p, dv, b_V1, b_V2, b_P1, b_P2, b_P3,
                                       b_D1, b_D2, b_T);
    k_edgeA<<<GRID_P, 256, SM_TOTAL>>>(e, src, dst, smask, b_E1, out + (size_t)NN * DD);
    k_edgeB<<<GRID_P, 256, SM_TOTAL>>>(h, b_V, src, dst);
    k_final<<<NN / 8, 256>>>(h, p, dv, dt, out);
}

// round 11
// speedup vs baseline: 1.1349x; 1.1349x over previous
#include <cuda_runtime.h>
#include <cuda_bf16.h>
#include <cstdint>
#include <math.h>

#define NN 10000
#define EE 320000
#define DD 128
#define NTILE_N 79      /* (NN+127)/128 */
#define NTILE_E 2500    /* EE/128 */
#define GRID_P 296      /* persistent grid: 148 SMs x 2 CTAs */

// ================= static device scratch =================
__device__ float g_proj[9][NN * DD];     // V1h V2h P1h P2h P3h D1h D2h ThA ThB
__device__ float g_enew[(size_t)EE * DD];
__device__ float g_enorm[EE];
__device__ float g_facc[NN * DD];
__device__ int   g_cnt0[NN];
__device__ int   g_mlist[EE];
__device__ int   g_mcount;
__device__ float g_bzero[DD];            // stays zero (module-load init)
// pre-split weight tiles in swizzled layout (32KB each):
// slots 0..6 node W (V1,V2,P1,P2,P3,D1,D2), 7 E1, 8 V, 9/10 = W_T halves
__device__ __align__(16) unsigned char g_wbh[11 * 32768];
__device__ __align__(16) unsigned char g_wbl[11 * 32768];

__device__ __forceinline__ float lrelu(float x) { return x > 0.f ? x : 0.01f * x; }
__device__ __forceinline__ float relu_(float x) { return x > 0.f ? x : 0.f; }

__device__ __forceinline__ uint32_t smem_u32(const void* p) {
    uint32_t a;
    asm("{ .reg .u64 t; cvta.to.shared.u64 t, %1; cvt.u32.u64 %0, t; }" : "=r"(a) : "l"(p));
    return a;
}
__device__ __forceinline__ uint32_t pack2(__nv_bfloat16 a, __nv_bfloat16 b) {
    __nv_bfloat162 t; t.x = a; t.y = b;
    return *reinterpret_cast<uint32_t*>(&t);
}
__device__ __forceinline__ void l2_prefetch(const void* p) {
    asm volatile("prefetch.global.L2 [%0];" :: "l"(p));
}

// swizzled byte offset inside a 128x128 bf16 tile (B tiles): row stride 256B
__device__ __forceinline__ uint32_t soff(int r, int c) {
    return (uint32_t)((r << 8) + ((((c >> 3) ^ (r & 7)) << 4) | ((c & 7) << 1)));
}
// swizzled byte offset inside a 128x64 bf16 tile (A half-tiles): row stride 128B
__device__ __forceinline__ uint32_t soff64(int r, int c) {
    return (uint32_t)((r << 7) + (((((c >> 3) ^ (r & 7)) & 7) << 4) | ((c & 7) << 1)));
}

__device__ __forceinline__ void ldsm4(uint32_t* r, uint32_t addr) {
    asm volatile("ldmatrix.sync.aligned.m8n8.x4.shared.b16 {%0,%1,%2,%3}, [%4];"
                 : "=r"(r[0]), "=r"(r[1]), "=r"(r[2]), "=r"(r[3]) : "r"(addr));
}
__device__ __forceinline__ void mma16816(float* d, const uint32_t* a,
                                         uint32_t b0, uint32_t b1) {
    asm volatile(
        "mma.sync.aligned.m16n8k16.row.col.f32.bf16.bf16.f32 "
        "{%0,%1,%2,%3}, {%4,%5,%6,%7}, {%8,%9}, {%0,%1,%2,%3};"
        : "+f"(d[0]), "+f"(d[1]), "+f"(d[2]), "+f"(d[3])
        : "r"(a[0]), "r"(a[1]), "r"(a[2]), "r"(a[3]), "r"(b0), "r"(b1));
}

// split 8 fp32 -> hi/lo bf16x2 quads
__device__ __forceinline__ void cvt8(float4 v0, float4 v1, uint4& hi, uint4& lo) {
    __nv_bfloat16 a0 = __float2bfloat16(v0.x), a1 = __float2bfloat16(v0.y);
    __nv_bfloat16 a2 = __float2bfloat16(v0.z), a3 = __float2bfloat16(v0.w);
    __nv_bfloat16 a4 = __float2bfloat16(v1.x), a5 = __float2bfloat16(v1.y);
    __nv_bfloat16 a6 = __float2bfloat16(v1.z), a7 = __float2bfloat16(v1.w);
    hi.x = pack2(a0, a1); hi.y = pack2(a2, a3);
    hi.z = pack2(a4, a5); hi.w = pack2(a6, a7);
    lo.x = pack2(__float2bfloat16(v0.x - __bfloat162float(a0)),
                 __float2bfloat16(v0.y - __bfloat162float(a1)));
    lo.y = pack2(__float2bfloat16(v0.z - __bfloat162float(a2)),
                 __float2bfloat16(v0.w - __bfloat162float(a3)));
    lo.z = pack2(__float2bfloat16(v1.x - __bfloat162float(a4)),
                 __float2bfloat16(v1.y - __bfloat162float(a5)));
    lo.w = pack2(__float2bfloat16(v1.z - __bfloat162float(a6)),
                 __float2bfloat16(v1.w - __bfloat162float(a7)));
}

// shared memory layout (102400 bytes -> 2 CTAs/SM)
#define SM_BIAS 0
#define SM_ROWA 512
#define SM_ROWB 1024
#define SM_ROWC 1536
#define SM_SV   2048
#define SM_AH   4096                 /* 128x64 bf16 hi (16KB) */
#define SM_AL   (4096 + 16384)       /* 128x64 bf16 lo (16KB) */
#define SM_BH   (4096 + 32768)       /* 128x128 bf16 hi (32KB) RESIDENT */
#define SM_BL   (4096 + 65536)       /* 128x128 bf16 lo (32KB) RESIDENT */
#define SM_C    4096                 /* fp32 C 64rows x 512B, overlays A only */
#define SM_TOTAL (4096 + 98304)

// C chunk-swizzled offset: local row r (0..63), float4-chunk c4 (0..31)
__device__ __forceinline__ uint32_t coff(int r, int c4) {
    return (uint32_t)(SM_C + r * 512 + (((c4 ^ (r & 7)) & 31) << 4));
}

// ---- 3-term split GEMM over one K-half, warp tile 32(M) x 64(N), 8 warps ----
__device__ __forceinline__ void gemm_half(uint32_t smb, int lane, int wm, int wn,
                                          int kh, float (&acc)[2][8][4]) {
    const int fr = lane & 15;
    const int fc = (lane >> 4) << 3;
    const int m0 = wm * 32;
    const int n0 = wn * 64;
#pragma unroll
    for (int ks = 0; ks < 4; ks++) {
        const int kc = kh * 64 + ks * 16 + fc;
        uint32_t aH[2][4], aL[2][4];
        uint32_t bH[2][4], bL[2][4];
        ldsm4(aH[0], smb + SM_AH + soff64(m0 + fr, ks * 16 + fc));
        ldsm4(aH[1], smb + SM_AH + soff64(m0 + 16 + fr, ks * 16 + fc));
        ldsm4(bH[0], smb + SM_BH + soff(n0 + fr, kc));
        ldsm4(bL[0], smb + SM_BL + soff(n0 + fr, kc));
        ldsm4(aL[0], smb + SM_AL + soff64(m0 + fr, ks * 16 + fc));
        ldsm4(aL[1], smb + SM_AL + soff64(m0 + 16 + fr, ks * 16 + fc));
        int cur = 0;
#pragma unroll
        for (int bn = 0; bn < 4; bn++) {
            int nxt = cur ^ 1;
            if (bn < 3) {
                ldsm4(bH[nxt], smb + SM_BH + soff(n0 + (bn + 1) * 16 + fr, kc));
                ldsm4(bL[nxt], smb + SM_BL + soff(n0 + (bn + 1) * 16 + fr, kc));
            }
#pragma unroll
            for (int mf = 0; mf < 2; mf++) {
                mma16816(acc[mf][2 * bn],     aH[mf], bH[cur][0], bH[cur][2]);
                mma16816(acc[mf][2 * bn + 1], aH[mf], bH[cur][1], bH[cur][3]);
                mma16816(acc[mf][2 * bn],     aL[mf], bH[cur][0], bH[cur][2]);
                mma16816(acc[mf][2 * bn + 1], aL[mf], bH[cur][1], bH[cur][3]);
                mma16816(acc[mf][2 * bn],     aH[mf], bL[cur][0], bL[cur][2]);
                mma16816(acc[mf][2 * bn + 1], aH[mf], bL[cur][1], bL[cur][3]);
            }
            cur = nxt;
        }
    }
}

__device__ __forceinline__ void copy_B(char* sm, int slot, int tid) {
    const uint4* gh = (const uint4*)(g_wbh + slot * 32768);
    const uint4* gl = (const uint4*)(g_wbl + slot * 32768);
    uint4* bh = (uint4*)(sm + SM_BH);
    uint4* bl = (uint4*)(sm + SM_BL);
    for (int i = tid; i < 2048; i += 256) { bh[i] = gh[i]; bl[i] = gl[i]; }
}

// store prefetched regs (one K-half of A) into swizzled smem
__device__ __forceinline__ void stage_sts(char* sm, int tid, const float4 (&s)[4][2]) {
#pragma unroll
    for (int i = 0; i < 4; i++) {
        int u = tid + i * 256;
        int row = u >> 3, ch = u & 7;
        uint4 hi, lo; cvt8(s[i][0], s[i][1], hi, lo);
        uint32_t off = soff64(row, ch * 8);
        *(uint4*)(sm + SM_AH + off) = hi;
        *(uint4*)(sm + SM_AL + off) = lo;
    }
}

// ================= prep: zero scratch + weight split/swizzle =================
__global__ void k_prep(const float* W0, const float* W1, const float* W2, const float* W3,
                       const float* W4, const float* W5, const float* W6, const float* W7,
                       const float* W8, const float* WT) {
    const float* Wp[9] = {W0, W1, W2, W3, W4, W5, W6, W7, W8};
    int i = blockIdx.x * blockDim.x + threadIdx.x;
    int stride = gridDim.x * blockDim.x;
    for (int t = i; t < NN * DD; t += stride) g_facc[t] = 0.f;
    for (int t = i; t < NN; t += stride) g_cnt0[t] = 0;
    if (i == 0) g_mcount = 0;
    for (int t = i; t < 11 * 2048; t += stride) {
        int slot = t >> 11, r = t & 2047;
        int n = r >> 4, k8 = r & 15;
        const float* srcp;
        if (slot < 9) srcp = Wp[slot] + n * 128 + k8 * 8;
        else if (slot == 9) srcp = WT + n * 256 + k8 * 8;
        else srcp = WT + n * 256 + 128 + k8 * 8;
        float4 v0 = ((const float4*)srcp)[0];
        float4 v1 = ((const float4*)srcp)[1];
        uint4 hi, lo; cvt8(v0, v1, hi, lo);
        uint32_t off = (uint32_t)slot * 32768u + soff(n, k8 * 8);
        *reinterpret_cast<uint4*>(g_wbh + off) = hi;
        *reinterpret_cast<uint4*>(g_wbl + off) = lo;
    }
}

__global__ void k_count(const int* __restrict__ smask, const int* __restrict__ dst) {
    int e = blockIdx.x * 256 + threadIdx.x;
    int lane = threadIdx.x & 31;
    int sm_ = smask[e];
    int d_ = dst[e];
    unsigned bal = __ballot_sync(0xffffffffu, sm_ == 1);
    if (sm_ == 0) atomicAdd(&g_cnt0[d_], 1);
    int lead = bal ? (__ffs(bal) - 1) : 0;
    int basec = 0;
    if (bal && lane == lead) basec = atomicAdd(&g_mcount, __popc(bal));
    basec = __shfl_sync(0xffffffffu, basec, lead);
    if (sm_ == 1) g_mlist[basec + __popc(bal & ((1u << lane) - 1u))] = e;
}

// ================= node GEMMs: persistent, 9 uniform jobs =================
__global__ void __launch_bounds__(256, 2)
k_nodeg(const float* __restrict__ h, const float* __restrict__ p,
        const float* __restrict__ dv,
        const float* bV1, const float* bV2, const float* bP1,
        const float* bP2, const float* bP3, const float* bD1,
        const float* bD2, const float* bT) {
    extern __shared__ char sm[];
    uint32_t smb = smem_u32(sm);
    int tid = threadIdx.x, lane = tid & 31, wid = tid >> 5;
    int wm = wid & 3, wn = wid >> 2;
    int pidx = blockIdx.x % 9;
    int nct = (gridDim.x - 1 - pidx) / 9 + 1;

    const float* X;
    const float* bias;
    int slot;
    switch (pidx) {
        case 0: X = h;  slot = 0;  bias = bV1; break;
        case 1: X = h;  slot = 1;  bias = bV2; break;
        case 2: X = p;  slot = 2;  bias = bP1; break;
        case 3: X = p;  slot = 3;  bias = bP2; break;
        case 4: X = p;  slot = 4;  bias = bP3; break;
        case 5: X = dv; slot = 5;  bias = bD1; break;
        case 6: X = dv; slot = 6;  bias = bD2; break;
        case 7: X = h;  slot = 9;  bias = bT; break;
        default: X = dv; slot = 10; bias = g_bzero; break;
    }
    if (tid < 128) ((float*)(sm + SM_BIAS))[tid] = bias[tid];
    copy_B(sm, slot, tid);
    float* outp = g_proj[pidx];
    int q = lane >> 2, m = lane & 3;

    for (int t = blockIdx.x / 9; t < NTILE_N; t += nct) {
        int r0 = t * 128;
        __syncthreads();

        float acc[2][8][4];
#pragma unroll
        for (int mf = 0; mf < 2; mf++)
#pragma unroll
            for (int j = 0; j < 8; j++)
#pragma unroll
                for (int i = 0; i < 4; i++) acc[mf][j][i] = 0.f;

        float4 s[4][2];
#pragma unroll
        for (int i = 0; i < 4; i++) {
            int u = tid + i * 256;
            int row = u >> 3, ch = u & 7;
            int g = r0 + row;
            s[i][0] = make_float4(0.f, 0.f, 0.f, 0.f);
            s[i][1] = s[i][0];
            if (g < NN) {
                s[i][0] = ((const float4*)X)[(size_t)g * 32 + ch * 2];
                s[i][1] = ((const float4*)X)[(size_t)g * 32 + ch * 2 + 1];
            }
        }
        stage_sts(sm, tid, s);
        __syncthreads();
        // prefetch kh1 while gemm kh0 runs
#pragma unroll
        for (int i = 0; i < 4; i++) {
            int u = tid + i * 256;
            int row = u >> 3, ch = u & 7;
            int g = r0 + row;
            if (g < NN) {
                s[i][0] = ((const float4*)X)[(size_t)g * 32 + 16 + ch * 2];
                s[i][1] = ((const float4*)X)[(size_t)g * 32 + 16 + ch * 2 + 1];
            } else {
                s[i][0] = make_float4(0.f, 0.f, 0.f, 0.f);
                s[i][1] = s[i][0];
            }
        }
        // register-free L2 prefetch of next tile's X rows (overlaps gemm+epilogue)
        {
            int t2 = t + nct;
            if (t2 < NTILE_N) {
                const char* nb = (const char*)(X + (size_t)t2 * 128 * DD);
                int lines = min(128 * 4, (NN - t2 * 128) * 4);  // 128B lines
#pragma unroll
                for (int i = 0; i < 2; i++) {
                    int ln = tid + i * 256;
                    if (ln < lines) l2_prefetch(nb + (size_t)ln * 128);
                }
            }
        }
        gemm_half(smb, lane, wm, wn, 0, acc);
        __syncthreads();
        stage_sts(sm, tid, s);
        __syncthreads();
        gemm_half(smb, lane, wm, wn, 1, acc);

        // register epilogue
        const float* bias_s = (const float*)(sm + SM_BIAS);
#pragma unroll
        for (int mf = 0; mf < 2; mf++) {
            int r1 = r0 + wm * 32 + mf * 16 + q;
            int r2 = r1 + 8;
#pragma unroll
            for (int j = 0; j < 8; j++) {
                int col = wn * 64 + j * 8 + m * 2;
                float b0 = bias_s[col], b1 = bias_s[col + 1];
                if (r1 < NN)
                    *(float2*)&outp[(size_t)r1 * DD + col] =
                        make_float2(acc[mf][j][0] + b0, acc[mf][j][1] + b1);
                if (r2 < NN)
                    *(float2*)&outp[(size_t)r2 * DD + col] =
                        make_float2(acc[mf][j][2] + b0, acc[mf][j][3] + b1);
            }
        }
    }
}

// ================= edge pass A: persistent, resident B, smem-C epilogue ==========
__global__ void __launch_bounds__(256, 2)
k_edgeA(const float* __restrict__ e_in, const int* __restrict__ src,
        const int* __restrict__ dst, const int* __restrict__ smask,
        const float* __restrict__ bE1, float* __restrict__ e_out) {
    extern __shared__ char sm[];
    uint32_t smb = smem_u32(sm);
    int tid = threadIdx.x, lane = tid & 31, wid = tid >> 5;
    int wm = wid & 3, wn = wid >> 2;
    int q = lane >> 2, m = lane & 3;

    if (tid < 128) ((float*)(sm + SM_BIAS))[tid] = bE1[tid];
    copy_B(sm, 7, tid);
    const float* P1 = g_proj[2];
    const float* P2 = g_proj[3];

    for (int t = blockIdx.x; t < NTILE_E; t += gridDim.x) {
        int e0 = t * 128;
        __syncthreads();
        if (tid < 128) {
            int eg = e0 + tid;
            ((int*)(sm + SM_ROWA))[tid] = src[eg];
            ((int*)(sm + SM_ROWB))[tid] = dst[eg];
            ((int*)(sm + SM_ROWC))[tid] = smask[eg];
        }
        float4 s[4][2];
#pragma unroll
        for (int i = 0; i < 4; i++) {
            int u = tid + i * 256;
            int row = u >> 3, ch = u & 7;
            s[i][0] = ((const float4*)e_in)[(size_t)(e0 + row) * 32 + ch * 2];
            s[i][1] = ((const float4*)e_in)[(size_t)(e0 + row) * 32 + ch * 2 + 1];
        }
        stage_sts(sm, tid, s);
        __syncthreads();

        float acc[2][8][4];
#pragma unroll
        for (int mf = 0; mf < 2; mf++)
#pragma unroll
            for (int j = 0; j < 8; j++)
#pragma unroll
                for (int i = 0; i < 4; i++) acc[mf][j][i] = 0.f;

#pragma unroll
        for (int i = 0; i < 4; i++) {
            int u = tid + i * 256;
            int row = u >> 3, ch = u & 7;
            s[i][0] = ((const float4*)e_in)[(size_t)(e0 + row) * 32 + 16 + ch * 2];
            s[i][1] = ((const float4*)e_in)[(size_t)(e0 + row) * 32 + 16 + ch * 2 + 1];
        }
        // register-free L2 prefetch of next tile's e_in (overlaps gemm+epilogue)
        {
            int t2 = t + gridDim.x;
            if (t2 < NTILE_E) {
                const char* nb = (const char*)(e_in + (size_t)t2 * 128 * DD);
#pragma unroll
                for (int i = 0; i < 2; i++)
                    l2_prefetch(nb + (size_t)(tid + i * 256) * 128);
            }
        }
        gemm_half(smb, lane, wm, wn, 0, acc);
        __syncthreads();
        stage_sts(sm, tid, s);
        __syncthreads();
        gemm_half(smb, lane, wm, wn, 1, acc);

        // epilogue: 2 passes of 64 rows through swizzled C in the A region
        const float* bias_s = (const float*)(sm + SM_BIAS);
        const int* ssrc = (const int*)(sm + SM_ROWA);
        const int* sdst = (const int*)(sm + SM_ROWB);
        const int* smsk = (const int*)(sm + SM_ROWC);
#pragma unroll
        for (int ph = 0; ph < 2; ph++) {
            __syncthreads();
            if ((wm >> 1) == ph) {
                int wml = wm & 1;
#pragma unroll
                for (int mf = 0; mf < 2; mf++) {
                    int rb = wml * 32 + mf * 16 + q;
#pragma unroll
                    for (int j = 0; j < 8; j++) {
                        int col = wn * 64 + j * 8 + m * 2;
                        int c4 = col >> 2;
                        uint32_t inoff = (uint32_t)((m & 1) * 8);
                        *(float2*)(sm + coff(rb, c4) + inoff) =
                            make_float2(acc[mf][j][0], acc[mf][j][1]);
                        *(float2*)(sm + coff(rb + 8, c4) + inoff) =
                            make_float2(acc[mf][j][2], acc[mf][j][3]);
                    }
                }
            }
            __syncthreads();
            for (int u = tid; u < 2048; u += 256) {
                int r = u >> 5, c4 = u & 31;   // c4 == lane
                int lr = ph * 64 + r;
                int eg = e0 + lr;
                int si = ssrc[lr], di = sdst[lr], msk = smsk[lr];
                float4 cC = *(float4*)(sm + coff(r, c4));
                float4 bv = *(const float4*)&bias_s[c4 * 4];
                float4 p1 = *(const float4*)&P1[(size_t)di * DD + c4 * 4];
                float4 p2 = *(const float4*)&P2[(size_t)si * DD + c4 * 4];
                float4 ev = *(const float4*)&e_in[(size_t)eg * DD + c4 * 4];
                float4 en;
                en.x = 0.5f * (p1.x - p2.x + cC.x + bv.x);
                en.y = 0.5f * (p1.y - p2.y + cC.y + bv.y);
                en.z = 0.5f * (p1.z - p2.z + cC.z + bv.z);
                en.w = 0.5f * (p1.w - p2.w + cC.w + bv.w);
                float4 o;
                o.x = ev.x + lrelu(en.x);
                o.y = ev.y + lrelu(en.y);
                o.z = ev.z + lrelu(en.z);
                o.w = ev.w + lrelu(en.w);
                *(float4*)&e_out[(size_t)eg * DD + c4 * 4] = o;
                if (msk) *(float4*)&g_enew[(size_t)eg * DD + c4 * 4] = en;
                // row-norm: whole row eg lives in this warp (lane == c4)
                float sq = en.x * en.x + en.y * en.y + en.z * en.z + en.w * en.w;
#pragma unroll
                for (int off = 16; off > 0; off >>= 1)
                    sq += __shfl_xor_sync(0xffffffffu, sq, off);
                if (c4 == 0 && msk) g_enorm[eg] = sqrtf(sq);
            }
        }
    }
}

// ================= edge pass B: persistent, resident B, masked V GEMM =============
__global__ void __launch_bounds__(256, 2)
k_edgeB(const float* __restrict__ h, const float* __restrict__ bV,
        const int* __restrict__ src, const int* __restrict__ dst) {
    extern __shared__ char sm[];
    uint32_t smb = smem_u32(sm);
    int tid = threadIdx.x, lane = tid & 31, wid = tid >> 5;
    int wm = wid & 3, wn = wid >> 2;
    int q = lane >> 2, m = lane & 3;
    int mc = g_mcount;
    int ntiles = (mc + 127) >> 7;

    if (tid < 128) ((float*)(sm + SM_BIAS))[tid] = bV[tid];
    copy_B(sm, 8, tid);
    int* seid = (int*)(sm + SM_ROWC);
    int* ssrc = (int*)(sm + SM_ROWA);
    int* sdst = (int*)(sm + SM_ROWB);
    const float* bias_s = (const float*)(sm + SM_BIAS);
    float* svb = (float*)(sm + SM_SV);

    for (int t = blockIdx.x; t < ntiles; t += gridDim.x) {
        int base = t * 128;
        int nt = min(128, mc - base);
        __syncthreads();
        if (tid < 128) {
            int eid = (tid < nt) ? g_mlist[base + tid] : -1;
            seid[tid] = eid;
            ssrc[tid] = (eid >= 0) ? src[eid] : 0;
            sdst[tid] = (eid >= 0) ? dst[eid] : 0;
        }
        __syncthreads();

        float acc[2][8][4];
#pragma unroll
        for (int mf = 0; mf < 2; mf++)
#pragma unroll
            for (int j = 0; j < 8; j++)
#pragma unroll
                for (int i = 0; i < 4; i++) acc[mf][j][i] = 0.f;

        for (int kh = 0; kh < 2; kh++) {
            for (int u = tid; u < 1024; u += 256) {
                int row = u >> 3, ch = u & 7;
                float4 v0 = make_float4(0.f, 0.f, 0.f, 0.f), v1 = v0;
                if (row < nt) {
                    float4 hs0 = ((const float4*)h)[(size_t)ssrc[row] * 32 + kh * 16 + ch * 2];
                    float4 hs1 = ((const float4*)h)[(size_t)ssrc[row] * 32 + kh * 16 + ch * 2 + 1];
                    float4 hd0 = ((const float4*)h)[(size_t)sdst[row] * 32 + kh * 16 + ch * 2];
                    float4 hd1 = ((const float4*)h)[(size_t)sdst[row] * 32 + kh * 16 + ch * 2 + 1];
                    v0.x = hs0.x * hd0.x; v0.y = hs0.y * hd0.y;
                    v0.z = hs0.z * hd0.z; v0.w = hs0.w * hd0.w;
                    v1.x = hs1.x * hd1.x; v1.y = hs1.y * hd1.y;
                    v1.z = hs1.z * hd1.z; v1.w = hs1.w * hd1.w;
                }
                uint4 hi, lo; cvt8(v0, v1, hi, lo);
                uint32_t off = soff64(row, ch * 8);
                *(uint4*)(sm + SM_AH + off) = hi;
                *(uint4*)(sm + SM_AL + off) = lo;
            }
            __syncthreads();
            gemm_half(smb, lane, wm, wn, kh, acc);
            __syncthreads();
        }

        float s0[2] = {0.f, 0.f}, s1[2] = {0.f, 0.f};
#pragma unroll
        for (int mf = 0; mf < 2; mf++)
#pragma unroll
            for (int j = 0; j < 8; j++) {
                float b0 = bias_s[wn * 64 + j * 8 + m * 2];
                float b1 = bias_s[wn * 64 + j * 8 + m * 2 + 1];
                s0[mf] += relu_(acc[mf][j][0] + b0) + relu_(acc[mf][j][1] + b1);
                s1[mf] += relu_(acc[mf][j][2] + b0) + relu_(acc[mf][j][3] + b1);
            }
#pragma unroll
        for (int mf = 0; mf < 2; mf++) {
            s0[mf] += __shfl_xor_sync(0xffffffffu, s0[mf], 1);
            s0[mf] += __shfl_xor_sync(0xffffffffu, s0[mf], 2);
            s1[mf] += __shfl_xor_sync(0xffffffffu, s1[mf], 1);
            s1[mf] += __shfl_xor_sync(0xffffffffu, s1[mf], 2);
        }
        if (m == 0) {
#pragma unroll
            for (int mf = 0; mf < 2; mf++) {
                svb[wn * 128 + wm * 32 + mf * 16 + q] = s0[mf];
                svb[wn * 128 + wm * 32 + mf * 16 + q + 8] = s1[mf];
            }
        }
        __syncthreads();

        // per-edge coefficient into smem
        if (tid < 128) {
            float cf = 0.f;
            if (tid < nt) {
                float sv = svb[tid] + svb[128 + tid];
                float L = g_enorm[seid[tid]];
                if (L > 1e-9f && sv > 0.f) {
                    float r = 0.5f * sqrtf(L);
                    cf = sv * expf(-r / 0.3f) / (1.2f * L * sqrtf(L));
                }
            }
            svb[256 + tid] = cf;
        }
        __syncthreads();

        // cooperative scatter: 256 threads, one float4 chunk each, v4 reductions
        const float* scf = svb + 256;
        for (int u = tid; u < 4096; u += 256) {
            int e = u >> 5, c4 = u & 31;
            float cf = scf[e];
            if (cf != 0.f) {
                int eid = seid[e];
                float4 en = ((const float4*)g_enew)[(size_t)eid * 32 + c4];
                float* fp = &g_facc[(size_t)sdst[e] * DD + c4 * 4];
                asm volatile(
                    "red.global.add.v4.f32 [%0], {%1, %2, %3, %4};"
                    :: "l"(fp), "f"(cf * en.x), "f"(cf * en.y),
                       "f"(cf * en.z), "f"(cf * en.w)
                    : "memory");
            }
        }
    }
}

// ================= node finalize =================
__global__ void k_final(const float* __restrict__ h, const float* __restrict__ p,
                        const float* __restrict__ dv, const float* __restrict__ dt,
                        float* __restrict__ out) {
    int w = threadIdx.x >> 5, l = threadIdx.x & 31;
    int n = blockIdx.x * 8 + w;
    int ix = n * 32 + l;
    const float4* V1 = (const float4*)g_proj[0];
    const float4* V2 = (const float4*)g_proj[1];
    const float4* P3 = (const float4*)g_proj[4];
    const float4* D1 = (const float4*)g_proj[5];
    const float4* D2 = (const float4*)g_proj[6];
    const float4* TA = (const float4*)g_proj[7];
    const float4* TB = (const float4*)g_proj[8];
    const float4* FA = (const float4*)g_facc;

    float4 v1 = V1[ix], v2 = V2[ix], p3 = P3[ix], d1 = D1[ix], d2 = D2[ix];
    float4 ta = TA[ix], tb = TB[ix], fa = FA[ix];
    float cnt = (float)g_cnt0[n];

    float4 th;
    th.x = ta.x + tb.x; th.y = ta.y + tb.y;
    th.z = ta.z + tb.z; th.w = ta.w + tb.w;

    float4 f;
    f.x = (d1.x - v1.x) * (cnt * relu_(th.x)) + fa.x;
    f.y = (d1.y - v1.y) * (cnt * relu_(th.y)) + fa.y;
    f.z = (d1.z - v1.z) * (cnt * relu_(th.z)) + fa.z;
    f.w = (d1.w - v1.w) * (cnt * relu_(th.w)) + fa.w;

    float sq = f.x * f.x + f.y * f.y + f.z * f.z + f.w * f.w;
#pragma unroll
    for (int off = 16; off > 0; off >>= 1) sq += __shfl_xor_sync(0xffffffffu, sq, off);
    float inv = 1.f / (sqrtf(sq) + 1e-9f);

    float dtv = dt[n];
    float dtp = dtv + 0.5f * dtv * dtv;

    float4 hv = ((const float4*)h)[ix];
    float4 pv = ((const float4*)p)[ix];
    float4 dvv = ((const float4*)dv)[ix];

    float4 ho, po, dq;
    ho.x = hv.x + lrelu(v2.x + f.x * dtv);
    ho.y = hv.y + lrelu(v2.y + f.y * dtv);
    ho.z = hv.z + lrelu(v2.z + f.z * dtv);
    ho.w = hv.w + lrelu(v2.w + f.w * dtv);
    po.x = pv.x + lrelu(p3.x + f.x * dtp);
    po.y = pv.y + lrelu(p3.y + f.y * dtp);
    po.z = pv.z + lrelu(p3.z + f.z * dtp);
    po.w = pv.w + lrelu(p3.w + f.w * dtp);
    dq.x = dvv.x + lrelu(d2.x + f.x * inv);
    dq.y = dvv.y + lrelu(d2.y + f.y * inv);
    dq.z = dvv.z + lrelu(d2.z + f.z * inv);
    dq.w = dvv.w + lrelu(d2.w + f.w * inv);

    float4* outH = (float4*)out;
    float4* outP = (float4*)(out + (size_t)NN * DD + (size_t)EE * DD);
    float4* outD = (float4*)(out + 2 * (size_t)NN * DD + (size_t)EE * DD);
    outH[ix] = ho;
    outP[ix] = po;
    outD[ix] = dq;
}

// ================= launch =================
extern "C" void kernel_launch(void* const* d_in, const int* in_sizes, int n_in,
                              void* d_out, int out_size) {
    const float* h   = (const float*)d_in[0];
    const float* e   = (const float*)d_in[1];
    const float* p   = (const float*)d_in[2];
    const float* dv  = (const float*)d_in[3];
    const float* dt  = (const float*)d_in[4];
    const int* smask = (const int*)d_in[5];
    const int* src   = (const int*)d_in[6];
    const int* dst   = (const int*)d_in[7];
    const float* W_V1 = (const float*)d_in[8],  *b_V1 = (const float*)d_in[9];
    const float* W_V2 = (const float*)d_in[10], *b_V2 = (const float*)d_in[11];
    const float* W_E1 = (const float*)d_in[12], *b_E1 = (const float*)d_in[13];
    const float* W_P1 = (const float*)d_in[14], *b_P1 = (const float*)d_in[15];
    const float* W_P2 = (const float*)d_in[16], *b_P2 = (const float*)d_in[17];
    const float* W_P3 = (const float*)d_in[18], *b_P3 = (const float*)d_in[19];
    const float* W_D1 = (const float*)d_in[20], *b_D1 = (const float*)d_in[21];
    const float* W_D2 = (const float*)d_in[22], *b_D2 = (const float*)d_in[23];
    const float* W_V  = (const float*)d_in[24], *b_V  = (const float*)d_in[25];
    const float* W_T  = (const float*)d_in[26], *b_T  = (const float*)d_in[27];
    float* out = (float*)d_out;

    cudaFuncSetAttribute(k_nodeg, cudaFuncAttributeMaxDynamicSharedMemorySize, SM_TOTAL);
    cudaFuncSetAttribute(k_edgeA, cudaFuncAttributeMaxDynamicSharedMemorySize, SM_TOTAL);
    cudaFuncSetAttribute(k_edgeB, cudaFuncAttributeMaxDynamicSharedMemorySize, SM_TOTAL);

    k_prep<<<640, 256>>>(W_V1, W_V2, W_P1, W_P2, W_P3, W_D1, W_D2, W_E1, W_V, W_T);
    k_count<<<EE / 256, 256>>>(smask, dst);
    k_nodeg<<<GRID_P, 256, SM_TOTAL>>>(h, p, dv, b_V1, b_V2, b_P1, b_P2, b_P3,
                                       b_D1, b_D2, b_T);
    k_edgeA<<<GRID_P, 256, SM_TOTAL>>>(e, src, dst, smask, b_E1, out + (size_t)NN * DD);
    k_edgeB<<<GRID_P, 256, SM_TOTAL>>>(h, b_V, src, dst);
    k_final<<<NN / 8, 256>>>(h, p, dv, dt, out);
}

// round 12
// speedup vs baseline: 1.3049x; 1.1498x over previous
#include <cuda_runtime.h>
#include <cuda_fp16.h>
#include <cstdint>
#include <math.h>

#define NN 10000
#define EE 320000
#define DD 128
#define NTILE_N 79      /* (NN+127)/128 */
#define NTILE_E 2500    /* EE/128 */
#define GRID_P 296      /* persistent grid: 148 SMs x 2 CTAs */

// ================= static device scratch =================
__device__ float g_proj[9][NN * DD];     // V1h V2h P1h P2h P3h D1h D2h ThA ThB
__device__ float g_enew[(size_t)EE * DD];
__device__ float g_enorm[EE];
__device__ float g_facc[NN * DD];
__device__ int   g_cnt0[NN];
__device__ int   g_mlist[EE];
__device__ int   g_mcount;
__device__ float g_bzero[DD];            // stays zero (module-load init)
// fp16 weight tiles in swizzled layout (32KB each):
// slots 0..6 node W (V1,V2,P1,P2,P3,D1,D2), 7 E1, 8 V, 9/10 = W_T halves
__device__ __align__(16) unsigned char g_wbh[11 * 32768];

__device__ __forceinline__ float lrelu(float x) { return x > 0.f ? x : 0.01f * x; }
__device__ __forceinline__ float relu_(float x) { return x > 0.f ? x : 0.f; }

__device__ __forceinline__ uint32_t smem_u32(const void* p) {
    uint32_t a;
    asm("{ .reg .u64 t; cvta.to.shared.u64 t, %1; cvt.u32.u64 %0, t; }" : "=r"(a) : "l"(p));
    return a;
}
__device__ __forceinline__ uint32_t pack2h(__half a, __half b) {
    __half2 t; t.x = a; t.y = b;
    return *reinterpret_cast<uint32_t*>(&t);
}
__device__ __forceinline__ void l2_prefetch(const void* p) {
    asm volatile("prefetch.global.L2 [%0];" :: "l"(p));
}

// swizzled byte offset inside a 128x128 fp16 tile: row stride 256B
__device__ __forceinline__ uint32_t soff(int r, int c) {
    return (uint32_t)((r << 8) + ((((c >> 3) ^ (r & 7)) << 4) | ((c & 7) << 1)));
}

__device__ __forceinline__ void ldsm4(uint32_t* r, uint32_t addr) {
    asm volatile("ldmatrix.sync.aligned.m8n8.x4.shared.b16 {%0,%1,%2,%3}, [%4];"
                 : "=r"(r[0]), "=r"(r[1]), "=r"(r[2]), "=r"(r[3]) : "r"(addr));
}
__device__ __forceinline__ void mma16816(float* d, const uint32_t* a,
                                         uint32_t b0, uint32_t b1) {
    asm volatile(
        "mma.sync.aligned.m16n8k16.row.col.f32.f16.f16.f32 "
        "{%0,%1,%2,%3}, {%4,%5,%6,%7}, {%8,%9}, {%0,%1,%2,%3};"
        : "+f"(d[0]), "+f"(d[1]), "+f"(d[2]), "+f"(d[3])
        : "r"(a[0]), "r"(a[1]), "r"(a[2]), "r"(a[3]), "r"(b0), "r"(b1));
}

// split 8 fp32 -> hi/lo fp16x2 quads
__device__ __forceinline__ void cvt8h(float4 v0, float4 v1, uint4& hi, uint4& lo) {
    __half a0 = __float2half_rn(v0.x), a1 = __float2half_rn(v0.y);
    __half a2 = __float2half_rn(v0.z), a3 = __float2half_rn(v0.w);
    __half a4 = __float2half_rn(v1.x), a5 = __float2half_rn(v1.y);
    __half a6 = __float2half_rn(v1.z), a7 = __float2half_rn(v1.w);
    hi.x = pack2h(a0, a1); hi.y = pack2h(a2, a3);
    hi.z = pack2h(a4, a5); hi.w = pack2h(a6, a7);
    lo.x = pack2h(__float2half_rn(v0.x - __half2float(a0)),
                  __float2half_rn(v0.y - __half2float(a1)));
    lo.y = pack2h(__float2half_rn(v0.z - __half2float(a2)),
                  __float2half_rn(v0.w - __half2float(a3)));
    lo.z = pack2h(__float2half_rn(v1.x - __half2float(a4)),
                  __float2half_rn(v1.y - __half2float(a5)));
    lo.w = pack2h(__float2half_rn(v1.z - __half2float(a6)),
                  __float2half_rn(v1.w - __half2float(a7)));
}

// shared memory layout (100352 bytes -> 2 CTAs/SM)
#define SM_BIAS 0
#define SM_ROWA 512
#define SM_ROWB 1024
#define SM_ROWC 1536
#define SM_SV   2048
#define SM_AH   4096                 /* 128x128 fp16 hi (32KB) */
#define SM_AL   (4096 + 32768)       /* 128x128 fp16 lo (32KB) */
#define SM_BH   (4096 + 65536)       /* 128x128 fp16 B  (32KB) RESIDENT */
#define SM_C    4096                 /* fp32 C 128rows x 512B, overlays AH+AL */
#define SM_TOTAL (4096 + 98304)

// C chunk-swizzled offset: row r (0..127), float4-chunk c4 (0..31)
__device__ __forceinline__ uint32_t coff(int r, int c4) {
    return (uint32_t)(SM_C + r * 512 + (((c4 ^ (r & 7)) & 31) << 4));
}

// ---- 2-term split GEMM over full K=128, warp tile 32(M) x 64(N), 8 warps ----
__device__ __forceinline__ void gemm(uint32_t smb, int lane, int wm, int wn,
                                     float (&acc)[2][8][4]) {
    const int fr = lane & 15;
    const int fc = (lane >> 4) << 3;
    const int m0 = wm * 32;
    const int n0 = wn * 64;
#pragma unroll
    for (int ks = 0; ks < 8; ks++) {
        const int kc = ks * 16 + fc;
        uint32_t aH[2][4], aL[2][4], bH[2][4];
        ldsm4(aH[0], smb + SM_AH + soff(m0 + fr, kc));
        ldsm4(aH[1], smb + SM_AH + soff(m0 + 16 + fr, kc));
        ldsm4(bH[0], smb + SM_BH + soff(n0 + fr, kc));
        ldsm4(aL[0], smb + SM_AL + soff(m0 + fr, kc));
        ldsm4(aL[1], smb + SM_AL + soff(m0 + 16 + fr, kc));
        int cur = 0;
#pragma unroll
        for (int bn = 0; bn < 4; bn++) {
            int nxt = cur ^ 1;
            if (bn < 3)
                ldsm4(bH[nxt], smb + SM_BH + soff(n0 + (bn + 1) * 16 + fr, kc));
#pragma unroll
            for (int mf = 0; mf < 2; mf++) {
                mma16816(acc[mf][2 * bn],     aH[mf], bH[cur][0], bH[cur][2]);
                mma16816(acc[mf][2 * bn + 1], aH[mf], bH[cur][1], bH[cur][3]);
                mma16816(acc[mf][2 * bn],     aL[mf], bH[cur][0], bH[cur][2]);
                mma16816(acc[mf][2 * bn + 1], aL[mf], bH[cur][1], bH[cur][3]);
            }
            cur = nxt;
        }
    }
}

__device__ __forceinline__ void copy_B(char* sm, int slot, int tid) {
    const uint4* gh = (const uint4*)(g_wbh + slot * 32768);
    uint4* bh = (uint4*)(sm + SM_BH);
    for (int i = tid; i < 2048; i += 256) bh[i] = gh[i];
}

// stage full-K A tile (dense rows from X, guarded)
__device__ __forceinline__ void stage_full(char* sm, int tid, const float* X,
                                           int r0, int limit) {
#pragma unroll
    for (int i = 0; i < 8; i++) {
        int u = tid + i * 256;
        int row = u >> 4, ch = u & 15;
        int g = r0 + row;
        float4 v0 = make_float4(0.f, 0.f, 0.f, 0.f), v1 = v0;
        if (g < limit) {
            v0 = ((const float4*)X)[(size_t)g * 32 + ch * 2];
            v1 = ((const float4*)X)[(size_t)g * 32 + ch * 2 + 1];
        }
        uint4 hi, lo; cvt8h(v0, v1, hi, lo);
        uint32_t off = soff(row, ch * 8);
        *(uint4*)(sm + SM_AH + off) = hi;
        *(uint4*)(sm + SM_AL + off) = lo;
    }
}

// ================= prep: zero scratch + weight fp16/swizzle =================
__global__ void k_prep(const float* W0, const float* W1, const float* W2, const float* W3,
                       const float* W4, const float* W5, const float* W6, const float* W7,
                       const float* W8, const float* WT) {
    const float* Wp[9] = {W0, W1, W2, W3, W4, W5, W6, W7, W8};
    int i = blockIdx.x * blockDim.x + threadIdx.x;
    int stride = gridDim.x * blockDim.x;
    for (int t = i; t < NN * DD; t += stride) g_facc[t] = 0.f;
    for (int t = i; t < NN; t += stride) g_cnt0[t] = 0;
    if (i == 0) g_mcount = 0;
    for (int t = i; t < 11 * 2048; t += stride) {
        int slot = t >> 11, r = t & 2047;
        int n = r >> 4, k8 = r & 15;
        const float* srcp;
        if (slot < 9) srcp = Wp[slot] + n * 128 + k8 * 8;
        else if (slot == 9) srcp = WT + n * 256 + k8 * 8;
        else srcp = WT + n * 256 + 128 + k8 * 8;
        float4 v0 = ((const float4*)srcp)[0];
        float4 v1 = ((const float4*)srcp)[1];
        uint4 hi;
        hi.x = pack2h(__float2half_rn(v0.x), __float2half_rn(v0.y));
        hi.y = pack2h(__float2half_rn(v0.z), __float2half_rn(v0.w));
        hi.z = pack2h(__float2half_rn(v1.x), __float2half_rn(v1.y));
        hi.w = pack2h(__float2half_rn(v1.z), __float2half_rn(v1.w));
        uint32_t off = (uint32_t)slot * 32768u + soff(n, k8 * 8);
        *reinterpret_cast<uint4*>(g_wbh + off) = hi;
    }
}

__global__ void k_count(const int* __restrict__ smask, const int* __restrict__ dst) {
    int e = blockIdx.x * 256 + threadIdx.x;
    int lane = threadIdx.x & 31;
    int sm_ = smask[e];
    int d_ = dst[e];
    unsigned bal = __ballot_sync(0xffffffffu, sm_ == 1);
    if (sm_ == 0) atomicAdd(&g_cnt0[d_], 1);
    int lead = bal ? (__ffs(bal) - 1) : 0;
    int basec = 0;
    if (bal && lane == lead) basec = atomicAdd(&g_mcount, __popc(bal));
    basec = __shfl_sync(0xffffffffu, basec, lead);
    if (sm_ == 1) g_mlist[basec + __popc(bal & ((1u << lane) - 1u))] = e;
}

// ================= node GEMMs: persistent, 9 uniform jobs =================
__global__ void __launch_bounds__(256, 2)
k_nodeg(const float* __restrict__ h, const float* __restrict__ p,
        const float* __restrict__ dv,
        const float* bV1, const float* bV2, const float* bP1,
        const float* bP2, const float* bP3, const float* bD1,
        const float* bD2, const float* bT) {
    extern __shared__ char sm[];
    uint32_t smb = smem_u32(sm);
    int tid = threadIdx.x, lane = tid & 31, wid = tid >> 5;
    int wm = wid & 3, wn = wid >> 2;
    int pidx = blockIdx.x % 9;
    int nct = (gridDim.x - 1 - pidx) / 9 + 1;

    const float* X;
    const float* bias;
    int slot;
    switch (pidx) {
        case 0: X = h;  slot = 0;  bias = bV1; break;
        case 1: X = h;  slot = 1;  bias = bV2; break;
        case 2: X = p;  slot = 2;  bias = bP1; break;
        case 3: X = p;  slot = 3;  bias = bP2; break;
        case 4: X = p;  slot = 4;  bias = bP3; break;
        case 5: X = dv; slot = 5;  bias = bD1; break;
        case 6: X = dv; slot = 6;  bias = bD2; break;
        case 7: X = h;  slot = 9;  bias = bT; break;
        default: X = dv; slot = 10; bias = g_bzero; break;
    }
    if (tid < 128) ((float*)(sm + SM_BIAS))[tid] = bias[tid];
    copy_B(sm, slot, tid);
    float* outp = g_proj[pidx];
    int q = lane >> 2, m = lane & 3;

    for (int t = blockIdx.x / 9; t < NTILE_N; t += nct) {
        int r0 = t * 128;
        __syncthreads();
        stage_full(sm, tid, X, r0, NN);
        // register-free L2 prefetch of next tile's X rows
        {
            int t2 = t + nct;
            if (t2 < NTILE_N) {
                const char* nb = (const char*)(X + (size_t)t2 * 128 * DD);
                int lines = min(128 * 4, (NN - t2 * 128) * 4);
#pragma unroll
                for (int i = 0; i < 2; i++) {
                    int ln = tid + i * 256;
                    if (ln < lines) l2_prefetch(nb + (size_t)ln * 128);
                }
            }
        }
        __syncthreads();

        float acc[2][8][4];
#pragma unroll
        for (int mf = 0; mf < 2; mf++)
#pragma unroll
            for (int j = 0; j < 8; j++)
#pragma unroll
                for (int i = 0; i < 4; i++) acc[mf][j][i] = 0.f;
        gemm(smb, lane, wm, wn, acc);

        // register epilogue
        const float* bias_s = (const float*)(sm + SM_BIAS);
#pragma unroll
        for (int mf = 0; mf < 2; mf++) {
            int r1 = r0 + wm * 32 + mf * 16 + q;
            int r2 = r1 + 8;
#pragma unroll
            for (int j = 0; j < 8; j++) {
                int col = wn * 64 + j * 8 + m * 2;
                float b0 = bias_s[col], b1 = bias_s[col + 1];
                if (r1 < NN)
                    *(float2*)&outp[(size_t)r1 * DD + col] =
                        make_float2(acc[mf][j][0] + b0, acc[mf][j][1] + b1);
                if (r2 < NN)
                    *(float2*)&outp[(size_t)r2 * DD + col] =
                        make_float2(acc[mf][j][2] + b0, acc[mf][j][3] + b1);
            }
        }
    }
}

// ================= edge pass A: persistent, resident B, smem-C epilogue ==========
__global__ void __launch_bounds__(256, 2)
k_edgeA(const float* __restrict__ e_in, const int* __restrict__ src,
        const int* __restrict__ dst, const int* __restrict__ smask,
        const float* __restrict__ bE1, float* __restrict__ e_out) {
    extern __shared__ char sm[];
    uint32_t smb = smem_u32(sm);
    int tid = threadIdx.x, lane = tid & 31, wid = tid >> 5;
    int wm = wid & 3, wn = wid >> 2;
    int q = lane >> 2, m = lane & 3;

    if (tid < 128) ((float*)(sm + SM_BIAS))[tid] = bE1[tid];
    copy_B(sm, 7, tid);
    const float* P1 = g_proj[2];
    const float* P2 = g_proj[3];

    for (int t = blockIdx.x; t < NTILE_E; t += gridDim.x) {
        int e0 = t * 128;
        __syncthreads();
        if (tid < 128) {
            int eg = e0 + tid;
            ((int*)(sm + SM_ROWA))[tid] = src[eg];
            ((int*)(sm + SM_ROWB))[tid] = dst[eg];
            ((int*)(sm + SM_ROWC))[tid] = smask[eg];
        }
        stage_full(sm, tid, e_in, e0, EE);
        // register-free L2 prefetch of next tile's e_in
        {
            int t2 = t + gridDim.x;
            if (t2 < NTILE_E) {
                const char* nb = (const char*)(e_in + (size_t)t2 * 128 * DD);
#pragma unroll
                for (int i = 0; i < 2; i++)
                    l2_prefetch(nb + (size_t)(tid + i * 256) * 128);
            }
        }
        __syncthreads();

        float acc[2][8][4];
#pragma unroll
        for (int mf = 0; mf < 2; mf++)
#pragma unroll
            for (int j = 0; j < 8; j++)
#pragma unroll
                for (int i = 0; i < 4; i++) acc[mf][j][i] = 0.f;
        gemm(smb, lane, wm, wn, acc);
        __syncthreads();

        // store C (128 rows x 512B, overlays A region)
#pragma unroll
        for (int mf = 0; mf < 2; mf++) {
            int r1 = wm * 32 + mf * 16 + q;
#pragma unroll
            for (int j = 0; j < 8; j++) {
                int col = wn * 64 + j * 8 + m * 2;
                int c4 = col >> 2;
                uint32_t inoff = (uint32_t)((m & 1) * 8);
                *(float2*)(sm + coff(r1, c4) + inoff) =
                    make_float2(acc[mf][j][0], acc[mf][j][1]);
                *(float2*)(sm + coff(r1 + 8, c4) + inoff) =
                    make_float2(acc[mf][j][2], acc[mf][j][3]);
            }
        }
        __syncthreads();

        const float* bias_s = (const float*)(sm + SM_BIAS);
        const int* ssrc = (const int*)(sm + SM_ROWA);
        const int* sdst = (const int*)(sm + SM_ROWB);
        const int* smsk = (const int*)(sm + SM_ROWC);
        for (int u = tid; u < 4096; u += 256) {
            int lr = u >> 5, c4 = u & 31;   // c4 == lane
            int eg = e0 + lr;
            int si = ssrc[lr], di = sdst[lr], msk = smsk[lr];
            float4 cC = *(float4*)(sm + coff(lr, c4));
            float4 bv = *(const float4*)&bias_s[c4 * 4];
            float4 p1 = *(const float4*)&P1[(size_t)di * DD + c4 * 4];
            float4 p2 = *(const float4*)&P2[(size_t)si * DD + c4 * 4];
            float4 ev = *(const float4*)&e_in[(size_t)eg * DD + c4 * 4];
            float4 en;
            en.x = 0.5f * (p1.x - p2.x + cC.x + bv.x);
            en.y = 0.5f * (p1.y - p2.y + cC.y + bv.y);
            en.z = 0.5f * (p1.z - p2.z + cC.z + bv.z);
            en.w = 0.5f * (p1.w - p2.w + cC.w + bv.w);
            float4 o;
            o.x = ev.x + lrelu(en.x);
            o.y = ev.y + lrelu(en.y);
            o.z = ev.z + lrelu(en.z);
            o.w = ev.w + lrelu(en.w);
            *(float4*)&e_out[(size_t)eg * DD + c4 * 4] = o;
            if (msk) *(float4*)&g_enew[(size_t)eg * DD + c4 * 4] = en;
            // row-norm: whole row eg lives in this warp (lane == c4)
            float sq = en.x * en.x + en.y * en.y + en.z * en.z + en.w * en.w;
#pragma unroll
            for (int off = 16; off > 0; off >>= 1)
                sq += __shfl_xor_sync(0xffffffffu, sq, off);
            if (c4 == 0 && msk) g_enorm[eg] = sqrtf(sq);
        }
    }
}

// ================= edge pass B: persistent, resident B, masked V GEMM =============
__global__ void __launch_bounds__(256, 2)
k_edgeB(const float* __restrict__ h, const float* __restrict__ bV,
        const int* __restrict__ src, const int* __restrict__ dst) {
    extern __shared__ char sm[];
    uint32_t smb = smem_u32(sm);
    int tid = threadIdx.x, lane = tid & 31, wid = tid >> 5;
    int wm = wid & 3, wn = wid >> 2;
    int q = lane >> 2, m = lane & 3;
    int mc = g_mcount;
    int ntiles = (mc + 127) >> 7;

    if (tid < 128) ((float*)(sm + SM_BIAS))[tid] = bV[tid];
    copy_B(sm, 8, tid);
    int* seid = (int*)(sm + SM_ROWC);
    int* ssrc = (int*)(sm + SM_ROWA);
    int* sdst = (int*)(sm + SM_ROWB);
    const float* bias_s = (const float*)(sm + SM_BIAS);
    float* svb = (float*)(sm + SM_SV);

    for (int t = blockIdx.x; t < ntiles; t += gridDim.x) {
        int base = t * 128;
        int nt = min(128, mc - base);
        __syncthreads();
        if (tid < 128) {
            int eid = (tid < nt) ? g_mlist[base + tid] : -1;
            seid[tid] = eid;
            ssrc[tid] = (eid >= 0) ? src[eid] : 0;
            sdst[tid] = (eid >= 0) ? dst[eid] : 0;
        }
        __syncthreads();

        // stage full-K A = h[src]*h[dst]
#pragma unroll
        for (int i = 0; i < 8; i++) {
            int u = tid + i * 256;
            int row = u >> 4, ch = u & 15;
            float4 v0 = make_float4(0.f, 0.f, 0.f, 0.f), v1 = v0;
            if (row < nt) {
                float4 hs0 = ((const float4*)h)[(size_t)ssrc[row] * 32 + ch * 2];
                float4 hs1 = ((const float4*)h)[(size_t)ssrc[row] * 32 + ch * 2 + 1];
                float4 hd0 = ((const float4*)h)[(size_t)sdst[row] * 32 + ch * 2];
                float4 hd1 = ((const float4*)h)[(size_t)sdst[row] * 32 + ch * 2 + 1];
                v0.x = hs0.x * hd0.x; v0.y = hs0.y * hd0.y;
                v0.z = hs0.z * hd0.z; v0.w = hs0.w * hd0.w;
                v1.x = hs1.x * hd1.x; v1.y = hs1.y * hd1.y;
                v1.z = hs1.z * hd1.z; v1.w = hs1.w * hd1.w;
            }
            uint4 hi, lo; cvt8h(v0, v1, hi, lo);
            uint32_t off = soff(row, ch * 8);
            *(uint4*)(sm + SM_AH + off) = hi;
            *(uint4*)(sm + SM_AL + off) = lo;
        }
        __syncthreads();

        float acc[2][8][4];
#pragma unroll
        for (int mf = 0; mf < 2; mf++)
#pragma unroll
            for (int j = 0; j < 8; j++)
#pragma unroll
                for (int i = 0; i < 4; i++) acc[mf][j][i] = 0.f;
        gemm(smb, lane, wm, wn, acc);

        float s0[2] = {0.f, 0.f}, s1[2] = {0.f, 0.f};
#pragma unroll
        for (int mf = 0; mf < 2; mf++)
#pragma unroll
            for (int j = 0; j < 8; j++) {
                float b0 = bias_s[wn * 64 + j * 8 + m * 2];
                float b1 = bias_s[wn * 64 + j * 8 + m * 2 + 1];
                s0[mf] += relu_(acc[mf][j][0] + b0) + relu_(acc[mf][j][1] + b1);
                s1[mf] += relu_(acc[mf][j][2] + b0) + relu_(acc[mf][j][3] + b1);
            }
#pragma unroll
        for (int mf = 0; mf < 2; mf++) {
            s0[mf] += __shfl_xor_sync(0xffffffffu, s0[mf], 1);
            s0[mf] += __shfl_xor_sync(0xffffffffu, s0[mf], 2);
            s1[mf] += __shfl_xor_sync(0xffffffffu, s1[mf], 1);
            s1[mf] += __shfl_xor_sync(0xffffffffu, s1[mf], 2);
        }
        if (m == 0) {
#pragma unroll
            for (int mf = 0; mf < 2; mf++) {
                svb[wn * 128 + wm * 32 + mf * 16 + q] = s0[mf];
                svb[wn * 128 + wm * 32 + mf * 16 + q + 8] = s1[mf];
            }
        }
        __syncthreads();

        // per-edge coefficient into smem
        if (tid < 128) {
            float cf = 0.f;
            if (tid < nt) {
                float sv = svb[tid] + svb[128 + tid];
                float L = g_enorm[seid[tid]];
                if (L > 1e-9f && sv > 0.f) {
                    float r = 0.5f * sqrtf(L);
                    cf = sv * expf(-r / 0.3f) / (1.2f * L * sqrtf(L));
                }
            }
            svb[256 + tid] = cf;
        }
        __syncthreads();

        // cooperative scatter: 256 threads, one float4 chunk each, v4 reductions
        const float* scf = svb + 256;
        for (int u = tid; u < 4096; u += 256) {
            int e = u >> 5, c4 = u & 31;
            float cf = scf[e];
            if (cf != 0.f) {
                int eid = seid[e];
                float4 en = ((const float4*)g_enew)[(size_t)eid * 32 + c4];
                float* fp = &g_facc[(size_t)sdst[e] * DD + c4 * 4];
                asm volatile(
                    "red.global.add.v4.f32 [%0], {%1, %2, %3, %4};"
                    :: "l"(fp), "f"(cf * en.x), "f"(cf * en.y),
                       "f"(cf * en.z), "f"(cf * en.w)
                    : "memory");
            }
        }
    }
}

// ================= node finalize =================
__global__ void k_final(const float* __restrict__ h, const float* __restrict__ p,
                        const float* __restrict__ dv, const float* __restrict__ dt,
                        float* __restrict__ out) {
    int w = threadIdx.x >> 5, l = threadIdx.x & 31;
    int n = blockIdx.x * 8 + w;
    int ix = n * 32 + l;
    const float4* V1 = (const float4*)g_proj[0];
    const float4* V2 = (const float4*)g_proj[1];
    const float4* P3 = (const float4*)g_proj[4];
    const float4* D1 = (const float4*)g_proj[5];
    const float4* D2 = (const float4*)g_proj[6];
    const float4* TA = (const float4*)g_proj[7];
    const float4* TB = (const float4*)g_proj[8];
    const float4* FA = (const float4*)g_facc;

    float4 v1 = V1[ix], v2 = V2[ix], p3 = P3[ix], d1 = D1[ix], d2 = D2[ix];
    float4 ta = TA[ix], tb = TB[ix], fa = FA[ix];
    float cnt = (float)g_cnt0[n];

    float4 th;
    th.x = ta.x + tb.x; th.y = ta.y + tb.y;
    th.z = ta.z + tb.z; th.w = ta.w + tb.w;

    float4 f;
    f.x = (d1.x - v1.x) * (cnt * relu_(th.x)) + fa.x;
    f.y = (d1.y - v1.y) * (cnt * relu_(th.y)) + fa.y;
    f.z = (d1.z - v1.z) * (cnt * relu_(th.z)) + fa.z;
    f.w = (d1.w - v1.w) * (cnt * relu_(th.w)) + fa.w;

    float sq = f.x * f.x + f.y * f.y + f.z * f.z + f.w * f.w;
#pragma unroll
    for (int off = 16; off > 0; off >>= 1) sq += __shfl_xor_sync(0xffffffffu, sq, off);
    float inv = 1.f / (sqrtf(sq) + 1e-9f);

    float dtv = dt[n];
    float dtp = dtv + 0.5f * dtv * dtv;

    float4 hv = ((const float4*)h)[ix];
    float4 pv = ((const float4*)p)[ix];
    float4 dvv = ((const float4*)dv)[ix];

    float4 ho, po, dq;
    ho.x = hv.x + lrelu(v2.x + f.x * dtv);
    ho.y = hv.y + lrelu(v2.y + f.y * dtv);
    ho.z = hv.z + lrelu(v2.z + f.z * dtv);
    ho.w = hv.w + lrelu(v2.w + f.w * dtv);
    po.x = pv.x + lrelu(p3.x + f.x * dtp);
    po.y = pv.y + lrelu(p3.y + f.y * dtp);
    po.z = pv.z + lrelu(p3.z + f.z * dtp);
    po.w = pv.w + lrelu(p3.w + f.w * dtp);
    dq.x = dvv.x + lrelu(d2.x + f.x * inv);
    dq.y = dvv.y + lrelu(d2.y + f.y * inv);
    dq.z = dvv.z + lrelu(d2.z + f.z * inv);
    dq.w = dvv.w + lrelu(d2.w + f.w * inv);

    float4* outH = (float4*)out;
    float4* outP = (float4*)(out + (size_t)NN * DD + (size_t)EE * DD);
    float4* outD = (float4*)(out + 2 * (size_t)NN * DD + (size_t)EE * DD);
    outH[ix] = ho;
    outP[ix] = po;
    outD[ix] = dq;
}

// ================= launch =================
extern "C" void kernel_launch(void* const* d_in, const int* in_sizes, int n_in,
                              void* d_out, int out_size) {
    const float* h   = (const float*)d_in[0];
    const float* e   = (const float*)d_in[1];
    const float* p   = (const float*)d_in[2];
    const float* dv  = (const float*)d_in[3];
    const float* dt  = (const float*)d_in[4];
    const int* smask = (const int*)d_in[5];
    const int* src   = (const int*)d_in[6];
    const int* dst   = (const int*)d_in[7];
    const float* W_V1 = (const float*)d_in[8],  *b_V1 = (const float*)d_in[9];
    const float* W_V2 = (const float*)d_in[10], *b_V2 = (const float*)d_in[11];
    const float* W_E1 = (const float*)d_in[12], *b_E1 = (const float*)d_in[13];
    const float* W_P1 = (const float*)d_in[14], *b_P1 = (const float*)d_in[15];
    const float* W_P2 = (const float*)d_in[16], *b_P2 = (const float*)d_in[17];
    const float* W_P3 = (const float*)d_in[18], *b_P3 = (const float*)d_in[19];
    const float* W_D1 = (const float*)d_in[20], *b_D1 = (const float*)d_in[21];
    const float* W_D2 = (const float*)d_in[22], *b_D2 = (const float*)d_in[23];
    const float* W_V  = (const float*)d_in[24], *b_V  = (const float*)d_in[25];
    const float* W_T  = (const float*)d_in[26], *b_T  = (const float*)d_in[27];
    float* out = (float*)d_out;

    cudaFuncSetAttribute(k_nodeg, cudaFuncAttributeMaxDynamicSharedMemorySize, SM_TOTAL);
    cudaFuncSetAttribute(k_edgeA, cudaFuncAttributeMaxDynamicSharedMemorySize, SM_TOTAL);
    cudaFuncSetAttribute(k_edgeB, cudaFuncAttributeMaxDynamicSharedMemorySize, SM_TOTAL);

    k_prep<<<640, 256>>>(W_V1, W_V2, W_P1, W_P2, W_P3, W_D1, W_D2, W_E1, W_V, W_T);
    k_count<<<EE / 256, 256>>>(smask, dst);
    k_nodeg<<<GRID_P, 256, SM_TOTAL>>>(h, p, dv, b_V1, b_V2, b_P1, b_P2, b_P3,
                                       b_D1, b_D2, b_T);
    k_edgeA<<<GRID_P, 256, SM_TOTAL>>>(e, src, dst, smask, b_E1, out + (size_t)NN * DD);
    k_edgeB<<<GRID_P, 256, SM_TOTAL>>>(h, b_V, src, dst);
    k_final<<<NN / 8, 256>>>(h, p, dv, dt, out);
}

// round 13
// speedup vs baseline: 1.4363x; 1.1007x over previous
#include <cuda_runtime.h>
#include <cuda_fp16.h>
#include <cstdint>
#include <math.h>

#define NN 10000
#define EE 320000
#define DD 128
#define NTILE_N 79      /* (NN+127)/128 */
#define NTILE_E 2500    /* EE/128 */
#define GRID_P 296      /* persistent grid: 148 SMs x 2 CTAs */

// ================= static device scratch =================
__device__ float g_proj[9][NN * DD];     // V1h V2h P1h P2h P3h D1h D2h ThA ThB
__device__ float g_enew[(size_t)EE * DD];
__device__ float g_enorm[EE];
__device__ float g_facc[NN * DD];
__device__ int   g_cnt0[NN];
__device__ int   g_mlist[EE];
__device__ int   g_mcount;
__device__ float g_bzero[DD];            // stays zero (module-load init)
// fp16 weight tiles in swizzled layout (32KB each):
// slots 0..6 node W (V1,V2,P1,P2,P3,D1,D2), 7 E1, 8 V, 9/10 = W_T halves
__device__ __align__(16) unsigned char g_wbh[11 * 32768];

__device__ __forceinline__ float lrelu(float x) { return x > 0.f ? x : 0.01f * x; }
__device__ __forceinline__ float relu_(float x) { return x > 0.f ? x : 0.f; }

__device__ __forceinline__ uint32_t smem_u32(const void* p) {
    uint32_t a;
    asm("{ .reg .u64 t; cvta.to.shared.u64 t, %1; cvt.u32.u64 %0, t; }" : "=r"(a) : "l"(p));
    return a;
}
__device__ __forceinline__ uint32_t pack2h(__half a, __half b) {
    __half2 t; t.x = a; t.y = b;
    return *reinterpret_cast<uint32_t*>(&t);
}
__device__ __forceinline__ void l2_prefetch(const void* p) {
    asm volatile("prefetch.global.L2 [%0];" :: "l"(p));
}

// swizzled byte offset inside a 128x128 fp16 tile: row stride 256B
__device__ __forceinline__ uint32_t soff(int r, int c) {
    return (uint32_t)((r << 8) + ((((c >> 3) ^ (r & 7)) << 4) | ((c & 7) << 1)));
}

__device__ __forceinline__ void ldsm4(uint32_t* r, uint32_t addr) {
    asm volatile("ldmatrix.sync.aligned.m8n8.x4.shared.b16 {%0,%1,%2,%3}, [%4];"
                 : "=r"(r[0]), "=r"(r[1]), "=r"(r[2]), "=r"(r[3]) : "r"(addr));
}
__device__ __forceinline__ void mma16816(float* d, const uint32_t* a,
                                         uint32_t b0, uint32_t b1) {
    asm volatile(
        "mma.sync.aligned.m16n8k16.row.col.f32.f16.f16.f32 "
        "{%0,%1,%2,%3}, {%4,%5,%6,%7}, {%8,%9}, {%0,%1,%2,%3};"
        : "+f"(d[0]), "+f"(d[1]), "+f"(d[2]), "+f"(d[3])
        : "r"(a[0]), "r"(a[1]), "r"(a[2]), "r"(a[3]), "r"(b0), "r"(b1));
}

// convert 8 fp32 -> fp16x2 quad
__device__ __forceinline__ void cvt8s(float4 v0, float4 v1, uint4& hi) {
    hi.x = pack2h(__float2half_rn(v0.x), __float2half_rn(v0.y));
    hi.y = pack2h(__float2half_rn(v0.z), __float2half_rn(v0.w));
    hi.z = pack2h(__float2half_rn(v1.x), __float2half_rn(v1.y));
    hi.w = pack2h(__float2half_rn(v1.z), __float2half_rn(v1.w));
}

// shared memory layout (102400 bytes -> 2 CTAs/SM)
#define SM_BIAS 0
#define SM_ROWA 512
#define SM_ROWB 1024
#define SM_ROWC 1536
#define SM_SV   2048
#define SM_AH   4096                 /* 128x128 fp16 A (32KB) */
#define SM_SPARE (4096 + 32768)      /* 32KB (C spill area)   */
#define SM_BH   (4096 + 65536)       /* 128x128 fp16 B (32KB) RESIDENT */
#define SM_C    4096                 /* fp32 C 128rows x 512B, overlays AH+SPARE */
#define SM_TOTAL (4096 + 98304)

// C chunk-swizzled offset: row r (0..127), float4-chunk c4 (0..31)
__device__ __forceinline__ uint32_t coff(int r, int c4) {
    return (uint32_t)(SM_C + r * 512 + (((c4 ^ (r & 7)) & 31) << 4));
}

// ---- single-fp16 GEMM over full K=128, warp tile 32(M) x 64(N), 8 warps ----
__device__ __forceinline__ void gemm(uint32_t smb, int lane, int wm, int wn,
                                     float (&acc)[2][8][4]) {
    const int fr = lane & 15;
    const int fc = (lane >> 4) << 3;
    const int m0 = wm * 32;
    const int n0 = wn * 64;
#pragma unroll
    for (int ks = 0; ks < 8; ks++) {
        const int kc = ks * 16 + fc;
        uint32_t aH[2][4], bH[2][4];
        ldsm4(aH[0], smb + SM_AH + soff(m0 + fr, kc));
        ldsm4(aH[1], smb + SM_AH + soff(m0 + 16 + fr, kc));
        ldsm4(bH[0], smb + SM_BH + soff(n0 + fr, kc));
        int cur = 0;
#pragma unroll
        for (int bn = 0; bn < 4; bn++) {
            int nxt = cur ^ 1;
            if (bn < 3)
                ldsm4(bH[nxt], smb + SM_BH + soff(n0 + (bn + 1) * 16 + fr, kc));
#pragma unroll
            for (int mf = 0; mf < 2; mf++) {
                mma16816(acc[mf][2 * bn],     aH[mf], bH[cur][0], bH[cur][2]);
                mma16816(acc[mf][2 * bn + 1], aH[mf], bH[cur][1], bH[cur][3]);
            }
            cur = nxt;
        }
    }
}

__device__ __forceinline__ void copy_B(char* sm, int slot, int tid) {
    const uint4* gh = (const uint4*)(g_wbh + slot * 32768);
    uint4* bh = (uint4*)(sm + SM_BH);
    for (int i = tid; i < 2048; i += 256) bh[i] = gh[i];
}

// stage full-K A tile (dense rows from X, guarded)
__device__ __forceinline__ void stage_full(char* sm, int tid, const float* X,
                                           int r0, int limit) {
#pragma unroll
    for (int i = 0; i < 8; i++) {
        int u = tid + i * 256;
        int row = u >> 4, ch = u & 15;
        int g = r0 + row;
        float4 v0 = make_float4(0.f, 0.f, 0.f, 0.f), v1 = v0;
        if (g < limit) {
            v0 = ((const float4*)X)[(size_t)g * 32 + ch * 2];
            v1 = ((const float4*)X)[(size_t)g * 32 + ch * 2 + 1];
        }
        uint4 hi; cvt8s(v0, v1, hi);
        *(uint4*)(sm + SM_AH + soff(row, ch * 8)) = hi;
    }
}

// ================= prep: zero scratch + weight fp16/swizzle =================
__global__ void k_prep(const float* W0, const float* W1, const float* W2, const float* W3,
                       const float* W4, const float* W5, const float* W6, const float* W7,
                       const float* W8, const float* WT) {
    const float* Wp[9] = {W0, W1, W2, W3, W4, W5, W6, W7, W8};
    int i = blockIdx.x * blockDim.x + threadIdx.x;
    int stride = gridDim.x * blockDim.x;
    for (int t = i; t < NN * DD; t += stride) g_facc[t] = 0.f;
    for (int t = i; t < NN; t += stride) g_cnt0[t] = 0;
    if (i == 0) g_mcount = 0;
    for (int t = i; t < 11 * 2048; t += stride) {
        int slot = t >> 11, r = t & 2047;
        int n = r >> 4, k8 = r & 15;
        const float* srcp;
        if (slot < 9) srcp = Wp[slot] + n * 128 + k8 * 8;
        else if (slot == 9) srcp = WT + n * 256 + k8 * 8;
        else srcp = WT + n * 256 + 128 + k8 * 8;
        float4 v0 = ((const float4*)srcp)[0];
        float4 v1 = ((const float4*)srcp)[1];
        uint4 hi; cvt8s(v0, v1, hi);
        uint32_t off = (uint32_t)slot * 32768u + soff(n, k8 * 8);
        *reinterpret_cast<uint4*>(g_wbh + off) = hi;
    }
}

__global__ void k_count(const int* __restrict__ smask, const int* __restrict__ dst) {
    int e = blockIdx.x * 256 + threadIdx.x;
    int lane = threadIdx.x & 31;
    int sm_ = smask[e];
    int d_ = dst[e];
    unsigned bal = __ballot_sync(0xffffffffu, sm_ == 1);
    if (sm_ == 0) atomicAdd(&g_cnt0[d_], 1);
    int lead = bal ? (__ffs(bal) - 1) : 0;
    int basec = 0;
    if (bal && lane == lead) basec = atomicAdd(&g_mcount, __popc(bal));
    basec = __shfl_sync(0xffffffffu, basec, lead);
    if (sm_ == 1) g_mlist[basec + __popc(bal & ((1u << lane) - 1u))] = e;
}

// ================= node GEMMs: persistent, 9 uniform jobs =================
__global__ void __launch_bounds__(256, 2)
k_nodeg(const float* __restrict__ h, const float* __restrict__ p,
        const float* __restrict__ dv,
        const float* bV1, const float* bV2, const float* bP1,
        const float* bP2, const float* bP3, const float* bD1,
        const float* bD2, const float* bT) {
    extern __shared__ char sm[];
    uint32_t smb = smem_u32(sm);
    int tid = threadIdx.x, lane = tid & 31, wid = tid >> 5;
    int wm = wid & 3, wn = wid >> 2;
    int pidx = blockIdx.x % 9;
    int nct = (gridDim.x - 1 - pidx) / 9 + 1;

    const float* X;
    const float* bias;
    int slot;
    switch (pidx) {
        case 0: X = h;  slot = 0;  bias = bV1; break;
        case 1: X = h;  slot = 1;  bias = bV2; break;
        case 2: X = p;  slot = 2;  bias = bP1; break;
        case 3: X = p;  slot = 3;  bias = bP2; break;
        case 4: X = p;  slot = 4;  bias = bP3; break;
        case 5: X = dv; slot = 5;  bias = bD1; break;
        case 6: X = dv; slot = 6;  bias = bD2; break;
        case 7: X = h;  slot = 9;  bias = bT; break;
        default: X = dv; slot = 10; bias = g_bzero; break;
    }
    if (tid < 128) ((float*)(sm + SM_BIAS))[tid] = bias[tid];
    copy_B(sm, slot, tid);
    float* outp = g_proj[pidx];
    int q = lane >> 2, m = lane & 3;

    for (int t = blockIdx.x / 9; t < NTILE_N; t += nct) {
        int r0 = t * 128;
        __syncthreads();
        stage_full(sm, tid, X, r0, NN);
        // register-free L2 prefetch of next tile's X rows
        {
            int t2 = t + nct;
            if (t2 < NTILE_N) {
                const char* nb = (const char*)(X + (size_t)t2 * 128 * DD);
                int lines = min(128 * 4, (NN - t2 * 128) * 4);
#pragma unroll
                for (int i = 0; i < 2; i++) {
                    int ln = tid + i * 256;
                    if (ln < lines) l2_prefetch(nb + (size_t)ln * 128);
                }
            }
        }
        __syncthreads();

        float acc[2][8][4];
#pragma unroll
        for (int mf = 0; mf < 2; mf++)
#pragma unroll
            for (int j = 0; j < 8; j++)
#pragma unroll
                for (int i = 0; i < 4; i++) acc[mf][j][i] = 0.f;
        gemm(smb, lane, wm, wn, acc);

        // register epilogue
        const float* bias_s = (const float*)(sm + SM_BIAS);
#pragma unroll
        for (int mf = 0; mf < 2; mf++) {
            int r1 = r0 + wm * 32 + mf * 16 + q;
            int r2 = r1 + 8;
#pragma unroll
            for (int j = 0; j < 8; j++) {
                int col = wn * 64 + j * 8 + m * 2;
                float b0 = bias_s[col], b1 = bias_s[col + 1];
                if (r1 < NN)
                    *(float2*)&outp[(size_t)r1 * DD + col] =
                        make_float2(acc[mf][j][0] + b0, acc[mf][j][1] + b1);
                if (r2 < NN)
                    *(float2*)&outp[(size_t)r2 * DD + col] =
                        make_float2(acc[mf][j][2] + b0, acc[mf][j][3] + b1);
            }
        }
    }
}

// ================= edge pass A: persistent, resident B, smem-C epilogue ==========
__global__ void __launch_bounds__(256, 2)
k_edgeA(const float* __restrict__ e_in, const int* __restrict__ src,
        const int* __restrict__ dst, const int* __restrict__ smask,
        const float* __restrict__ bE1, float* __restrict__ e_out) {
    extern __shared__ char sm[];
    uint32_t smb = smem_u32(sm);
    int tid = threadIdx.x, lane = tid & 31, wid = tid >> 5;
    int wm = wid & 3, wn = wid >> 2;
    int q = lane >> 2, m = lane & 3;

    if (tid < 128) ((float*)(sm + SM_BIAS))[tid] = bE1[tid];
    copy_B(sm, 7, tid);
    const float* P1 = g_proj[2];
    const float* P2 = g_proj[3];

    for (int t = blockIdx.x; t < NTILE_E; t += gridDim.x) {
        int e0 = t * 128;
        __syncthreads();
        if (tid < 128) {
            int eg = e0 + tid;
            ((int*)(sm + SM_ROWA))[tid] = src[eg];
            ((int*)(sm + SM_ROWB))[tid] = dst[eg];
            ((int*)(sm + SM_ROWC))[tid] = smask[eg];
        }
        stage_full(sm, tid, e_in, e0, EE);
        // register-free L2 prefetch of next tile's e_in
        {
            int t2 = t + gridDim.x;
            if (t2 < NTILE_E) {
                const char* nb = (const char*)(e_in + (size_t)t2 * 128 * DD);
#pragma unroll
                for (int i = 0; i < 2; i++)
                    l2_prefetch(nb + (size_t)(tid + i * 256) * 128);
            }
        }
        __syncthreads();

        float acc[2][8][4];
#pragma unroll
        for (int mf = 0; mf < 2; mf++)
#pragma unroll
            for (int j = 0; j < 8; j++)
#pragma unroll
                for (int i = 0; i < 4; i++) acc[mf][j][i] = 0.f;
        gemm(smb, lane, wm, wn, acc);
        __syncthreads();

        // store C (128 rows x 512B, overlays AH+SPARE)
#pragma unroll
        for (int mf = 0; mf < 2; mf++) {
            int r1 = wm * 32 + mf * 16 + q;
#pragma unroll
            for (int j = 0; j < 8; j++) {
                int col = wn * 64 + j * 8 + m * 2;
                int c4 = col >> 2;
                uint32_t inoff = (uint32_t)((m & 1) * 8);
                *(float2*)(sm + coff(r1, c4) + inoff) =
                    make_float2(acc[mf][j][0], acc[mf][j][1]);
                *(float2*)(sm + coff(r1 + 8, c4) + inoff) =
                    make_float2(acc[mf][j][2], acc[mf][j][3]);
            }
        }
        __syncthreads();

        const float* bias_s = (const float*)(sm + SM_BIAS);
        const int* ssrc = (const int*)(sm + SM_ROWA);
        const int* sdst = (const int*)(sm + SM_ROWB);
        const int* smsk = (const int*)(sm + SM_ROWC);
        for (int u = tid; u < 4096; u += 256) {
            int lr = u >> 5, c4 = u & 31;   // c4 == lane
            int eg = e0 + lr;
            int si = ssrc[lr], di = sdst[lr], msk = smsk[lr];
            float4 cC = *(float4*)(sm + coff(lr, c4));
            float4 bv = *(const float4*)&bias_s[c4 * 4];
            float4 p1 = *(const float4*)&P1[(size_t)di * DD + c4 * 4];
            float4 p2 = *(const float4*)&P2[(size_t)si * DD + c4 * 4];
            float4 ev = *(const float4*)&e_in[(size_t)eg * DD + c4 * 4];
            float4 en;
            en.x = 0.5f * (p1.x - p2.x + cC.x + bv.x);
            en.y = 0.5f * (p1.y - p2.y + cC.y + bv.y);
            en.z = 0.5f * (p1.z - p2.z + cC.z + bv.z);
            en.w = 0.5f * (p1.w - p2.w + cC.w + bv.w);
            float4 o;
            o.x = ev.x + lrelu(en.x);
            o.y = ev.y + lrelu(en.y);
            o.z = ev.z + lrelu(en.z);
            o.w = ev.w + lrelu(en.w);
            *(float4*)&e_out[(size_t)eg * DD + c4 * 4] = o;
            if (msk) *(float4*)&g_enew[(size_t)eg * DD + c4 * 4] = en;
            // row-norm: whole row eg lives in this warp (lane == c4)
            float sq = en.x * en.x + en.y * en.y + en.z * en.z + en.w * en.w;
#pragma unroll
            for (int off = 16; off > 0; off >>= 1)
                sq += __shfl_xor_sync(0xffffffffu, sq, off);
            if (c4 == 0 && msk) g_enorm[eg] = sqrtf(sq);
        }
    }
}

// ================= edge pass B: persistent, resident B, masked V GEMM =============
__global__ void __launch_bounds__(256, 2)
k_edgeB(const float* __restrict__ h, const float* __restrict__ bV,
        const int* __restrict__ src, const int* __restrict__ dst) {
    extern __shared__ char sm[];
    uint32_t smb = smem_u32(sm);
    int tid = threadIdx.x, lane = tid & 31, wid = tid >> 5;
    int wm = wid & 3, wn = wid >> 2;
    int q = lane >> 2, m = lane & 3;
    int mc = g_mcount;
    int ntiles = (mc + 127) >> 7;

    if (tid < 128) ((float*)(sm + SM_BIAS))[tid] = bV[tid];
    copy_B(sm, 8, tid);
    int* seid = (int*)(sm + SM_ROWC);
    int* ssrc = (int*)(sm + SM_ROWA);
    int* sdst = (int*)(sm + SM_ROWB);
    const float* bias_s = (const float*)(sm + SM_BIAS);
    float* svb = (float*)(sm + SM_SV);

    for (int t = blockIdx.x; t < ntiles; t += gridDim.x) {
        int base = t * 128;
        int nt = min(128, mc - base);
        __syncthreads();
        if (tid < 128) {
            int eid = (tid < nt) ? g_mlist[base + tid] : -1;
            seid[tid] = eid;
            ssrc[tid] = (eid >= 0) ? src[eid] : 0;
            sdst[tid] = (eid >= 0) ? dst[eid] : 0;
        }
        __syncthreads();

        // stage full-K A = h[src]*h[dst]
#pragma unroll
        for (int i = 0; i < 8; i++) {
            int u = tid + i * 256;
            int row = u >> 4, ch = u & 15;
            float4 v0 = make_float4(0.f, 0.f, 0.f, 0.f), v1 = v0;
            if (row < nt) {
                float4 hs0 = ((const float4*)h)[(size_t)ssrc[row] * 32 + ch * 2];
                float4 hs1 = ((const float4*)h)[(size_t)ssrc[row] * 32 + ch * 2 + 1];
                float4 hd0 = ((const float4*)h)[(size_t)sdst[row] * 32 + ch * 2];
                float4 hd1 = ((const float4*)h)[(size_t)sdst[row] * 32 + ch * 2 + 1];
                v0.x = hs0.x * hd0.x; v0.y = hs0.y * hd0.y;
                v0.z = hs0.z * hd0.z; v0.w = hs0.w * hd0.w;
                v1.x = hs1.x * hd1.x; v1.y = hs1.y * hd1.y;
                v1.z = hs1.z * hd1.z; v1.w = hs1.w * hd1.w;
            }
            uint4 hi; cvt8s(v0, v1, hi);
            *(uint4*)(sm + SM_AH + soff(row, ch * 8)) = hi;
        }
        __syncthreads();

        float acc[2][8][4];
#pragma unroll
        for (int mf = 0; mf < 2; mf++)
#pragma unroll
            for (int j = 0; j < 8; j++)
#pragma unroll
                for (int i = 0; i < 4; i++) acc[mf][j][i] = 0.f;
        gemm(smb, lane, wm, wn, acc);

        float s0[2] = {0.f, 0.f}, s1[2] = {0.f, 0.f};
#pragma unroll
        for (int mf = 0; mf < 2; mf++)
#pragma unroll
            for (int j = 0; j < 8; j++) {
                float b0 = bias_s[wn * 64 + j * 8 + m * 2];
                float b1 = bias_s[wn * 64 + j * 8 + m * 2 + 1];
                s0[mf] += relu_(acc[mf][j][0] + b0) + relu_(acc[mf][j][1] + b1);
                s1[mf] += relu_(acc[mf][j][2] + b0) + relu_(acc[mf][j][3] + b1);
            }
#pragma unroll
        for (int mf = 0; mf < 2; mf++) {
            s0[mf] += __shfl_xor_sync(0xffffffffu, s0[mf], 1);
            s0[mf] += __shfl_xor_sync(0xffffffffu, s0[mf], 2);
            s1[mf] += __shfl_xor_sync(0xffffffffu, s1[mf], 1);
            s1[mf] += __shfl_xor_sync(0xffffffffu, s1[mf], 2);
        }
        if (m == 0) {
#pragma unroll
            for (int mf = 0; mf < 2; mf++) {
                svb[wn * 128 + wm * 32 + mf * 16 + q] = s0[mf];
                svb[wn * 128 + wm * 32 + mf * 16 + q + 8] = s1[mf];
            }
        }
        __syncthreads();

        // per-edge coefficient into smem
        if (tid < 128) {
            float cf = 0.f;
            if (tid < nt) {
                float sv = svb[tid] + svb[128 + tid];
                float L = g_enorm[seid[tid]];
                if (L > 1e-9f && sv > 0.f) {
                    float r = 0.5f * sqrtf(L);
                    cf = sv * expf(-r / 0.3f) / (1.2f * L * sqrtf(L));
                }
            }
            svb[256 + tid] = cf;
        }
        __syncthreads();

        // cooperative scatter: 256 threads, one float4 chunk each, v4 reductions
        const float* scf = svb + 256;
        for (int u = tid; u < 4096; u += 256) {
            int e = u >> 5, c4 = u & 31;
            float cf = scf[e];
            if (cf != 0.f) {
                int eid = seid[e];
                float4 en = ((const float4*)g_enew)[(size_t)eid * 32 + c4];
                float* fp = &g_facc[(size_t)sdst[e] * DD + c4 * 4];
                asm volatile(
                    "red.global.add.v4.f32 [%0], {%1, %2, %3, %4};"
                    :: "l"(fp), "f"(cf * en.x), "f"(cf * en.y),
                       "f"(cf * en.z), "f"(cf * en.w)
                    : "memory");
            }
        }
    }
}

// ================= node finalize =================
__global__ void k_final(const float* __restrict__ h, const float* __restrict__ p,
                        const float* __restrict__ dv, const float* __restrict__ dt,
                        float* __restrict__ out) {
    int w = threadIdx.x >> 5, l = threadIdx.x & 31;
    int n = blockIdx.x * 8 + w;
    int ix = n * 32 + l;
    const float4* V1 = (const float4*)g_proj[0];
    const float4* V2 = (const float4*)g_proj[1];
    const float4* P3 = (const float4*)g_proj[4];
    const float4* D1 = (const float4*)g_proj[5];
    const float4* D2 = (const float4*)g_proj[6];
    const float4* TA = (const float4*)g_proj[7];
    const float4* TB = (const float4*)g_proj[8];
    const float4* FA = (const float4*)g_facc;

    float4 v1 = V1[ix], v2 = V2[ix], p3 = P3[ix], d1 = D1[ix], d2 = D2[ix];
    float4 ta = TA[ix], tb = TB[ix], fa = FA[ix];
    float cnt = (float)g_cnt0[n];

    float4 th;
    th.x = ta.x + tb.x; th.y = ta.y + tb.y;
    th.z = ta.z + tb.z; th.w = ta.w + tb.w;

    float4 f;
    f.x = (d1.x - v1.x) * (cnt * relu_(th.x)) + fa.x;
    f.y = (d1.y - v1.y) * (cnt * relu_(th.y)) + fa.y;
    f.z = (d1.z - v1.z) * (cnt * relu_(th.z)) + fa.z;
    f.w = (d1.w - v1.w) * (cnt * relu_(th.w)) + fa.w;

    float sq = f.x * f.x + f.y * f.y + f.z * f.z + f.w * f.w;
#pragma unroll
    for (int off = 16; off > 0; off >>= 1) sq += __shfl_xor_sync(0xffffffffu, sq, off);
    float inv = 1.f / (sqrtf(sq) + 1e-9f);

    float dtv = dt[n];
    float dtp = dtv + 0.5f * dtv * dtv;

    float4 hv = ((const float4*)h)[ix];
    float4 pv = ((const float4*)p)[ix];
    float4 dvv = ((const float4*)dv)[ix];

    float4 ho, po, dq;
    ho.x = hv.x + lrelu(v2.x + f.x * dtv);
    ho.y = hv.y + lrelu(v2.y + f.y * dtv);
    ho.z = hv.z + lrelu(v2.z + f.z * dtv);
    ho.w = hv.w + lrelu(v2.w + f.w * dtv);
    po.x = pv.x + lrelu(p3.x + f.x * dtp);
    po.y = pv.y + lrelu(p3.y + f.y * dtp);
    po.z = pv.z + lrelu(p3.z + f.z * dtp);
    po.w = pv.w + lrelu(p3.w + f.w * dtp);
    dq.x = dvv.x + lrelu(d2.x + f.x * inv);
    dq.y = dvv.y + lrelu(d2.y + f.y * inv);
    dq.z = dvv.z + lrelu(d2.z + f.z * inv);
    dq.w = dvv.w + lrelu(d2.w + f.w * inv);

    float4* outH = (float4*)out;
    float4* outP = (float4*)(out + (size_t)NN * DD + (size_t)EE * DD);
    float4* outD = (float4*)(out + 2 * (size_t)NN * DD + (size_t)EE * DD);
    outH[ix] = ho;
    outP[ix] = po;
    outD[ix] = dq;
}

// ================= launch =================
extern "C" void kernel_launch(void* const* d_in, const int* in_sizes, int n_in,
                              void* d_out, int out_size) {
    const float* h   = (const float*)d_in[0];
    const float* e   = (const float*)d_in[1];
    const float* p   = (const float*)d_in[2];
    const float* dv  = (const float*)d_in[3];
    const float* dt  = (const float*)d_in[4];
    const int* smask = (const int*)d_in[5];
    const int* src   = (const int*)d_in[6];
    const int* dst   = (const int*)d_in[7];
    const float* W_V1 = (const float*)d_in[8],  *b_V1 = (const float*)d_in[9];
    const float* W_V2 = (const float*)d_in[10], *b_V2 = (const float*)d_in[11];
    const float* W_E1 = (const float*)d_in[12], *b_E1 = (const float*)d_in[13];
    const float* W_P1 = (const float*)d_in[14], *b_P1 = (const float*)d_in[15];
    const float* W_P2 = (const float*)d_in[16], *b_P2 = (const float*)d_in[17];
    const float* W_P3 = (const float*)d_in[18], *b_P3 = (const float*)d_in[19];
    const float* W_D1 = (const float*)d_in[20], *b_D1 = (const float*)d_in[21];
    const float* W_D2 = (const float*)d_in[22], *b_D2 = (const float*)d_in[23];
    const float* W_V  = (const float*)d_in[24], *b_V  = (const float*)d_in[25];
    const float* W_T  = (const float*)d_in[26], *b_T  = (const float*)d_in[27];
    float* out = (float*)d_out;

    cudaFuncSetAttribute(k_nodeg, cudaFuncAttributeMaxDynamicSharedMemorySize, SM_TOTAL);
    cudaFuncSetAttribute(k_edgeA, cudaFuncAttributeMaxDynamicSharedMemorySize, SM_TOTAL);
    cudaFuncSetAttribute(k_edgeB, cudaFuncAttributeMaxDynamicSharedMemorySize, SM_TOTAL);

    k_prep<<<640, 256>>>(W_V1, W_V2, W_P1, W_P2, W_P3, W_D1, W_D2, W_E1, W_V, W_T);
    k_count<<<EE / 256, 256>>>(smask, dst);
    k_nodeg<<<GRID_P, 256, SM_TOTAL>>>(h, p, dv, b_V1, b_V2, b_P1, b_P2, b_P3,
                                       b_D1, b_D2, b_T);
    k_edgeA<<<GRID_P, 256, SM_TOTAL>>>(e, src, dst, smask, b_E1, out + (size_t)NN * DD);
    k_edgeB<<<GRID_P, 256, SM_TOTAL>>>(h, b_V, src, dst);
    k_final<<<NN / 8, 256>>>(h, p, dv, dt, out);
}

// round 14
// speedup vs baseline: 1.5624x; 1.0878x over previous
#include <cuda_runtime.h>
#include <cuda_fp16.h>
#include <cstdint>
#include <math.h>

#define NN 10000
#define EE 320000
#define DD 128
#define NTILE_N 79      /* (NN+127)/128 */
#define NTILE_E 2500    /* EE/128 */
#define GRID_P 296      /* persistent grid: 148 SMs x 2 CTAs */

// ================= static device scratch =================
__device__ float g_proj[9][NN * DD];     // V1h V2h P1h P2h P3h D1h D2h ThA ThB
__device__ __half g_enew[(size_t)EE * DD];   // fp16: feeds fab scatter only
__device__ float g_enorm[EE];
__device__ float g_facc[NN * DD];
__device__ int   g_cnt0[NN];
__device__ int   g_mlist[EE];
__device__ int   g_mcount;
__device__ float g_bzero[DD];            // stays zero (module-load init)
// fp16 weight tiles in swizzled layout (32KB each):
// slots 0..6 node W (V1,V2,P1,P2,P3,D1,D2), 7 E1, 8 V, 9/10 = W_T halves
__device__ __align__(16) unsigned char g_wbh[11 * 32768];

__device__ __forceinline__ float lrelu(float x) { return x > 0.f ? x : 0.01f * x; }
__device__ __forceinline__ float relu_(float x) { return x > 0.f ? x : 0.f; }

__device__ __forceinline__ uint32_t smem_u32(const void* p) {
    uint32_t a;
    asm("{ .reg .u64 t; cvta.to.shared.u64 t, %1; cvt.u32.u64 %0, t; }" : "=r"(a) : "l"(p));
    return a;
}
__device__ __forceinline__ uint32_t pack2h(__half a, __half b) {
    __half2 t; t.x = a; t.y = b;
    return *reinterpret_cast<uint32_t*>(&t);
}
__device__ __forceinline__ void l2_prefetch(const void* p) {
    asm volatile("prefetch.global.L2 [%0];" :: "l"(p));
}

// swizzled byte offset inside a 128x128 fp16 tile: row stride 256B
__device__ __forceinline__ uint32_t soff(int r, int c) {
    return (uint32_t)((r << 8) + ((((c >> 3) ^ (r & 7)) << 4) | ((c & 7) << 1)));
}

__device__ __forceinline__ void ldsm4(uint32_t* r, uint32_t addr) {
    asm volatile("ldmatrix.sync.aligned.m8n8.x4.shared.b16 {%0,%1,%2,%3}, [%4];"
                 : "=r"(r[0]), "=r"(r[1]), "=r"(r[2]), "=r"(r[3]) : "r"(addr));
}
__device__ __forceinline__ void mma16816(float* d, const uint32_t* a,
                                         uint32_t b0, uint32_t b1) {
    asm volatile(
        "mma.sync.aligned.m16n8k16.row.col.f32.f16.f16.f32 "
        "{%0,%1,%2,%3}, {%4,%5,%6,%7}, {%8,%9}, {%0,%1,%2,%3};"
        : "+f"(d[0]), "+f"(d[1]), "+f"(d[2]), "+f"(d[3])
        : "r"(a[0]), "r"(a[1]), "r"(a[2]), "r"(a[3]), "r"(b0), "r"(b1));
}

// convert 8 fp32 -> fp16x2 quad
__device__ __forceinline__ void cvt8s(float4 v0, float4 v1, uint4& hi) {
    hi.x = pack2h(__float2half_rn(v0.x), __float2half_rn(v0.y));
    hi.y = pack2h(__float2half_rn(v0.z), __float2half_rn(v0.w));
    hi.z = pack2h(__float2half_rn(v1.x), __float2half_rn(v1.y));
    hi.w = pack2h(__float2half_rn(v1.z), __float2half_rn(v1.w));
}

// shared memory layout (102400 bytes -> 2 CTAs/SM)
#define SM_BIAS 0
#define SM_ROWA 512
#define SM_ROWB 1024
#define SM_ROWC 1536
#define SM_SV   2048
#define SM_AH   4096                 /* 128x128 fp16 A (32KB) */
#define SM_SPARE (4096 + 32768)      /* 32KB (C spill area)   */
#define SM_BH   (4096 + 65536)       /* 128x128 fp16 B (32KB) RESIDENT */
#define SM_C    4096                 /* fp32 C 128rows x 512B, overlays AH+SPARE */
#define SM_TOTAL (4096 + 98304)

// C chunk-swizzled offset: row r (0..127), float4-chunk c4 (0..31)
__device__ __forceinline__ uint32_t coff(int r, int c4) {
    return (uint32_t)(SM_C + r * 512 + (((c4 ^ (r & 7)) & 31) << 4));
}

// ---- single-fp16 GEMM over full K=128, warp tile 32(M) x 64(N), 8 warps ----
__device__ __forceinline__ void gemm(uint32_t smb, int lane, int wm, int wn,
                                     float (&acc)[2][8][4]) {
    const int fr = lane & 15;
    const int fc = (lane >> 4) << 3;
    const int m0 = wm * 32;
    const int n0 = wn * 64;
#pragma unroll
    for (int ks = 0; ks < 8; ks++) {
        const int kc = ks * 16 + fc;
        uint32_t aH[2][4], bH[2][4];
        ldsm4(aH[0], smb + SM_AH + soff(m0 + fr, kc));
        ldsm4(aH[1], smb + SM_AH + soff(m0 + 16 + fr, kc));
        ldsm4(bH[0], smb + SM_BH + soff(n0 + fr, kc));
        int cur = 0;
#pragma unroll
        for (int bn = 0; bn < 4; bn++) {
            int nxt = cur ^ 1;
            if (bn < 3)
                ldsm4(bH[nxt], smb + SM_BH + soff(n0 + (bn + 1) * 16 + fr, kc));
#pragma unroll
            for (int mf = 0; mf < 2; mf++) {
                mma16816(acc[mf][2 * bn],     aH[mf], bH[cur][0], bH[cur][2]);
                mma16816(acc[mf][2 * bn + 1], aH[mf], bH[cur][1], bH[cur][3]);
            }
            cur = nxt;
        }
    }
}

__device__ __forceinline__ void copy_B(char* sm, int slot, int tid) {
    const uint4* gh = (const uint4*)(g_wbh + slot * 32768);
    uint4* bh = (uint4*)(sm + SM_BH);
    for (int i = tid; i < 2048; i += 256) bh[i] = gh[i];
}

// stage full-K A tile (dense rows from X, guarded)
__device__ __forceinline__ void stage_full(char* sm, int tid, const float* X,
                                           int r0, int limit) {
#pragma unroll
    for (int i = 0; i < 8; i++) {
        int u = tid + i * 256;
        int row = u >> 4, ch = u & 15;
        int g = r0 + row;
        float4 v0 = make_float4(0.f, 0.f, 0.f, 0.f), v1 = v0;
        if (g < limit) {
            v0 = ((const float4*)X)[(size_t)g * 32 + ch * 2];
            v1 = ((const float4*)X)[(size_t)g * 32 + ch * 2 + 1];
        }
        uint4 hi; cvt8s(v0, v1, hi);
        *(uint4*)(sm + SM_AH + soff(row, ch * 8)) = hi;
    }
}

// ================= prep: zero scratch + weight fp16/swizzle =================
__global__ void k_prep(const float* W0, const float* W1, const float* W2, const float* W3,
                       const float* W4, const float* W5, const float* W6, const float* W7,
                       const float* W8, const float* WT) {
    const float* Wp[9] = {W0, W1, W2, W3, W4, W5, W6, W7, W8};
    int i = blockIdx.x * blockDim.x + threadIdx.x;
    int stride = gridDim.x * blockDim.x;
    for (int t = i; t < NN * DD; t += stride) g_facc[t] = 0.f;
    for (int t = i; t < NN; t += stride) g_cnt0[t] = 0;
    if (i == 0) g_mcount = 0;
    for (int t = i; t < 11 * 2048; t += stride) {
        int slot = t >> 11, r = t & 2047;
        int n = r >> 4, k8 = r & 15;
        const float* srcp;
        if (slot < 9) srcp = Wp[slot] + n * 128 + k8 * 8;
        else if (slot == 9) srcp = WT + n * 256 + k8 * 8;
        else srcp = WT + n * 256 + 128 + k8 * 8;
        float4 v0 = ((const float4*)srcp)[0];
        float4 v1 = ((const float4*)srcp)[1];
        uint4 hi; cvt8s(v0, v1, hi);
        uint32_t off = (uint32_t)slot * 32768u + soff(n, k8 * 8);
        *reinterpret_cast<uint4*>(g_wbh + off) = hi;
    }
}

__global__ void k_count(const int* __restrict__ smask, const int* __restrict__ dst) {
    int e = blockIdx.x * 256 + threadIdx.x;
    int lane = threadIdx.x & 31;
    int sm_ = smask[e];
    int d_ = dst[e];
    unsigned bal = __ballot_sync(0xffffffffu, sm_ == 1);
    if (sm_ == 0) atomicAdd(&g_cnt0[d_], 1);
    int lead = bal ? (__ffs(bal) - 1) : 0;
    int basec = 0;
    if (bal && lane == lead) basec = atomicAdd(&g_mcount, __popc(bal));
    basec = __shfl_sync(0xffffffffu, basec, lead);
    if (sm_ == 1) g_mlist[basec + __popc(bal & ((1u << lane) - 1u))] = e;
}

// ================= node GEMMs: persistent, 9 uniform jobs =================
__global__ void __launch_bounds__(256, 2)
k_nodeg(const float* __restrict__ h, const float* __restrict__ p,
        const float* __restrict__ dv,
        const float* bV1, const float* bV2, const float* bP1,
        const float* bP2, const float* bP3, const float* bD1,
        const float* bD2, const float* bT) {
    extern __shared__ char sm[];
    uint32_t smb = smem_u32(sm);
    int tid = threadIdx.x, lane = tid & 31, wid = tid >> 5;
    int wm = wid & 3, wn = wid >> 2;
    int pidx = blockIdx.x % 9;
    int nct = (gridDim.x - 1 - pidx) / 9 + 1;

    const float* X;
    const float* bias;
    int slot;
    switch (pidx) {
        case 0: X = h;  slot = 0;  bias = bV1; break;
        case 1: X = h;  slot = 1;  bias = bV2; break;
        case 2: X = p;  slot = 2;  bias = bP1; break;
        case 3: X = p;  slot = 3;  bias = bP2; break;
        case 4: X = p;  slot = 4;  bias = bP3; break;
        case 5: X = dv; slot = 5;  bias = bD1; break;
        case 6: X = dv; slot = 6;  bias = bD2; break;
        case 7: X = h;  slot = 9;  bias = bT; break;
        default: X = dv; slot = 10; bias = g_bzero; break;
    }
    if (tid < 128) ((float*)(sm + SM_BIAS))[tid] = bias[tid];
    copy_B(sm, slot, tid);
    float* outp = g_proj[pidx];
    int q = lane >> 2, m = lane & 3;

    for (int t = blockIdx.x / 9; t < NTILE_N; t += nct) {
        int r0 = t * 128;
        __syncthreads();
        stage_full(sm, tid, X, r0, NN);
        // register-free L2 prefetch of next tile's X rows
        {
            int t2 = t + nct;
            if (t2 < NTILE_N) {
                const char* nb = (const char*)(X + (size_t)t2 * 128 * DD);
                int lines = min(128 * 4, (NN - t2 * 128) * 4);
#pragma unroll
                for (int i = 0; i < 2; i++) {
                    int ln = tid + i * 256;
                    if (ln < lines) l2_prefetch(nb + (size_t)ln * 128);
                }
            }
        }
        __syncthreads();

        float acc[2][8][4];
#pragma unroll
        for (int mf = 0; mf < 2; mf++)
#pragma unroll
            for (int j = 0; j < 8; j++)
#pragma unroll
                for (int i = 0; i < 4; i++) acc[mf][j][i] = 0.f;
        gemm(smb, lane, wm, wn, acc);

        // register epilogue
        const float* bias_s = (const float*)(sm + SM_BIAS);
#pragma unroll
        for (int mf = 0; mf < 2; mf++) {
            int r1 = r0 + wm * 32 + mf * 16 + q;
            int r2 = r1 + 8;
#pragma unroll
            for (int j = 0; j < 8; j++) {
                int col = wn * 64 + j * 8 + m * 2;
                float b0 = bias_s[col], b1 = bias_s[col + 1];
                if (r1 < NN)
                    *(float2*)&outp[(size_t)r1 * DD + col] =
                        make_float2(acc[mf][j][0] + b0, acc[mf][j][1] + b1);
                if (r2 < NN)
                    *(float2*)&outp[(size_t)r2 * DD + col] =
                        make_float2(acc[mf][j][2] + b0, acc[mf][j][3] + b1);
            }
        }
    }
}

// ================= edge pass A: persistent, resident B, smem-C epilogue ==========
__global__ void __launch_bounds__(256, 2)
k_edgeA(const float* __restrict__ e_in, const int* __restrict__ src,
        const int* __restrict__ dst, const int* __restrict__ smask,
        const float* __restrict__ bE1, float* __restrict__ e_out) {
    extern __shared__ char sm[];
    uint32_t smb = smem_u32(sm);
    int tid = threadIdx.x, lane = tid & 31, wid = tid >> 5;
    int wm = wid & 3, wn = wid >> 2;
    int q = lane >> 2, m = lane & 3;

    if (tid < 128) ((float*)(sm + SM_BIAS))[tid] = bE1[tid];
    copy_B(sm, 7, tid);
    const float* P1 = g_proj[2];
    const float* P2 = g_proj[3];

    for (int t = blockIdx.x; t < NTILE_E; t += gridDim.x) {
        int e0 = t * 128;
        __syncthreads();
        if (tid < 128) {
            int eg = e0 + tid;
            int si = src[eg], di = dst[eg];
            ((int*)(sm + SM_ROWA))[tid] = si;
            ((int*)(sm + SM_ROWB))[tid] = di;
            ((int*)(sm + SM_ROWC))[tid] = smask[eg];
            // prefetch gathered P1/P2 rows (consumed after the GEMM)
            const char* pp1 = (const char*)(P1 + (size_t)di * DD);
            const char* pp2 = (const char*)(P2 + (size_t)si * DD);
#pragma unroll
            for (int l = 0; l < 4; l++) {
                l2_prefetch(pp1 + l * 128);
                l2_prefetch(pp2 + l * 128);
            }
        }
        stage_full(sm, tid, e_in, e0, EE);
        // register-free L2 prefetch of next tile's e_in
        {
            int t2 = t + gridDim.x;
            if (t2 < NTILE_E) {
                const char* nb = (const char*)(e_in + (size_t)t2 * 128 * DD);
#pragma unroll
                for (int i = 0; i < 2; i++)
                    l2_prefetch(nb + (size_t)(tid + i * 256) * 128);
            }
        }
        __syncthreads();

        float acc[2][8][4];
#pragma unroll
        for (int mf = 0; mf < 2; mf++)
#pragma unroll
            for (int j = 0; j < 8; j++)
#pragma unroll
                for (int i = 0; i < 4; i++) acc[mf][j][i] = 0.f;
        gemm(smb, lane, wm, wn, acc);
        __syncthreads();

        // store C (128 rows x 512B, overlays AH+SPARE)
#pragma unroll
        for (int mf = 0; mf < 2; mf++) {
            int r1 = wm * 32 + mf * 16 + q;
#pragma unroll
            for (int j = 0; j < 8; j++) {
                int col = wn * 64 + j * 8 + m * 2;
                int c4 = col >> 2;
                uint32_t inoff = (uint32_t)((m & 1) * 8);
                *(float2*)(sm + coff(r1, c4) + inoff) =
                    make_float2(acc[mf][j][0], acc[mf][j][1]);
                *(float2*)(sm + coff(r1 + 8, c4) + inoff) =
                    make_float2(acc[mf][j][2], acc[mf][j][3]);
            }
        }
        __syncthreads();

        const float* bias_s = (const float*)(sm + SM_BIAS);
        const int* ssrc = (const int*)(sm + SM_ROWA);
        const int* sdst = (const int*)(sm + SM_ROWB);
        const int* smsk = (const int*)(sm + SM_ROWC);
        for (int u = tid; u < 4096; u += 256) {
            int lr = u >> 5, c4 = u & 31;   // c4 == lane, lr warp-uniform
            int eg = e0 + lr;
            int si = ssrc[lr], di = sdst[lr], msk = smsk[lr];
            float4 cC = *(float4*)(sm + coff(lr, c4));
            float4 bv = *(const float4*)&bias_s[c4 * 4];
            float4 p1 = *(const float4*)&P1[(size_t)di * DD + c4 * 4];
            float4 p2 = *(const float4*)&P2[(size_t)si * DD + c4 * 4];
            float4 ev = *(const float4*)&e_in[(size_t)eg * DD + c4 * 4];
            float4 en;
            en.x = 0.5f * (p1.x - p2.x + cC.x + bv.x);
            en.y = 0.5f * (p1.y - p2.y + cC.y + bv.y);
            en.z = 0.5f * (p1.z - p2.z + cC.z + bv.z);
            en.w = 0.5f * (p1.w - p2.w + cC.w + bv.w);
            float4 o;
            o.x = ev.x + lrelu(en.x);
            o.y = ev.y + lrelu(en.y);
            o.z = ev.z + lrelu(en.z);
            o.w = ev.w + lrelu(en.w);
            *(float4*)&e_out[(size_t)eg * DD + c4 * 4] = o;
            if (msk) {  // warp-uniform branch: norms + enew only for masked rows
                uint2 eh;
                eh.x = pack2h(__float2half_rn(en.x), __float2half_rn(en.y));
                eh.y = pack2h(__float2half_rn(en.z), __float2half_rn(en.w));
                *(uint2*)&g_enew[(size_t)eg * DD + c4 * 4] = eh;
                float sq = en.x * en.x + en.y * en.y + en.z * en.z + en.w * en.w;
#pragma unroll
                for (int off = 16; off > 0; off >>= 1)
                    sq += __shfl_xor_sync(0xffffffffu, sq, off);
                if (c4 == 0) g_enorm[eg] = sqrtf(sq);
            }
        }
    }
}

// ================= edge pass B: persistent, resident B, masked V GEMM =============
__global__ void __launch_bounds__(256, 2)
k_edgeB(const float* __restrict__ h, const float* __restrict__ bV,
        const int* __restrict__ src, const int* __restrict__ dst) {
    extern __shared__ char sm[];
    uint32_t smb = smem_u32(sm);
    int tid = threadIdx.x, lane = tid & 31, wid = tid >> 5;
    int wm = wid & 3, wn = wid >> 2;
    int q = lane >> 2, m = lane & 3;
    int mc = g_mcount;
    int ntiles = (mc + 127) >> 7;

    if (tid < 128) ((float*)(sm + SM_BIAS))[tid] = bV[tid];
    copy_B(sm, 8, tid);
    int* seid = (int*)(sm + SM_ROWC);
    int* ssrc = (int*)(sm + SM_ROWA);
    int* sdst = (int*)(sm + SM_ROWB);
    const float* bias_s = (const float*)(sm + SM_BIAS);
    float* svb = (float*)(sm + SM_SV);

    for (int t = blockIdx.x; t < ntiles; t += gridDim.x) {
        int base = t * 128;
        int nt = min(128, mc - base);
        __syncthreads();
        if (tid < 128) {
            int eid = (tid < nt) ? g_mlist[base + tid] : -1;
            seid[tid] = eid;
            ssrc[tid] = (eid >= 0) ? src[eid] : 0;
            sdst[tid] = (eid >= 0) ? dst[eid] : 0;
            if (eid >= 0) {   // prefetch enew fp16 row (consumed after GEMM)
                const char* pe = (const char*)(g_enew + (size_t)eid * DD);
                l2_prefetch(pe);
                l2_prefetch(pe + 128);
            }
        }
        __syncthreads();

        // stage full-K A = h[src]*h[dst]
#pragma unroll
        for (int i = 0; i < 8; i++) {
            int u = tid + i * 256;
            int row = u >> 4, ch = u & 15;
            float4 v0 = make_float4(0.f, 0.f, 0.f, 0.f), v1 = v0;
            if (row < nt) {
                float4 hs0 = ((const float4*)h)[(size_t)ssrc[row] * 32 + ch * 2];
                float4 hs1 = ((const float4*)h)[(size_t)ssrc[row] * 32 + ch * 2 + 1];
                float4 hd0 = ((const float4*)h)[(size_t)sdst[row] * 32 + ch * 2];
                float4 hd1 = ((const float4*)h)[(size_t)sdst[row] * 32 + ch * 2 + 1];
                v0.x = hs0.x * hd0.x; v0.y = hs0.y * hd0.y;
                v0.z = hs0.z * hd0.z; v0.w = hs0.w * hd0.w;
                v1.x = hs1.x * hd1.x; v1.y = hs1.y * hd1.y;
                v1.z = hs1.z * hd1.z; v1.w = hs1.w * hd1.w;
            }
            uint4 hi; cvt8s(v0, v1, hi);
            *(uint4*)(sm + SM_AH + soff(row, ch * 8)) = hi;
        }
        __syncthreads();

        float acc[2][8][4];
#pragma unroll
        for (int mf = 0; mf < 2; mf++)
#pragma unroll
            for (int j = 0; j < 8; j++)
#pragma unroll
                for (int i = 0; i < 4; i++) acc[mf][j][i] = 0.f;
        gemm(smb, lane, wm, wn, acc);

        float s0[2] = {0.f, 0.f}, s1[2] = {0.f, 0.f};
#pragma unroll
        for (int mf = 0; mf < 2; mf++)
#pragma unroll
            for (int j = 0; j < 8; j++) {
                float b0 = bias_s[wn * 64 + j * 8 + m * 2];
                float b1 = bias_s[wn * 64 + j * 8 + m * 2 + 1];
                s0[mf] += relu_(acc[mf][j][0] + b0) + relu_(acc[mf][j][1] + b1);
                s1[mf] += relu_(acc[mf][j][2] + b0) + relu_(acc[mf][j][3] + b1);
            }
#pragma unroll
        for (int mf = 0; mf < 2; mf++) {
            s0[mf] += __shfl_xor_sync(0xffffffffu, s0[mf], 1);
            s0[mf] += __shfl_xor_sync(0xffffffffu, s0[mf], 2);
            s1[mf] += __shfl_xor_sync(0xffffffffu, s1[mf], 1);
            s1[mf] += __shfl_xor_sync(0xffffffffu, s1[mf], 2);
        }
        if (m == 0) {
#pragma unroll
            for (int mf = 0; mf < 2; mf++) {
                svb[wn * 128 + wm * 32 + mf * 16 + q] = s0[mf];
                svb[wn * 128 + wm * 32 + mf * 16 + q + 8] = s1[mf];
            }
        }
        __syncthreads();

        // per-edge coefficient into smem
        if (tid < 128) {
            float cf = 0.f;
            if (tid < nt) {
                float sv = svb[tid] + svb[128 + tid];
                float L = g_enorm[seid[tid]];
                if (L > 1e-9f && sv > 0.f) {
                    float r = 0.5f * sqrtf(L);
                    cf = sv * expf(-r / 0.3f) / (1.2f * L * sqrtf(L));
                }
            }
            svb[256 + tid] = cf;
        }
        __syncthreads();

        // cooperative scatter: 256 threads, one float4 chunk each, v4 reductions
        const float* scf = svb + 256;
        for (int u = tid; u < 4096; u += 256) {
            int e = u >> 5, c4 = u & 31;
            float cf = scf[e];
            if (cf != 0.f) {
                int eid = seid[e];
                uint2 eh = *(const uint2*)&g_enew[(size_t)eid * DD + c4 * 4];
                float2 f0 = __half22float2(*reinterpret_cast<__half2*>(&eh.x));
                float2 f1 = __half22float2(*reinterpret_cast<__half2*>(&eh.y));
                float* fp = &g_facc[(size_t)sdst[e] * DD + c4 * 4];
                asm volatile(
                    "red.global.add.v4.f32 [%0], {%1, %2, %3, %4};"
                    :: "l"(fp), "f"(cf * f0.x), "f"(cf * f0.y),
                       "f"(cf * f1.x), "f"(cf * f1.y)
                    : "memory");
            }
        }
    }
}

// ================= node finalize =================
__global__ void k_final(const float* __restrict__ h, const float* __restrict__ p,
                        const float* __restrict__ dv, const float* __restrict__ dt,
                        float* __restrict__ out) {
    int w = threadIdx.x >> 5, l = threadIdx.x & 31;
    int n = blockIdx.x * 8 + w;
    int ix = n * 32 + l;
    const float4* V1 = (const float4*)g_proj[0];
    const float4* V2 = (const float4*)g_proj[1];
    const float4* P3 = (const float4*)g_proj[4];
    const float4* D1 = (const float4*)g_proj[5];
    const float4* D2 = (const float4*)g_proj[6];
    const float4* TA = (const float4*)g_proj[7];
    const float4* TB = (const float4*)g_proj[8];
    const float4* FA = (const float4*)g_facc;

    float4 v1 = V1[ix], v2 = V2[ix], p3 = P3[ix], d1 = D1[ix], d2 = D2[ix];
    float4 ta = TA[ix], tb = TB[ix], fa = FA[ix];
    float cnt = (float)g_cnt0[n];

    float4 th;
    th.x = ta.x + tb.x; th.y = ta.y + tb.y;
    th.z = ta.z + tb.z; th.w = ta.w + tb.w;

    float4 f;
    f.x = (d1.x - v1.x) * (cnt * relu_(th.x)) + fa.x;
    f.y = (d1.y - v1.y) * (cnt * relu_(th.y)) + fa.y;
    f.z = (d1.z - v1.z) * (cnt * relu_(th.z)) + fa.z;
    f.w = (d1.w - v1.w) * (cnt * relu_(th.w)) + fa.w;

    float sq = f.x * f.x + f.y * f.y + f.z * f.z + f.w * f.w;
#pragma unroll
    for (int off = 16; off > 0; off >>= 1) sq += __shfl_xor_sync(0xffffffffu, sq, off);
    float inv = 1.f / (sqrtf(sq) + 1e-9f);

    float dtv = dt[n];
    float dtp = dtv + 0.5f * dtv * dtv;

    float4 hv = ((const float4*)h)[ix];
    float4 pv = ((const float4*)p)[ix];
    float4 dvv = ((const float4*)dv)[ix];

    float4 ho, po, dq;
    ho.x = hv.x + lrelu(v2.x + f.x * dtv);
    ho.y = hv.y + lrelu(v2.y + f.y * dtv);
    ho.z = hv.z + lrelu(v2.z + f.z * dtv);
    ho.w = hv.w + lrelu(v2.w + f.w * dtv);
    po.x = pv.x + lrelu(p3.x + f.x * dtp);
    po.y = pv.y + lrelu(p3.y + f.y * dtp);
    po.z = pv.z + lrelu(p3.z + f.z * dtp);
    po.w = pv.w + lrelu(p3.w + f.w * dtp);
    dq.x = dvv.x + lrelu(d2.x + f.x * inv);
    dq.y = dvv.y + lrelu(d2.y + f.y * inv);
    dq.z = dvv.z + lrelu(d2.z + f.z * inv);
    dq.w = dvv.w + lrelu(d2.w + f.w * inv);

    float4* outH = (float4*)out;
    float4* outP = (float4*)(out + (size_t)NN * DD + (size_t)EE * DD);
    float4* outD = (float4*)(out + 2 * (size_t)NN * DD + (size_t)EE * DD);
    outH[ix] = ho;
    outP[ix] = po;
    outD[ix] = dq;
}

// ================= launch =================
extern "C" void kernel_launch(void* const* d_in, const int* in_sizes, int n_in,
                              void* d_out, int out_size) {
    const float* h   = (const float*)d_in[0];
    const float* e   = (const float*)d_in[1];
    const float* p   = (const float*)d_in[2];
    const float* dv  = (const float*)d_in[3];
    const float* dt  = (const float*)d_in[4];
    const int* smask = (const int*)d_in[5];
    const int* src   = (const int*)d_in[6];
    const int* dst   = (const int*)d_in[7];
    const float* W_V1 = (const float*)d_in[8],  *b_V1 = (const float*)d_in[9];
    const float* W_V2 = (const float*)d_in[10], *b_V2 = (const float*)d_in[11];
    const float* W_E1 = (const float*)d_in[12], *b_E1 = (const float*)d_in[13];
    const float* W_P1 = (const float*)d_in[14], *b_P1 = (const float*)d_in[15];
    const float* W_P2 = (const float*)d_in[16], *b_P2 = (const float*)d_in[17];
    const float* W_P3 = (const float*)d_in[18], *b_P3 = (const float*)d_in[19];
    const float* W_D1 = (const float*)d_in[20], *b_D1 = (const float*)d_in[21];
    const float* W_D2 = (const float*)d_in[22], *b_D2 = (const float*)d_in[23];
    const float* W_V  = (const float*)d_in[24], *b_V  = (const float*)d_in[25];
    const float* W_T  = (const float*)d_in[26], *b_T  = (const float*)d_in[27];
    float* out = (float*)d_out;

    cudaFuncSetAttribute(k_nodeg, cudaFuncAttributeMaxDynamicSharedMemorySize, SM_TOTAL);
    cudaFuncSetAttribute(k_edgeA, cudaFuncAttributeMaxDynamicSharedMemorySize, SM_TOTAL);
    cudaFuncSetAttribute(k_edgeB, cudaFuncAttributeMaxDynamicSharedMemorySize, SM_TOTAL);

    k_prep<<<640, 256>>>(W_V1, W_V2, W_P1, W_P2, W_P3, W_D1, W_D2, W_E1, W_V, W_T);
    k_count<<<EE / 256, 256>>>(smask, dst);
    k_nodeg<<<GRID_P, 256, SM_TOTAL>>>(h, p, dv, b_V1, b_V2, b_P1, b_P2, b_P3,
                                       b_D1, b_D2, b_T);
    k_edgeA<<<GRID_P, 256, SM_TOTAL>>>(e, src, dst, smask, b_E1, out + (size_t)NN * DD);
    k_edgeB<<<GRID_P, 256, SM_TOTAL>>>(h, b_V, src, dst);
    k_final<<<NN / 8, 256>>>(h, p, dv, dt, out);
}

// round 15
// speedup vs baseline: 1.5886x; 1.0168x over previous
#include <cuda_runtime.h>
#include <cuda_fp16.h>
#include <cstdint>
#include <math.h>

#define NN 10000
#define EE 320000
#define DD 128
#define NTILE_N 79      /* (NN+127)/128 */
#define NTILE_E 2500    /* EE/128 */
#define GRID_P 296      /* persistent grid: 148 SMs x 2 CTAs */

// ================= static device scratch =================
__device__ float g_proj[9][NN * DD];     // V1h V2h P1h P2h P3h D1h D2h ThA ThB
__device__ __half g_enew[(size_t)EE * DD];   // fp16: feeds fab scatter only
__device__ float g_enorm[EE];
__device__ float g_facc[NN * DD];
__device__ int   g_cnt0[NN];
__device__ int   g_mlist[EE];
__device__ int   g_mcount;
__device__ float g_bzero[DD];            // stays zero (module-load init)
// fp16 weight tiles in swizzled layout (32KB each):
// slots 0..6 node W (V1,V2,P1,P2,P3,D1,D2), 7 E1, 8 V, 9/10 = W_T halves
__device__ __align__(16) unsigned char g_wbh[11 * 32768];

__device__ __forceinline__ float lrelu(float x) { return x > 0.f ? x : 0.01f * x; }
__device__ __forceinline__ float relu_(float x) { return x > 0.f ? x : 0.f; }

__device__ __forceinline__ uint32_t smem_u32(const void* p) {
    uint32_t a;
    asm("{ .reg .u64 t; cvta.to.shared.u64 t, %1; cvt.u32.u64 %0, t; }" : "=r"(a) : "l"(p));
    return a;
}
__device__ __forceinline__ uint32_t pack2h(__half a, __half b) {
    __half2 t; t.x = a; t.y = b;
    return *reinterpret_cast<uint32_t*>(&t);
}
__device__ __forceinline__ void l2_prefetch(const void* p) {
    asm volatile("prefetch.global.L2 [%0];" :: "l"(p));
}

// swizzled byte offset inside a 128x128 fp16 tile: row stride 256B
__device__ __forceinline__ uint32_t soff(int r, int c) {
    return (uint32_t)((r << 8) + ((((c >> 3) ^ (r & 7)) << 4) | ((c & 7) << 1)));
}

__device__ __forceinline__ void ldsm4(uint32_t* r, uint32_t addr) {
    asm volatile("ldmatrix.sync.aligned.m8n8.x4.shared.b16 {%0,%1,%2,%3}, [%4];"
                 : "=r"(r[0]), "=r"(r[1]), "=r"(r[2]), "=r"(r[3]) : "r"(addr));
}
__device__ __forceinline__ void mma16816(float* d, const uint32_t* a,
                                         uint32_t b0, uint32_t b1) {
    asm volatile(
        "mma.sync.aligned.m16n8k16.row.col.f32.f16.f16.f32 "
        "{%0,%1,%2,%3}, {%4,%5,%6,%7}, {%8,%9}, {%0,%1,%2,%3};"
        : "+f"(d[0]), "+f"(d[1]), "+f"(d[2]), "+f"(d[3])
        : "r"(a[0]), "r"(a[1]), "r"(a[2]), "r"(a[3]), "r"(b0), "r"(b1));
}

// convert 8 fp32 -> fp16x2 quad
__device__ __forceinline__ void cvt8s(float4 v0, float4 v1, uint4& hi) {
    hi.x = pack2h(__float2half_rn(v0.x), __float2half_rn(v0.y));
    hi.y = pack2h(__float2half_rn(v0.z), __float2half_rn(v0.w));
    hi.z = pack2h(__float2half_rn(v1.x), __float2half_rn(v1.y));
    hi.w = pack2h(__float2half_rn(v1.z), __float2half_rn(v1.w));
}

// shared memory layout (102400 bytes -> 2 CTAs/SM)
#define SM_BIAS 0
#define SM_ROWA 512
#define SM_ROWB 1024
#define SM_ROWC 1536
#define SM_SV   2048
#define SM_AH   4096                 /* 128x128 fp16 A (32KB) */
#define SM_CH   (4096 + 32768)       /* fp16 C 128rows x 256B (32KB) */
#define SM_BH   (4096 + 65536)       /* 128x128 fp16 B (32KB) RESIDENT */
#define SM_TOTAL (4096 + 98304)

// fp16 C granule-swizzled offset: row r (0..127), 8B-granule g (0..31)
__device__ __forceinline__ uint32_t coff16(int r, int g) {
    return (uint32_t)(SM_CH + (r << 8) + (((g ^ (r & 7)) & 31) << 3));
}

// ---- single-fp16 GEMM over full K=128, warp tile 32(M) x 64(N), 8 warps ----
__device__ __forceinline__ void gemm(uint32_t smb, int lane, int wm, int wn,
                                     float (&acc)[2][8][4]) {
    const int fr = lane & 15;
    const int fc = (lane >> 4) << 3;
    const int m0 = wm * 32;
    const int n0 = wn * 64;
#pragma unroll
    for (int ks = 0; ks < 8; ks++) {
        const int kc = ks * 16 + fc;
        uint32_t aH[2][4], bH[2][4];
        ldsm4(aH[0], smb + SM_AH + soff(m0 + fr, kc));
        ldsm4(aH[1], smb + SM_AH + soff(m0 + 16 + fr, kc));
        ldsm4(bH[0], smb + SM_BH + soff(n0 + fr, kc));
        int cur = 0;
#pragma unroll
        for (int bn = 0; bn < 4; bn++) {
            int nxt = cur ^ 1;
            if (bn < 3)
                ldsm4(bH[nxt], smb + SM_BH + soff(n0 + (bn + 1) * 16 + fr, kc));
#pragma unroll
            for (int mf = 0; mf < 2; mf++) {
                mma16816(acc[mf][2 * bn],     aH[mf], bH[cur][0], bH[cur][2]);
                mma16816(acc[mf][2 * bn + 1], aH[mf], bH[cur][1], bH[cur][3]);
            }
            cur = nxt;
        }
    }
}

__device__ __forceinline__ void copy_B(char* sm, int slot, int tid) {
    const uint4* gh = (const uint4*)(g_wbh + slot * 32768);
    uint4* bh = (uint4*)(sm + SM_BH);
    for (int i = tid; i < 2048; i += 256) bh[i] = gh[i];
}

// stage full-K A tile (dense rows from X, guarded)
__device__ __forceinline__ void stage_full(char* sm, int tid, const float* X,
                                           int r0, int limit) {
#pragma unroll
    for (int i = 0; i < 8; i++) {
        int u = tid + i * 256;
        int row = u >> 4, ch = u & 15;
        int g = r0 + row;
        float4 v0 = make_float4(0.f, 0.f, 0.f, 0.f), v1 = v0;
        if (g < limit) {
            v0 = ((const float4*)X)[(size_t)g * 32 + ch * 2];
            v1 = ((const float4*)X)[(size_t)g * 32 + ch * 2 + 1];
        }
        uint4 hi; cvt8s(v0, v1, hi);
        *(uint4*)(sm + SM_AH + soff(row, ch * 8)) = hi;
    }
}

// ================= prep: zero scratch + weight fp16/swizzle =================
__global__ void k_prep(const float* W0, const float* W1, const float* W2, const float* W3,
                       const float* W4, const float* W5, const float* W6, const float* W7,
                       const float* W8, const float* WT) {
    const float* Wp[9] = {W0, W1, W2, W3, W4, W5, W6, W7, W8};
    int i = blockIdx.x * blockDim.x + threadIdx.x;
    int stride = gridDim.x * blockDim.x;
    for (int t = i; t < NN * DD; t += stride) g_facc[t] = 0.f;
    for (int t = i; t < NN; t += stride) g_cnt0[t] = 0;
    if (i == 0) g_mcount = 0;
    for (int t = i; t < 11 * 2048; t += stride) {
        int slot = t >> 11, r = t & 2047;
        int n = r >> 4, k8 = r & 15;
        const float* srcp;
        if (slot < 9) srcp = Wp[slot] + n * 128 + k8 * 8;
        else if (slot == 9) srcp = WT + n * 256 + k8 * 8;
        else srcp = WT + n * 256 + 128 + k8 * 8;
        float4 v0 = ((const float4*)srcp)[0];
        float4 v1 = ((const float4*)srcp)[1];
        uint4 hi; cvt8s(v0, v1, hi);
        uint32_t off = (uint32_t)slot * 32768u + soff(n, k8 * 8);
        *reinterpret_cast<uint4*>(g_wbh + off) = hi;
    }
}

__global__ void k_count(const int* __restrict__ smask, const int* __restrict__ dst) {
    int e = blockIdx.x * 256 + threadIdx.x;
    int lane = threadIdx.x & 31;
    int sm_ = smask[e];
    int d_ = dst[e];
    unsigned bal = __ballot_sync(0xffffffffu, sm_ == 1);
    if (sm_ == 0) atomicAdd(&g_cnt0[d_], 1);
    int lead = bal ? (__ffs(bal) - 1) : 0;
    int basec = 0;
    if (bal && lane == lead) basec = atomicAdd(&g_mcount, __popc(bal));
    basec = __shfl_sync(0xffffffffu, basec, lead);
    if (sm_ == 1) g_mlist[basec + __popc(bal & ((1u << lane) - 1u))] = e;
}

// ================= node GEMMs: persistent, 9 uniform jobs =================
__global__ void __launch_bounds__(256, 2)
k_nodeg(const float* __restrict__ h, const float* __restrict__ p,
        const float* __restrict__ dv,
        const float* bV1, const float* bV2, const float* bP1,
        const float* bP2, const float* bP3, const float* bD1,
        const float* bD2, const float* bT) {
    extern __shared__ char sm[];
    uint32_t smb = smem_u32(sm);
    int tid = threadIdx.x, lane = tid & 31, wid = tid >> 5;
    int wm = wid & 3, wn = wid >> 2;
    int pidx = blockIdx.x % 9;
    int nct = (gridDim.x - 1 - pidx) / 9 + 1;

    const float* X;
    const float* bias;
    int slot;
    switch (pidx) {
        case 0: X = h;  slot = 0;  bias = bV1; break;
        case 1: X = h;  slot = 1;  bias = bV2; break;
        case 2: X = p;  slot = 2;  bias = bP1; break;
        case 3: X = p;  slot = 3;  bias = bP2; break;
        case 4: X = p;  slot = 4;  bias = bP3; break;
        case 5: X = dv; slot = 5;  bias = bD1; break;
        case 6: X = dv; slot = 6;  bias = bD2; break;
        case 7: X = h;  slot = 9;  bias = bT; break;
        default: X = dv; slot = 10; bias = g_bzero; break;
    }
    if (tid < 128) ((float*)(sm + SM_BIAS))[tid] = bias[tid];
    copy_B(sm, slot, tid);
    float* outp = g_proj[pidx];
    int q = lane >> 2, m = lane & 3;

    for (int t = blockIdx.x / 9; t < NTILE_N; t += nct) {
        int r0 = t * 128;
        __syncthreads();
        stage_full(sm, tid, X, r0, NN);
        // register-free L2 prefetch of next tile's X rows
        {
            int t2 = t + nct;
            if (t2 < NTILE_N) {
                const char* nb = (const char*)(X + (size_t)t2 * 128 * DD);
                int lines = min(128 * 4, (NN - t2 * 128) * 4);
#pragma unroll
                for (int i = 0; i < 2; i++) {
                    int ln = tid + i * 256;
                    if (ln < lines) l2_prefetch(nb + (size_t)ln * 128);
                }
            }
        }
        __syncthreads();

        float acc[2][8][4];
#pragma unroll
        for (int mf = 0; mf < 2; mf++)
#pragma unroll
            for (int j = 0; j < 8; j++)
#pragma unroll
                for (int i = 0; i < 4; i++) acc[mf][j][i] = 0.f;
        gemm(smb, lane, wm, wn, acc);

        // register epilogue
        const float* bias_s = (const float*)(sm + SM_BIAS);
#pragma unroll
        for (int mf = 0; mf < 2; mf++) {
            int r1 = r0 + wm * 32 + mf * 16 + q;
            int r2 = r1 + 8;
#pragma unroll
            for (int j = 0; j < 8; j++) {
                int col = wn * 64 + j * 8 + m * 2;
                float b0 = bias_s[col], b1 = bias_s[col + 1];
                if (r1 < NN)
                    *(float2*)&outp[(size_t)r1 * DD + col] =
                        make_float2(acc[mf][j][0] + b0, acc[mf][j][1] + b1);
                if (r2 < NN)
                    *(float2*)&outp[(size_t)r2 * DD + col] =
                        make_float2(acc[mf][j][2] + b0, acc[mf][j][3] + b1);
            }
        }
    }
}

// ================= edge pass A: persistent, resident B, fp16-C epilogue ==========
__global__ void __launch_bounds__(256, 2)
k_edgeA(const float* __restrict__ e_in, const int* __restrict__ src,
        const int* __restrict__ dst, const int* __restrict__ smask,
        const float* __restrict__ bE1, float* __restrict__ e_out) {
    extern __shared__ char sm[];
    uint32_t smb = smem_u32(sm);
    int tid = threadIdx.x, lane = tid & 31, wid = tid >> 5;
    int wm = wid & 3, wn = wid >> 2;
    int q = lane >> 2, m = lane & 3;

    if (tid < 128) ((float*)(sm + SM_BIAS))[tid] = bE1[tid];
    copy_B(sm, 7, tid);
    const float* P1 = g_proj[2];
    const float* P2 = g_proj[3];

    for (int t = blockIdx.x; t < NTILE_E; t += gridDim.x) {
        int e0 = t * 128;
        __syncthreads();
        if (tid < 128) {
            int eg = e0 + tid;
            int si = src[eg], di = dst[eg];
            ((int*)(sm + SM_ROWA))[tid] = si;
            ((int*)(sm + SM_ROWB))[tid] = di;
            ((int*)(sm + SM_ROWC))[tid] = smask[eg];
            // prefetch gathered P1/P2 rows (consumed after the GEMM)
            const char* pp1 = (const char*)(P1 + (size_t)di * DD);
            const char* pp2 = (const char*)(P2 + (size_t)si * DD);
#pragma unroll
            for (int l = 0; l < 4; l++) {
                l2_prefetch(pp1 + l * 128);
                l2_prefetch(pp2 + l * 128);
            }
        }
        stage_full(sm, tid, e_in, e0, EE);
        // register-free L2 prefetch of next tile's e_in
        {
            int t2 = t + gridDim.x;
            if (t2 < NTILE_E) {
                const char* nb = (const char*)(e_in + (size_t)t2 * 128 * DD);
#pragma unroll
                for (int i = 0; i < 2; i++)
                    l2_prefetch(nb + (size_t)(tid + i * 256) * 128);
            }
        }
        __syncthreads();

        float acc[2][8][4];
#pragma unroll
        for (int mf = 0; mf < 2; mf++)
#pragma unroll
            for (int j = 0; j < 8; j++)
#pragma unroll
                for (int i = 0; i < 4; i++) acc[mf][j][i] = 0.f;
        gemm(smb, lane, wm, wn, acc);
        __syncthreads();

        // store C as fp16 (128 rows x 256B in SM_CH)
#pragma unroll
        for (int mf = 0; mf < 2; mf++) {
            int r1 = wm * 32 + mf * 16 + q;
#pragma unroll
            for (int j = 0; j < 8; j++) {
                int col = wn * 64 + j * 8 + m * 2;
                int gs = col >> 2;
                uint32_t inoff = (uint32_t)((m & 1) * 4);
                *(uint32_t*)(sm + coff16(r1, gs) + inoff) =
                    pack2h(__float2half_rn(acc[mf][j][0]), __float2half_rn(acc[mf][j][1]));
                *(uint32_t*)(sm + coff16(r1 + 8, gs) + inoff) =
                    pack2h(__float2half_rn(acc[mf][j][2]), __float2half_rn(acc[mf][j][3]));
            }
        }
        __syncthreads();

        const float* bias_s = (const float*)(sm + SM_BIAS);
        const int* ssrc = (const int*)(sm + SM_ROWA);
        const int* sdst = (const int*)(sm + SM_ROWB);
        const int* smsk = (const int*)(sm + SM_ROWC);
        for (int u = tid; u < 4096; u += 256) {
            int lr = u >> 5, c4 = u & 31;   // c4 == lane, lr warp-uniform
            int eg = e0 + lr;
            int si = ssrc[lr], di = sdst[lr], msk = smsk[lr];
            uint2 ch16 = *(uint2*)(sm + coff16(lr, c4));
            float2 cc0 = __half22float2(*reinterpret_cast<__half2*>(&ch16.x));
            float2 cc1 = __half22float2(*reinterpret_cast<__half2*>(&ch16.y));
            float4 bv = *(const float4*)&bias_s[c4 * 4];
            float4 p1 = *(const float4*)&P1[(size_t)di * DD + c4 * 4];
            float4 p2 = *(const float4*)&P2[(size_t)si * DD + c4 * 4];
            float4 ev = *(const float4*)&e_in[(size_t)eg * DD + c4 * 4];
            float4 en;
            en.x = 0.5f * (p1.x - p2.x + cc0.x + bv.x);
            en.y = 0.5f * (p1.y - p2.y + cc0.y + bv.y);
            en.z = 0.5f * (p1.z - p2.z + cc1.x + bv.z);
            en.w = 0.5f * (p1.w - p2.w + cc1.y + bv.w);
            float4 o;
            o.x = ev.x + lrelu(en.x);
            o.y = ev.y + lrelu(en.y);
            o.z = ev.z + lrelu(en.z);
            o.w = ev.w + lrelu(en.w);
            *(float4*)&e_out[(size_t)eg * DD + c4 * 4] = o;
            if (msk) {  // warp-uniform branch: norms + enew only for masked rows
                uint2 eh;
                eh.x = pack2h(__float2half_rn(en.x), __float2half_rn(en.y));
                eh.y = pack2h(__float2half_rn(en.z), __float2half_rn(en.w));
                *(uint2*)&g_enew[(size_t)eg * DD + c4 * 4] = eh;
                float sq = en.x * en.x + en.y * en.y + en.z * en.z + en.w * en.w;
#pragma unroll
                for (int off = 16; off > 0; off >>= 1)
                    sq += __shfl_xor_sync(0xffffffffu, sq, off);
                if (c4 == 0) g_enorm[eg] = sqrtf(sq);
            }
        }
    }
}

// ================= edge pass B: persistent, resident B, masked V GEMM =============
__global__ void __launch_bounds__(256, 2)
k_edgeB(const float* __restrict__ h, const float* __restrict__ bV,
        const int* __restrict__ src, const int* __restrict__ dst) {
    extern __shared__ char sm[];
    uint32_t smb = smem_u32(sm);
    int tid = threadIdx.x, lane = tid & 31, wid = tid >> 5;
    int wm = wid & 3, wn = wid >> 2;
    int q = lane >> 2, m = lane & 3;
    int mc = g_mcount;
    int ntiles = (mc + 127) >> 7;

    if (tid < 128) ((float*)(sm + SM_BIAS))[tid] = bV[tid];
    copy_B(sm, 8, tid);
    int* seid = (int*)(sm + SM_ROWC);
    int* ssrc = (int*)(sm + SM_ROWA);
    int* sdst = (int*)(sm + SM_ROWB);
    const float* bias_s = (const float*)(sm + SM_BIAS);
    float* svb = (float*)(sm + SM_SV);

    for (int t = blockIdx.x; t < ntiles; t += gridDim.x) {
        int base = t * 128;
        int nt = min(128, mc - base);
        __syncthreads();
        if (tid < 128) {
            int eid = (tid < nt) ? g_mlist[base + tid] : -1;
            seid[tid] = eid;
            ssrc[tid] = (eid >= 0) ? src[eid] : 0;
            sdst[tid] = (eid >= 0) ? dst[eid] : 0;
            if (eid >= 0) {   // prefetch enew fp16 row (consumed after GEMM)
                const char* pe = (const char*)(g_enew + (size_t)eid * DD);
                l2_prefetch(pe);
                l2_prefetch(pe + 128);
            }
        }
        __syncthreads();

        // stage full-K A = h[src]*h[dst]
#pragma unroll
        for (int i = 0; i < 8; i++) {
            int u = tid + i * 256;
            int row = u >> 4, ch = u & 15;
            float4 v0 = make_float4(0.f, 0.f, 0.f, 0.f), v1 = v0;
            if (row < nt) {
                float4 hs0 = ((const float4*)h)[(size_t)ssrc[row] * 32 + ch * 2];
                float4 hs1 = ((const float4*)h)[(size_t)ssrc[row] * 32 + ch * 2 + 1];
                float4 hd0 = ((const float4*)h)[(size_t)sdst[row] * 32 + ch * 2];
                float4 hd1 = ((const float4*)h)[(size_t)sdst[row] * 32 + ch * 2 + 1];
                v0.x = hs0.x * hd0.x; v0.y = hs0.y * hd0.y;
                v0.z = hs0.z * hd0.z; v0.w = hs0.w * hd0.w;
                v1.x = hs1.x * hd1.x; v1.y = hs1.y * hd1.y;
                v1.z = hs1.z * hd1.z; v1.w = hs1.w * hd1.w;
            }
            uint4 hi; cvt8s(v0, v1, hi);
            *(uint4*)(sm + SM_AH + soff(row, ch * 8)) = hi;
        }
        __syncthreads();

        float acc[2][8][4];
#pragma unroll
        for (int mf = 0; mf < 2; mf++)
#pragma unroll
            for (int j = 0; j < 8; j++)
#pragma unroll
                for (int i = 0; i < 4; i++) acc[mf][j][i] = 0.f;
        gemm(smb, lane, wm, wn, acc);

        float s0[2] = {0.f, 0.f}, s1[2] = {0.f, 0.f};
#pragma unroll
        for (int mf = 0; mf < 2; mf++)
#pragma unroll
            for (int j = 0; j < 8; j++) {
                float b0 = bias_s[wn * 64 + j * 8 + m * 2];
                float b1 = bias_s[wn * 64 + j * 8 + m * 2 + 1];
                s0[mf] += relu_(acc[mf][j][0] + b0) + relu_(acc[mf][j][1] + b1);
                s1[mf] += relu_(acc[mf][j][2] + b0) + relu_(acc[mf][j][3] + b1);
            }
#pragma unroll
        for (int mf = 0; mf < 2; mf++) {
            s0[mf] += __shfl_xor_sync(0xffffffffu, s0[mf], 1);
            s0[mf] += __shfl_xor_sync(0xffffffffu, s0[mf], 2);
            s1[mf] += __shfl_xor_sync(0xffffffffu, s1[mf], 1);
            s1[mf] += __shfl_xor_sync(0xffffffffu, s1[mf], 2);
        }
        if (m == 0) {
#pragma unroll
            for (int mf = 0; mf < 2; mf++) {
                svb[wn * 128 + wm * 32 + mf * 16 + q] = s0[mf];
                svb[wn * 128 + wm * 32 + mf * 16 + q + 8] = s1[mf];
            }
        }
        __syncthreads();

        // per-edge coefficient into smem
        if (tid < 128) {
            float cf = 0.f;
            if (tid < nt) {
                float sv = svb[tid] + svb[128 + tid];
                float L = g_enorm[seid[tid]];
                if (L > 1e-9f && sv > 0.f) {
                    float r = 0.5f * sqrtf(L);
                    cf = sv * expf(-r / 0.3f) / (1.2f * L * sqrtf(L));
                }
            }
            svb[256 + tid] = cf;
        }
        __syncthreads();

        // cooperative scatter: 256 threads, one float4 chunk each, v4 reductions
        const float* scf = svb + 256;
        for (int u = tid; u < 4096; u += 256) {
            int e = u >> 5, c4 = u & 31;
            float cf = scf[e];
            if (cf != 0.f) {
                int eid = seid[e];
                uint2 eh = *(const uint2*)&g_enew[(size_t)eid * DD + c4 * 4];
                float2 f0 = __half22float2(*reinterpret_cast<__half2*>(&eh.x));
                float2 f1 = __half22float2(*reinterpret_cast<__half2*>(&eh.y));
                float* fp = &g_facc[(size_t)sdst[e] * DD + c4 * 4];
                asm volatile(
                    "red.global.add.v4.f32 [%0], {%1, %2, %3, %4};"
                    :: "l"(fp), "f"(cf * f0.x), "f"(cf * f0.y),
                       "f"(cf * f1.x), "f"(cf * f1.y)
                    : "memory");
            }
        }
    }
}

// ================= node finalize =================
__global__ void k_final(const float* __restrict__ h, const float* __restrict__ p,
                        const float* __restrict__ dv, const float* __restrict__ dt,
                        float* __restrict__ out) {
    int w = threadIdx.x >> 5, l = threadIdx.x & 31;
    int n = blockIdx.x * 8 + w;
    int ix = n * 32 + l;
    const float4* V1 = (const float4*)g_proj[0];
    const float4* V2 = (const float4*)g_proj[1];
    const float4* P3 = (const float4*)g_proj[4];
    const float4* D1 = (const float4*)g_proj[5];
    const float4* D2 = (const float4*)g_proj[6];
    const float4* TA = (const float4*)g_proj[7];
    const float4* TB = (const float4*)g_proj[8];
    const float4* FA = (const float4*)g_facc;

    float4 v1 = V1[ix], v2 = V2[ix], p3 = P3[ix], d1 = D1[ix], d2 = D2[ix];
    float4 ta = TA[ix], tb = TB[ix], fa = FA[ix];
    float cnt = (float)g_cnt0[n];

    float4 th;
    th.x = ta.x + tb.x; th.y = ta.y + tb.y;
    th.z = ta.z + tb.z; th.w = ta.w + tb.w;

    float4 f;
    f.x = (d1.x - v1.x) * (cnt * relu_(th.x)) + fa.x;
    f.y = (d1.y - v1.y) * (cnt * relu_(th.y)) + fa.y;
    f.z = (d1.z - v1.z) * (cnt * relu_(th.z)) + fa.z;
    f.w = (d1.w - v1.w) * (cnt * relu_(th.w)) + fa.w;

    float sq = f.x * f.x + f.y * f.y + f.z * f.z + f.w * f.w;
#pragma unroll
    for (int off = 16; off > 0; off >>= 1) sq += __shfl_xor_sync(0xffffffffu, sq, off);
    float inv = 1.f / (sqrtf(sq) + 1e-9f);

    float dtv = dt[n];
    float dtp = dtv + 0.5f * dtv * dtv;

    float4 hv = ((const float4*)h)[ix];
    float4 pv = ((const float4*)p)[ix];
    float4 dvv = ((const float4*)dv)[ix];

    float4 ho, po, dq;
    ho.x = hv.x + lrelu(v2.x + f.x * dtv);
    ho.y = hv.y + lrelu(v2.y + f.y * dtv);
    ho.z = hv.z + lrelu(v2.z + f.z * dtv);
    ho.w = hv.w + lrelu(v2.w + f.w * dtv);
    po.x = pv.x + lrelu(p3.x + f.x * dtp);
    po.y = pv.y + lrelu(p3.y + f.y * dtp);
    po.z = pv.z + lrelu(p3.z + f.z * dtp);
    po.w = pv.w + lrelu(p3.w + f.w * dtp);
    dq.x = dvv.x + lrelu(d2.x + f.x * inv);
    dq.y = dvv.y + lrelu(d2.y + f.y * inv);
    dq.z = dvv.z + lrelu(d2.z + f.z * inv);
    dq.w = dvv.w + lrelu(d2.w + f.w * inv);

    float4* outH = (float4*)out;
    float4* outP = (float4*)(out + (size_t)NN * DD + (size_t)EE * DD);
    float4* outD = (float4*)(out + 2 * (size_t)NN * DD + (size_t)EE * DD);
    outH[ix] = ho;
    outP[ix] = po;
    outD[ix] = dq;
}

// ================= launch =================
extern "C" void kernel_launch(void* const* d_in, const int* in_sizes, int n_in,
                              void* d_out, int out_size) {
    const float* h   = (const float*)d_in[0];
    const float* e   = (const float*)d_in[1];
    const float* p   = (const float*)d_in[2];
    const float* dv  = (const float*)d_in[3];
    const float* dt  = (const float*)d_in[4];
    const int* smask = (const int*)d_in[5];
    const int* src   = (const int*)d_in[6];
    const int* dst   = (const int*)d_in[7];
    const float* W_V1 = (const float*)d_in[8],  *b_V1 = (const float*)d_in[9];
    const float* W_V2 = (const float*)d_in[10], *b_V2 = (const float*)d_in[11];
    const float* W_E1 = (const float*)d_in[12], *b_E1 = (const float*)d_in[13];
    const float* W_P1 = (const float*)d_in[14], *b_P1 = (const float*)d_in[15];
    const float* W_P2 = (const float*)d_in[16], *b_P2 = (const float*)d_in[17];
    const float* W_P3 = (const float*)d_in[18], *b_P3 = (const float*)d_in[19];
    const float* W_D1 = (const float*)d_in[20], *b_D1 = (const float*)d_in[21];
    const float* W_D2 = (const float*)d_in[22], *b_D2 = (const float*)d_in[23];
    const float* W_V  = (const float*)d_in[24], *b_V  = (const float*)d_in[25];
    const float* W_T  = (const float*)d_in[26], *b_T  = (const float*)d_in[27];
    float* out = (float*)d_out;

    cudaFuncSetAttribute(k_nodeg, cudaFuncAttributeMaxDynamicSharedMemorySize, SM_TOTAL);
    cudaFuncSetAttribute(k_edgeA, cudaFuncAttributeMaxDynamicSharedMemorySize, SM_TOTAL);
    cudaFuncSetAttribute(k_edgeB, cudaFuncAttributeMaxDynamicSharedMemorySize, SM_TOTAL);

    k_prep<<<640, 256>>>(W_V1, W_V2, W_P1, W_P2, W_P3, W_D1, W_D2, W_E1, W_V, W_T);
    k_count<<<EE / 256, 256>>>(smask, dst);
    k_nodeg<<<GRID_P, 256, SM_TOTAL>>>(h, p, dv, b_V1, b_V2, b_P1, b_P2, b_P3,
                                       b_D1, b_D2, b_T);
    k_edgeA<<<GRID_P, 256, SM_TOTAL>>>(e, src, dst, smask, b_E1, out + (size_t)NN * DD);
    k_edgeB<<<GRID_P, 256, SM_TOTAL>>>(h, b_V, src, dst);
    k_final<<<NN / 8, 256>>>(h, p, dv, dt, out);
}

// round 16
// speedup vs baseline: 1.6180x; 1.0185x over previous
#include <cuda_runtime.h>
#include <cuda_fp16.h>
#include <cstdint>
#include <math.h>

#define NN 10000
#define EE 320000
#define DD 128
#define NTILE_N 79      /* (NN+127)/128 */
#define NTILE_E 2500    /* EE/128 */
#define GRID_P 296      /* persistent grid: 148 SMs x 2 CTAs */

// ================= static device scratch =================
__device__ float g_proj[9][NN * DD];     // V1h V2h P1h P2h P3h D1h D2h ThA ThB
__device__ __half g_enew[(size_t)EE * DD];   // fp16: feeds fab scatter only
__device__ float g_enorm[EE];
__device__ float g_facc[NN * DD];
__device__ int   g_cnt0[NN];
__device__ int   g_mlist[EE];
__device__ int   g_mcount;
__device__ float g_bzero[DD];            // stays zero (module-load init)
// fp16 weight tiles in swizzled layout (32KB each):
// slots 0..6 node W (V1,V2,P1,P2,P3,D1,D2), 7 E1, 8 V, 9/10 = W_T halves
__device__ __align__(16) unsigned char g_wbh[11 * 32768];

__device__ __forceinline__ float lrelu(float x) { return x > 0.f ? x : 0.01f * x; }
__device__ __forceinline__ float relu_(float x) { return x > 0.f ? x : 0.f; }

__device__ __forceinline__ uint32_t smem_u32(const void* p) {
    uint32_t a;
    asm("{ .reg .u64 t; cvta.to.shared.u64 t, %1; cvt.u32.u64 %0, t; }" : "=r"(a) : "l"(p));
    return a;
}
__device__ __forceinline__ uint32_t pack2h(__half a, __half b) {
    __half2 t; t.x = a; t.y = b;
    return *reinterpret_cast<uint32_t*>(&t);
}
__device__ __forceinline__ void l2_prefetch(const void* p) {
    asm volatile("prefetch.global.L2 [%0];" :: "l"(p));
}

// swizzled byte offset inside a 128x128 fp16 tile: row stride 256B
__device__ __forceinline__ uint32_t soff(int r, int c) {
    return (uint32_t)((r << 8) + ((((c >> 3) ^ (r & 7)) << 4) | ((c & 7) << 1)));
}

__device__ __forceinline__ void ldsm4(uint32_t* r, uint32_t addr) {
    asm volatile("ldmatrix.sync.aligned.m8n8.x4.shared.b16 {%0,%1,%2,%3}, [%4];"
                 : "=r"(r[0]), "=r"(r[1]), "=r"(r[2]), "=r"(r[3]) : "r"(addr));
}
__device__ __forceinline__ void mma16816(float* d, const uint32_t* a,
                                         uint32_t b0, uint32_t b1) {
    asm volatile(
        "mma.sync.aligned.m16n8k16.row.col.f32.f16.f16.f32 "
        "{%0,%1,%2,%3}, {%4,%5,%6,%7}, {%8,%9}, {%0,%1,%2,%3};"
        : "+f"(d[0]), "+f"(d[1]), "+f"(d[2]), "+f"(d[3])
        : "r"(a[0]), "r"(a[1]), "r"(a[2]), "r"(a[3]), "r"(b0), "r"(b1));
}

// convert 8 fp32 -> fp16x2 quad
__device__ __forceinline__ void cvt8s(float4 v0, float4 v1, uint4& hi) {
    hi.x = pack2h(__float2half_rn(v0.x), __float2half_rn(v0.y));
    hi.y = pack2h(__float2half_rn(v0.z), __float2half_rn(v0.w));
    hi.z = pack2h(__float2half_rn(v1.x), __float2half_rn(v1.y));
    hi.w = pack2h(__float2half_rn(v1.z), __float2half_rn(v1.w));
}

// shared memory layout (102400 bytes -> 2 CTAs/SM)
#define SM_BIAS 0
#define SM_ROWA 512
#define SM_ROWB 1024
#define SM_ROWC 1536
#define SM_SV   2048
#define SM_AH   4096                 /* 128x128 fp16 A (32KB) */
#define SM_CH   (4096 + 32768)       /* fp16 C 128rows x 256B (32KB) */
#define SM_BH   (4096 + 65536)       /* 128x128 fp16 B (32KB) RESIDENT */
#define SM_TOTAL (4096 + 98304)

// fp16 C granule-swizzled offset: row r (0..127), 8B-granule g (0..31)
__device__ __forceinline__ uint32_t coff16(int r, int g) {
    return (uint32_t)(SM_CH + (r << 8) + (((g ^ (r & 7)) & 31) << 3));
}

// ---- single-fp16 GEMM over full K=128, warp tile 32(M) x 64(N), 8 warps ----
__device__ __forceinline__ void gemm(uint32_t smb, int lane, int wm, int wn,
                                     float (&acc)[2][8][4]) {
    const int fr = lane & 15;
    const int fc = (lane >> 4) << 3;
    const int m0 = wm * 32;
    const int n0 = wn * 64;
#pragma unroll
    for (int ks = 0; ks < 8; ks++) {
        const int kc = ks * 16 + fc;
        uint32_t aH[2][4], bH[2][4];
        ldsm4(aH[0], smb + SM_AH + soff(m0 + fr, kc));
        ldsm4(aH[1], smb + SM_AH + soff(m0 + 16 + fr, kc));
        ldsm4(bH[0], smb + SM_BH + soff(n0 + fr, kc));
        int cur = 0;
#pragma unroll
        for (int bn = 0; bn < 4; bn++) {
            int nxt = cur ^ 1;
            if (bn < 3)
                ldsm4(bH[nxt], smb + SM_BH + soff(n0 + (bn + 1) * 16 + fr, kc));
#pragma unroll
            for (int mf = 0; mf < 2; mf++) {
                mma16816(acc[mf][2 * bn],     aH[mf], bH[cur][0], bH[cur][2]);
                mma16816(acc[mf][2 * bn + 1], aH[mf], bH[cur][1], bH[cur][3]);
            }
            cur = nxt;
        }
    }
}

__device__ __forceinline__ void copy_B(char* sm, int slot, int tid) {
    const uint4* gh = (const uint4*)(g_wbh + slot * 32768);
    uint4* bh = (uint4*)(sm + SM_BH);
    for (int i = tid; i < 2048; i += 256) bh[i] = gh[i];
}

// stage full-K A tile (dense rows from X, guarded)
__device__ __forceinline__ void stage_full(char* sm, int tid, const float* X,
                                           int r0, int limit) {
#pragma unroll
    for (int i = 0; i < 8; i++) {
        int u = tid + i * 256;
        int row = u >> 4, ch = u & 15;
        int g = r0 + row;
        float4 v0 = make_float4(0.f, 0.f, 0.f, 0.f), v1 = v0;
        if (g < limit) {
            v0 = ((const float4*)X)[(size_t)g * 32 + ch * 2];
            v1 = ((const float4*)X)[(size_t)g * 32 + ch * 2 + 1];
        }
        uint4 hi; cvt8s(v0, v1, hi);
        *(uint4*)(sm + SM_AH + soff(row, ch * 8)) = hi;
    }
}

// ========= prep: zero scratch + weight fp16/swizzle + edge count/compaction ======
__global__ void k_prep(const float* W0, const float* W1, const float* W2, const float* W3,
                       const float* W4, const float* W5, const float* W6, const float* W7,
                       const float* W8, const float* WT,
                       const int* __restrict__ smask, const int* __restrict__ dst) {
    const float* Wp[9] = {W0, W1, W2, W3, W4, W5, W6, W7, W8};
    int i = blockIdx.x * blockDim.x + threadIdx.x;
    int lane = threadIdx.x & 31;
    int stride = gridDim.x * blockDim.x;
    for (int t = i; t < NN * DD; t += stride) g_facc[t] = 0.f;
    for (int t = i; t < NN; t += stride) g_cnt0[t] = 0;
    for (int t = i; t < 11 * 2048; t += stride) {
        int slot = t >> 11, r = t & 2047;
        int n = r >> 4, k8 = r & 15;
        const float* srcp;
        if (slot < 9) srcp = Wp[slot] + n * 128 + k8 * 8;
        else if (slot == 9) srcp = WT + n * 256 + k8 * 8;
        else srcp = WT + n * 256 + 128 + k8 * 8;
        float4 v0 = ((const float4*)srcp)[0];
        float4 v1 = ((const float4*)srcp)[1];
        uint4 hi; cvt8s(v0, v1, hi);
        uint32_t off = (uint32_t)slot * 32768u + soff(n, k8 * 8);
        *reinterpret_cast<uint4*>(g_wbh + off) = hi;
    }
    // edge histogram + compaction (grid-stride; g_cnt0 zeroed above is a
    // different range only when grid covers; use atomic-safe ordering: this
    // kernel zeroes g_cnt0[t] for all t before any thread counts only if
    // the counting loop starts after the zero loop *in every thread* AND
    // inter-thread: each g_cnt0 slot is zeroed by exactly one thread and
    // counted via atomics by others — races possible. So count into the
    // second pass of a separate launch? Keep safe: counting moved to
    // k_count below (still merged file, separate kernel).
}

__global__ void k_count(const int* __restrict__ smask, const int* __restrict__ dst) {
    int e = blockIdx.x * 256 + threadIdx.x;
    int lane = threadIdx.x & 31;
    int sm_ = smask[e];
    int d_ = dst[e];
    unsigned bal = __ballot_sync(0xffffffffu, sm_ == 1);
    if (sm_ == 0) atomicAdd(&g_cnt0[d_], 1);
    int lead = bal ? (__ffs(bal) - 1) : 0;
    int basec = 0;
    if (bal && lane == lead) basec = atomicAdd(&g_mcount, __popc(bal));
    basec = __shfl_sync(0xffffffffu, basec, lead);
    if (sm_ == 1) g_mlist[basec + __popc(bal & ((1u << lane) - 1u))] = e;
}

__global__ void k_zero_mc() { if (threadIdx.x == 0 && blockIdx.x == 0) g_mcount = 0; }

// ================= node GEMMs: persistent, 9 uniform jobs =================
__global__ void __launch_bounds__(256, 2)
k_nodeg(const float* __restrict__ h, const float* __restrict__ p,
        const float* __restrict__ dv,
        const float* bV1, const float* bV2, const float* bP1,
        const float* bP2, const float* bP3, const float* bD1,
        const float* bD2, const float* bT) {
    extern __shared__ char sm[];
    uint32_t smb = smem_u32(sm);
    int tid = threadIdx.x, lane = tid & 31, wid = tid >> 5;
    int wm = wid & 3, wn = wid >> 2;
    int pidx = blockIdx.x % 9;
    int nct = (gridDim.x - 1 - pidx) / 9 + 1;

    const float* X;
    const float* bias;
    int slot;
    switch (pidx) {
        case 0: X = h;  slot = 0;  bias = bV1; break;
        case 1: X = h;  slot = 1;  bias = bV2; break;
        case 2: X = p;  slot = 2;  bias = bP1; break;
        case 3: X = p;  slot = 3;  bias = bP2; break;
        case 4: X = p;  slot = 4;  bias = bP3; break;
        case 5: X = dv; slot = 5;  bias = bD1; break;
        case 6: X = dv; slot = 6;  bias = bD2; break;
        case 7: X = h;  slot = 9;  bias = bT; break;
        default: X = dv; slot = 10; bias = g_bzero; break;
    }
    if (tid < 128) ((float*)(sm + SM_BIAS))[tid] = bias[tid];
    copy_B(sm, slot, tid);
    float* outp = g_proj[pidx];
    int q = lane >> 2, m = lane & 3;

    for (int t = blockIdx.x / 9; t < NTILE_N; t += nct) {
        int r0 = t * 128;
        __syncthreads();
        stage_full(sm, tid, X, r0, NN);
        // register-free L2 prefetch of next tile's X rows
        {
            int t2 = t + nct;
            if (t2 < NTILE_N) {
                const char* nb = (const char*)(X + (size_t)t2 * 128 * DD);
                int lines = min(128 * 4, (NN - t2 * 128) * 4);
#pragma unroll
                for (int i = 0; i < 2; i++) {
                    int ln = tid + i * 256;
                    if (ln < lines) l2_prefetch(nb + (size_t)ln * 128);
                }
            }
        }
        __syncthreads();

        float acc[2][8][4];
#pragma unroll
        for (int mf = 0; mf < 2; mf++)
#pragma unroll
            for (int j = 0; j < 8; j++)
#pragma unroll
                for (int i = 0; i < 4; i++) acc[mf][j][i] = 0.f;
        gemm(smb, lane, wm, wn, acc);

        // register epilogue
        const float* bias_s = (const float*)(sm + SM_BIAS);
#pragma unroll
        for (int mf = 0; mf < 2; mf++) {
            int r1 = r0 + wm * 32 + mf * 16 + q;
            int r2 = r1 + 8;
#pragma unroll
            for (int j = 0; j < 8; j++) {
                int col = wn * 64 + j * 8 + m * 2;
                float b0 = bias_s[col], b1 = bias_s[col + 1];
                if (r1 < NN)
                    *(float2*)&outp[(size_t)r1 * DD + col] =
                        make_float2(acc[mf][j][0] + b0, acc[mf][j][1] + b1);
                if (r2 < NN)
                    *(float2*)&outp[(size_t)r2 * DD + col] =
                        make_float2(acc[mf][j][2] + b0, acc[mf][j][3] + b1);
            }
        }
    }
}

// ================= edge pass A: persistent, resident B, fp16-C epilogue ==========
__global__ void __launch_bounds__(256, 2)
k_edgeA(const float* __restrict__ e_in, const int* __restrict__ src,
        const int* __restrict__ dst, const int* __restrict__ smask,
        const float* __restrict__ bE1, float* __restrict__ e_out) {
    extern __shared__ char sm[];
    uint32_t smb = smem_u32(sm);
    int tid = threadIdx.x, lane = tid & 31, wid = tid >> 5;
    int wm = wid & 3, wn = wid >> 2;
    int q = lane >> 2, m = lane & 3;

    if (tid < 128) ((float*)(sm + SM_BIAS))[tid] = bE1[tid];
    copy_B(sm, 7, tid);
    const float* P1 = g_proj[2];
    const float* P2 = g_proj[3];

    for (int t = blockIdx.x; t < NTILE_E; t += gridDim.x) {
        int e0 = t * 128;
        __syncthreads();
        if (tid < 128) {
            int eg = e0 + tid;
            int si = src[eg], di = dst[eg];
            ((int*)(sm + SM_ROWA))[tid] = si;
            ((int*)(sm + SM_ROWB))[tid] = di;
            ((int*)(sm + SM_ROWC))[tid] = smask[eg];
            // prefetch gathered P1/P2 rows (consumed after the GEMM)
            const char* pp1 = (const char*)(P1 + (size_t)di * DD);
            const char* pp2 = (const char*)(P2 + (size_t)si * DD);
#pragma unroll
            for (int l = 0; l < 4; l++) {
                l2_prefetch(pp1 + l * 128);
                l2_prefetch(pp2 + l * 128);
            }
        }
        stage_full(sm, tid, e_in, e0, EE);
        // register-free L2 prefetch of next tile's e_in
        {
            int t2 = t + gridDim.x;
            if (t2 < NTILE_E) {
                const char* nb = (const char*)(e_in + (size_t)t2 * 128 * DD);
#pragma unroll
                for (int i = 0; i < 2; i++)
                    l2_prefetch(nb + (size_t)(tid + i * 256) * 128);
            }
        }
        __syncthreads();

        float acc[2][8][4];
#pragma unroll
        for (int mf = 0; mf < 2; mf++)
#pragma unroll
            for (int j = 0; j < 8; j++)
#pragma unroll
                for (int i = 0; i < 4; i++) acc[mf][j][i] = 0.f;
        gemm(smb, lane, wm, wn, acc);
        // NOTE: no sync needed — gemm reads AH/BH, C store writes CH (disjoint)

        // store C as fp16 (128 rows x 256B in SM_CH)
#pragma unroll
        for (int mf = 0; mf < 2; mf++) {
            int r1 = wm * 32 + mf * 16 + q;
#pragma unroll
            for (int j = 0; j < 8; j++) {
                int col = wn * 64 + j * 8 + m * 2;
                int gs = col >> 2;
                uint32_t inoff = (uint32_t)((m & 1) * 4);
                *(uint32_t*)(sm + coff16(r1, gs) + inoff) =
                    pack2h(__float2half_rn(acc[mf][j][0]), __float2half_rn(acc[mf][j][1]));
                *(uint32_t*)(sm + coff16(r1 + 8, gs) + inoff) =
                    pack2h(__float2half_rn(acc[mf][j][2]), __float2half_rn(acc[mf][j][3]));
            }
        }
        __syncthreads();

        const float* bias_s = (const float*)(sm + SM_BIAS);
        const int* ssrc = (const int*)(sm + SM_ROWA);
        const int* sdst = (const int*)(sm + SM_ROWB);
        const int* smsk = (const int*)(sm + SM_ROWC);
        for (int u = tid; u < 4096; u += 256) {
            int lr = u >> 5, c4 = u & 31;   // c4 == lane, lr warp-uniform
            int eg = e0 + lr;
            int si = ssrc[lr], di = sdst[lr], msk = smsk[lr];
            uint2 ch16 = *(uint2*)(sm + coff16(lr, c4));
            float2 cc0 = __half22float2(*reinterpret_cast<__half2*>(&ch16.x));
            float2 cc1 = __half22float2(*reinterpret_cast<__half2*>(&ch16.y));
            // ev from the fp16 A tile in smem (replaces global e_in re-read)
            uint2 ah16 = *(uint2*)(sm + SM_AH + soff(lr, c4 * 4));
            float2 ev0 = __half22float2(*reinterpret_cast<__half2*>(&ah16.x));
            float2 ev1 = __half22float2(*reinterpret_cast<__half2*>(&ah16.y));
            float4 bv = *(const float4*)&bias_s[c4 * 4];
            float4 p1 = *(const float4*)&P1[(size_t)di * DD + c4 * 4];
            float4 p2 = *(const float4*)&P2[(size_t)si * DD + c4 * 4];
            float4 en;
            en.x = 0.5f * (p1.x - p2.x + cc0.x + bv.x);
            en.y = 0.5f * (p1.y - p2.y + cc0.y + bv.y);
            en.z = 0.5f * (p1.z - p2.z + cc1.x + bv.z);
            en.w = 0.5f * (p1.w - p2.w + cc1.y + bv.w);
            float4 o;
            o.x = ev0.x + lrelu(en.x);
            o.y = ev0.y + lrelu(en.y);
            o.z = ev1.x + lrelu(en.z);
            o.w = ev1.y + lrelu(en.w);
            *(float4*)&e_out[(size_t)eg * DD + c4 * 4] = o;
            if (msk) {  // warp-uniform branch: norms + enew only for masked rows
                uint2 eh;
                eh.x = pack2h(__float2half_rn(en.x), __float2half_rn(en.y));
                eh.y = pack2h(__float2half_rn(en.z), __float2half_rn(en.w));
                *(uint2*)&g_enew[(size_t)eg * DD + c4 * 4] = eh;
                float sq = en.x * en.x + en.y * en.y + en.z * en.z + en.w * en.w;
#pragma unroll
                for (int off = 16; off > 0; off >>= 1)
                    sq += __shfl_xor_sync(0xffffffffu, sq, off);
                if (c4 == 0) g_enorm[eg] = sqrtf(sq);
            }
        }
    }
}

// ================= edge pass B: persistent, resident B, masked V GEMM =============
__global__ void __launch_bounds__(256, 2)
k_edgeB(const float* __restrict__ h, const float* __restrict__ bV,
        const int* __restrict__ src, const int* __restrict__ dst) {
    extern __shared__ char sm[];
    uint32_t smb = smem_u32(sm);
    int tid = threadIdx.x, lane = tid & 31, wid = tid >> 5;
    int wm = wid & 3, wn = wid >> 2;
    int q = lane >> 2, m = lane & 3;
    int mc = g_mcount;
    int ntiles = (mc + 127) >> 7;

    if (tid < 128) ((float*)(sm + SM_BIAS))[tid] = bV[tid];
    copy_B(sm, 8, tid);
    int* seid = (int*)(sm + SM_ROWC);
    int* ssrc = (int*)(sm + SM_ROWA);
    int* sdst = (int*)(sm + SM_ROWB);
    const float* bias_s = (const float*)(sm + SM_BIAS);
    float* svb = (float*)(sm + SM_SV);

    for (int t = blockIdx.x; t < ntiles; t += gridDim.x) {
        int base = t * 128;
        int nt = min(128, mc - base);
        __syncthreads();
        if (tid < 128) {
            int eid = (tid < nt) ? g_mlist[base + tid] : -1;
            seid[tid] = eid;
            ssrc[tid] = (eid >= 0) ? src[eid] : 0;
            sdst[tid] = (eid >= 0) ? dst[eid] : 0;
            if (eid >= 0) {   // prefetch enew fp16 row (consumed after GEMM)
                const char* pe = (const char*)(g_enew + (size_t)eid * DD);
                l2_prefetch(pe);
                l2_prefetch(pe + 128);
            }
        }
        __syncthreads();

        // stage full-K A = h[src]*h[dst]
#pragma unroll
        for (int i = 0; i < 8; i++) {
            int u = tid + i * 256;
            int row = u >> 4, ch = u & 15;
            float4 v0 = make_float4(0.f, 0.f, 0.f, 0.f), v1 = v0;
            if (row < nt) {
                float4 hs0 = ((const float4*)h)[(size_t)ssrc[row] * 32 + ch * 2];
                float4 hs1 = ((const float4*)h)[(size_t)ssrc[row] * 32 + ch * 2 + 1];
                float4 hd0 = ((const float4*)h)[(size_t)sdst[row] * 32 + ch * 2];
                float4 hd1 = ((const float4*)h)[(size_t)sdst[row] * 32 + ch * 2 + 1];
                v0.x = hs0.x * hd0.x; v0.y = hs0.y * hd0.y;
                v0.z = hs0.z * hd0.z; v0.w = hs0.w * hd0.w;
                v1.x = hs1.x * hd1.x; v1.y = hs1.y * hd1.y;
                v1.z = hs1.z * hd1.z; v1.w = hs1.w * hd1.w;
            }
            uint4 hi; cvt8s(v0, v1, hi);
            *(uint4*)(sm + SM_AH + soff(row, ch * 8)) = hi;
        }
        __syncthreads();

        float acc[2][8][4];
#pragma unroll
        for (int mf = 0; mf < 2; mf++)
#pragma unroll
            for (int j = 0; j < 8; j++)
#pragma unroll
                for (int i = 0; i < 4; i++) acc[mf][j][i] = 0.f;
        gemm(smb, lane, wm, wn, acc);

        float s0[2] = {0.f, 0.f}, s1[2] = {0.f, 0.f};
#pragma unroll
        for (int mf = 0; mf < 2; mf++)
#pragma unroll
            for (int j = 0; j < 8; j++) {
                float b0 = bias_s[wn * 64 + j * 8 + m * 2];
                float b1 = bias_s[wn * 64 + j * 8 + m * 2 + 1];
                s0[mf] += relu_(acc[mf][j][0] + b0) + relu_(acc[mf][j][1] + b1);
                s1[mf] += relu_(acc[mf][j][2] + b0) + relu_(acc[mf][j][3] + b1);
            }
#pragma unroll
        for (int mf = 0; mf < 2; mf++) {
            s0[mf] += __shfl_xor_sync(0xffffffffu, s0[mf], 1);
            s0[mf] += __shfl_xor_sync(0xffffffffu, s0[mf], 2);
            s1[mf] += __shfl_xor_sync(0xffffffffu, s1[mf], 1);
            s1[mf] += __shfl_xor_sync(0xffffffffu, s1[mf], 2);
        }
        if (m == 0) {
#pragma unroll
            for (int mf = 0; mf < 2; mf++) {
                svb[wn * 128 + wm * 32 + mf * 16 + q] = s0[mf];
                svb[wn * 128 + wm * 32 + mf * 16 + q + 8] = s1[mf];
            }
        }
        __syncthreads();

        // per-edge coefficient into smem
        if (tid < 128) {
            float cf = 0.f;
            if (tid < nt) {
                float sv = svb[tid] + svb[128 + tid];
                float L = g_enorm[seid[tid]];
                if (L > 1e-9f && sv > 0.f) {
                    float r = 0.5f * sqrtf(L);
                    cf = sv * expf(-r / 0.3f) / (1.2f * L * sqrtf(L));
                }
            }
            svb[256 + tid] = cf;
        }
        __syncthreads();

        // cooperative scatter: 256 threads, one float4 chunk each, v4 reductions
        const float* scf = svb + 256;
        for (int u = tid; u < 4096; u += 256) {
            int e = u >> 5, c4 = u & 31;
            float cf = scf[e];
            if (cf != 0.f) {
                int eid = seid[e];
                uint2 eh = *(const uint2*)&g_enew[(size_t)eid * DD + c4 * 4];
                float2 f0 = __half22float2(*reinterpret_cast<__half2*>(&eh.x));
                float2 f1 = __half22float2(*reinterpret_cast<__half2*>(&eh.y));
                float* fp = &g_facc[(size_t)sdst[e] * DD + c4 * 4];
                asm volatile(
                    "red.global.add.v4.f32 [%0], {%1, %2, %3, %4};"
                    :: "l"(fp), "f"(cf * f0.x), "f"(cf * f0.y),
                       "f"(cf * f1.x), "f"(cf * f1.y)
                    : "memory");
            }
        }
    }
}

// ================= node finalize =================
__global__ void k_final(const float* __restrict__ h, const float* __restrict__ p,
                        const float* __restrict__ dv, const float* __restrict__ dt,
                        float* __restrict__ out) {
    int w = threadIdx.x >> 5, l = threadIdx.x & 31;
    int n = blockIdx.x * 8 + w;
    int ix = n * 32 + l;
    const float4* V1 = (const float4*)g_proj[0];
    const float4* V2 = (const float4*)g_proj[1];
    const float4* P3 = (const float4*)g_proj[4];
    const float4* D1 = (const float4*)g_proj[5];
    const float4* D2 = (const float4*)g_proj[6];
    const float4* TA = (const float4*)g_proj[7];
    const float4* TB = (const float4*)g_proj[8];
    const float4* FA = (const float4*)g_facc;

    float4 v1 = V1[ix], v2 = V2[ix], p3 = P3[ix], d1 = D1[ix], d2 = D2[ix];
    float4 ta = TA[ix], tb = TB[ix], fa = FA[ix];
    float cnt = (float)g_cnt0[n];

    float4 th;
    th.x = ta.x + tb.x; th.y = ta.y + tb.y;
    th.z = ta.z + tb.z; th.w = ta.w + tb.w;

    float4 f;
    f.x = (d1.x - v1.x) * (cnt * relu_(th.x)) + fa.x;
    f.y = (d1.y - v1.y) * (cnt * relu_(th.y)) + fa.y;
    f.z = (d1.z - v1.z) * (cnt * relu_(th.z)) + fa.z;
    f.w = (d1.w - v1.w) * (cnt * relu_(th.w)) + fa.w;

    float sq = f.x * f.x + f.y * f.y + f.z * f.z + f.w * f.w;
#pragma unroll
    for (int off = 16; off > 0; off >>= 1) sq += __shfl_xor_sync(0xffffffffu, sq, off);
    float inv = 1.f / (sqrtf(sq) + 1e-9f);

    float dtv = dt[n];
    float dtp = dtv + 0.5f * dtv * dtv;

    float4 hv = ((const float4*)h)[ix];
    float4 pv = ((const float4*)p)[ix];
    float4 dvv = ((const float4*)dv)[ix];

    float4 ho, po, dq;
    ho.x = hv.x + lrelu(v2.x + f.x * dtv);
    ho.y = hv.y + lrelu(v2.y + f.y * dtv);
    ho.z = hv.z + lrelu(v2.z + f.z * dtv);
    ho.w = hv.w + lrelu(v2.w + f.w * dtv);
    po.x = pv.x + lrelu(p3.x + f.x * dtp);
    po.y = pv.y + lrelu(p3.y + f.y * dtp);
    po.z = pv.z + lrelu(p3.z + f.z * dtp);
    po.w = pv.w + lrelu(p3.w + f.w * dtp);
    dq.x = dvv.x + lrelu(d2.x + f.x * inv);
    dq.y = dvv.y + lrelu(d2.y + f.y * inv);
    dq.z = dvv.z + lrelu(d2.z + f.z * inv);
    dq.w = dvv.w + lrelu(d2.w + f.w * inv);

    float4* outH = (float4*)out;
    float4* outP = (float4*)(out + (size_t)NN * DD + (size_t)EE * DD);
    float4* outD = (float4*)(out + 2 * (size_t)NN * DD + (size_t)EE * DD);
    outH[ix] = ho;
    outP[ix] = po;
    outD[ix] = dq;
}

// ================= launch =================
extern "C" void kernel_launch(void* const* d_in, const int* in_sizes, int n_in,
                              void* d_out, int out_size) {
    const float* h   = (const float*)d_in[0];
    const float* e   = (const float*)d_in[1];
    const float* p   = (const float*)d_in[2];
    const float* dv  = (const float*)d_in[3];
    const float* dt  = (const float*)d_in[4];
    const int* smask = (const int*)d_in[5];
    const int* src   = (const int*)d_in[6];
    const int* dst   = (const int*)d_in[7];
    const float* W_V1 = (const float*)d_in[8],  *b_V1 = (const float*)d_in[9];
    const float* W_V2 = (const float*)d_in[10], *b_V2 = (const float*)d_in[11];
    const float* W_E1 = (const float*)d_in[12], *b_E1 = (const float*)d_in[13];
    const float* W_P1 = (const float*)d_in[14], *b_P1 = (const float*)d_in[15];
    const float* W_P2 = (const float*)d_in[16], *b_P2 = (const float*)d_in[17];
    const float* W_P3 = (const float*)d_in[18], *b_P3 = (const float*)d_in[19];
    const float* W_D1 = (const float*)d_in[20], *b_D1 = (const float*)d_in[21];
    const float* W_D2 = (const float*)d_in[22], *b_D2 = (const float*)d_in[23];
    const float* W_V  = (const float*)d_in[24], *b_V  = (const float*)d_in[25];
    const float* W_T  = (const float*)d_in[26], *b_T  = (const float*)d_in[27];
    float* out = (float*)d_out;

    cudaFuncSetAttribute(k_nodeg, cudaFuncAttributeMaxDynamicSharedMemorySize, SM_TOTAL);
    cudaFuncSetAttribute(k_edgeA, cudaFuncAttributeMaxDynamicSharedMemorySize, SM_TOTAL);
    cudaFuncSetAttribute(k_edgeB, cudaFuncAttributeMaxDynamicSharedMemorySize, SM_TOTAL);

    k_zero_mc<<<1, 32>>>();
    k_prep<<<640, 256>>>(W_V1, W_V2, W_P1, W_P2, W_P3, W_D1, W_D2, W_E1, W_V, W_T,
                         smask, dst);
    k_count<<<EE / 256, 256>>>(smask, dst);
    k_nodeg<<<GRID_P, 256, SM_TOTAL>>>(h, p, dv, b_V1, b_V2, b_P1, b_P2, b_P3,
                                       b_D1, b_D2, b_T);
    k_edgeA<<<GRID_P, 256, SM_TOTAL>>>(e, src, dst, smask, b_E1, out + (size_t)NN * DD);
    k_edgeB<<<GRID_P, 256, SM_TOTAL>>>(h, b_V, src, dst);
    k_final<<<NN / 8, 256>>>(h, p, dv, dt, out);
}

// round 17
// speedup vs baseline: 1.6849x; 1.0414x over previous
#include <cuda_runtime.h>
#include <cuda_fp16.h>
#include <cstdint>
#include <math.h>

#define NN 10000
#define EE 320000
#define DD 128
#define NTILE_N 79      /* (NN+127)/128 */
#define NTILE_E 2500    /* EE/128 */
#define GRID_P 296      /* persistent grid: 148 SMs x 2 CTAs */

// ================= static device scratch =================
__device__ float g_proj[9][NN * DD];     // V1h V2h (P1h P2h unused) P3h D1h D2h ThA ThB
__device__ __half g_p1h[NN * DD];        // fp16 P1h (edgeA-only consumer)
__device__ __half g_p2h[NN * DD];        // fp16 P2h (edgeA-only consumer)
__device__ __half g_enew[(size_t)EE * DD];   // fp16: feeds fab scatter only
__device__ float g_enorm[EE];
__device__ float g_facc[NN * DD];
__device__ int   g_cnt0[NN];
__device__ int   g_mlist[EE];
__device__ int   g_mcount;
__device__ float g_bzero[DD];            // stays zero (module-load init)
// fp16 weight tiles in swizzled layout (32KB each):
// slots 0..6 node W (V1,V2,P1,P2,P3,D1,D2), 7 E1, 8 V, 9/10 = W_T halves
__device__ __align__(16) unsigned char g_wbh[11 * 32768];

__device__ __forceinline__ float lrelu(float x) { return x > 0.f ? x : 0.01f * x; }
__device__ __forceinline__ float relu_(float x) { return x > 0.f ? x : 0.f; }

__device__ __forceinline__ uint32_t smem_u32(const void* p) {
    uint32_t a;
    asm("{ .reg .u64 t; cvta.to.shared.u64 t, %1; cvt.u32.u64 %0, t; }" : "=r"(a) : "l"(p));
    return a;
}
__device__ __forceinline__ uint32_t pack2h(__half a, __half b) {
    __half2 t; t.x = a; t.y = b;
    return *reinterpret_cast<uint32_t*>(&t);
}
__device__ __forceinline__ void l2_prefetch(const void* p) {
    asm volatile("prefetch.global.L2 [%0];" :: "l"(p));
}

// swizzled byte offset inside a 128x128 fp16 tile: row stride 256B
__device__ __forceinline__ uint32_t soff(int r, int c) {
    return (uint32_t)((r << 8) + ((((c >> 3) ^ (r & 7)) << 4) | ((c & 7) << 1)));
}

__device__ __forceinline__ void ldsm4(uint32_t* r, uint32_t addr) {
    asm volatile("ldmatrix.sync.aligned.m8n8.x4.shared.b16 {%0,%1,%2,%3}, [%4];"
                 : "=r"(r[0]), "=r"(r[1]), "=r"(r[2]), "=r"(r[3]) : "r"(addr));
}
__device__ __forceinline__ void mma16816(float* d, const uint32_t* a,
                                         uint32_t b0, uint32_t b1) {
    asm volatile(
        "mma.sync.aligned.m16n8k16.row.col.f32.f16.f16.f32 "
        "{%0,%1,%2,%3}, {%4,%5,%6,%7}, {%8,%9}, {%0,%1,%2,%3};"
        : "+f"(d[0]), "+f"(d[1]), "+f"(d[2]), "+f"(d[3])
        : "r"(a[0]), "r"(a[1]), "r"(a[2]), "r"(a[3]), "r"(b0), "r"(b1));
}

// convert 8 fp32 -> fp16x2 quad
__device__ __forceinline__ void cvt8s(float4 v0, float4 v1, uint4& hi) {
    hi.x = pack2h(__float2half_rn(v0.x), __float2half_rn(v0.y));
    hi.y = pack2h(__float2half_rn(v0.z), __float2half_rn(v0.w));
    hi.z = pack2h(__float2half_rn(v1.x), __float2half_rn(v1.y));
    hi.w = pack2h(__float2half_rn(v1.z), __float2half_rn(v1.w));
}

// shared memory layout (102400 bytes -> 2 CTAs/SM)
#define SM_BIAS 0
#define SM_ROWA 512
#define SM_ROWB 1024
#define SM_ROWC 1536
#define SM_SV   2048
#define SM_AH   4096                 /* 128x128 fp16 A (32KB) */
#define SM_CH   (4096 + 32768)       /* fp16 C 128rows x 256B (32KB) */
#define SM_BH   (4096 + 65536)       /* 128x128 fp16 B (32KB) RESIDENT */
#define SM_TOTAL (4096 + 98304)

// fp16 C granule-swizzled offset: row r (0..127), 8B-granule g (0..31)
__device__ __forceinline__ uint32_t coff16(int r, int g) {
    return (uint32_t)(SM_CH + (r << 8) + (((g ^ (r & 7)) & 31) << 3));
}

// ---- single-fp16 GEMM over full K=128, warp tile 32(M) x 64(N), 8 warps ----
__device__ __forceinline__ void gemm(uint32_t smb, int lane, int wm, int wn,
                                     float (&acc)[2][8][4]) {
    const int fr = lane & 15;
    const int fc = (lane >> 4) << 3;
    const int m0 = wm * 32;
    const int n0 = wn * 64;
#pragma unroll
    for (int ks = 0; ks < 8; ks++) {
        const int kc = ks * 16 + fc;
        uint32_t aH[2][4], bH[2][4];
        ldsm4(aH[0], smb + SM_AH + soff(m0 + fr, kc));
        ldsm4(aH[1], smb + SM_AH + soff(m0 + 16 + fr, kc));
        ldsm4(bH[0], smb + SM_BH + soff(n0 + fr, kc));
        int cur = 0;
#pragma unroll
        for (int bn = 0; bn < 4; bn++) {
            int nxt = cur ^ 1;
            if (bn < 3)
                ldsm4(bH[nxt], smb + SM_BH + soff(n0 + (bn + 1) * 16 + fr, kc));
#pragma unroll
            for (int mf = 0; mf < 2; mf++) {
                mma16816(acc[mf][2 * bn],     aH[mf], bH[cur][0], bH[cur][2]);
                mma16816(acc[mf][2 * bn + 1], aH[mf], bH[cur][1], bH[cur][3]);
            }
            cur = nxt;
        }
    }
}

__device__ __forceinline__ void copy_B(char* sm, int slot, int tid) {
    const uint4* gh = (const uint4*)(g_wbh + slot * 32768);
    uint4* bh = (uint4*)(sm + SM_BH);
    for (int i = tid; i < 2048; i += 256) bh[i] = gh[i];
}

// stage full-K A tile (dense rows from X, guarded)
__device__ __forceinline__ void stage_full(char* sm, int tid, const float* X,
                                           int r0, int limit) {
#pragma unroll
    for (int i = 0; i < 8; i++) {
        int u = tid + i * 256;
        int row = u >> 4, ch = u & 15;
        int g = r0 + row;
        float4 v0 = make_float4(0.f, 0.f, 0.f, 0.f), v1 = v0;
        if (g < limit) {
            v0 = ((const float4*)X)[(size_t)g * 32 + ch * 2];
            v1 = ((const float4*)X)[(size_t)g * 32 + ch * 2 + 1];
        }
        uint4 hi; cvt8s(v0, v1, hi);
        *(uint4*)(sm + SM_AH + soff(row, ch * 8)) = hi;
    }
}

// ========= prep: zero scratch + weight fp16/swizzle =================
__global__ void k_prep(const float* W0, const float* W1, const float* W2, const float* W3,
                       const float* W4, const float* W5, const float* W6, const float* W7,
                       const float* W8, const float* WT) {
    const float* Wp[9] = {W0, W1, W2, W3, W4, W5, W6, W7, W8};
    int i = blockIdx.x * blockDim.x + threadIdx.x;
    int stride = gridDim.x * blockDim.x;
    for (int t = i; t < NN * DD; t += stride) g_facc[t] = 0.f;
    for (int t = i; t < NN; t += stride) g_cnt0[t] = 0;
    if (i == 0) g_mcount = 0;
    for (int t = i; t < 11 * 2048; t += stride) {
        int slot = t >> 11, r = t & 2047;
        int n = r >> 4, k8 = r & 15;
        const float* srcp;
        if (slot < 9) srcp = Wp[slot] + n * 128 + k8 * 8;
        else if (slot == 9) srcp = WT + n * 256 + k8 * 8;
        else srcp = WT + n * 256 + 128 + k8 * 8;
        float4 v0 = ((const float4*)srcp)[0];
        float4 v1 = ((const float4*)srcp)[1];
        uint4 hi; cvt8s(v0, v1, hi);
        uint32_t off = (uint32_t)slot * 32768u + soff(n, k8 * 8);
        *reinterpret_cast<uint4*>(g_wbh + off) = hi;
    }
}

// ================= node GEMMs: persistent, 9 uniform jobs + edge count ===========
__global__ void __launch_bounds__(256, 2)
k_nodeg(const float* __restrict__ h, const float* __restrict__ p,
        const float* __restrict__ dv,
        const float* bV1, const float* bV2, const float* bP1,
        const float* bP2, const float* bP3, const float* bD1,
        const float* bD2, const float* bT,
        const int* __restrict__ smask, const int* __restrict__ dstp) {
    extern __shared__ char sm[];
    uint32_t smb = smem_u32(sm);
    int tid = threadIdx.x, lane = tid & 31, wid = tid >> 5;
    int wm = wid & 3, wn = wid >> 2;
    int pidx = blockIdx.x % 9;
    int nct = (gridDim.x - 1 - pidx) / 9 + 1;

    // ---- edge histogram + compaction (was k_count); padded bound keeps ballots
    // convergent. g_cnt0/g_mcount zeroed by k_prep (prior launch). ----
    {
        int stride = gridDim.x * 256;
        int total = ((EE + stride - 1) / stride) * stride;
        for (int e0 = blockIdx.x * 256 + tid; e0 < total; e0 += stride) {
            bool valid = e0 < EE;
            int sm_ = valid ? smask[e0] : 0;
            int d_ = valid ? dstp[e0] : 0;
            unsigned bal = __ballot_sync(0xffffffffu, valid && sm_ == 1);
            if (valid && sm_ == 0) atomicAdd(&g_cnt0[d_], 1);
            int lead = bal ? (__ffs(bal) - 1) : 0;
            int basec = 0;
            if (bal && lane == lead) basec = atomicAdd(&g_mcount, __popc(bal));
            basec = __shfl_sync(0xffffffffu, basec, lead);
            if (valid && sm_ == 1)
                g_mlist[basec + __popc(bal & ((1u << lane) - 1u))] = e0;
        }
    }

    const float* X;
    const float* bias;
    int slot;
    switch (pidx) {
        case 0: X = h;  slot = 0;  bias = bV1; break;
        case 1: X = h;  slot = 1;  bias = bV2; break;
        case 2: X = p;  slot = 2;  bias = bP1; break;
        case 3: X = p;  slot = 3;  bias = bP2; break;
        case 4: X = p;  slot = 4;  bias = bP3; break;
        case 5: X = dv; slot = 5;  bias = bD1; break;
        case 6: X = dv; slot = 6;  bias = bD2; break;
        case 7: X = h;  slot = 9;  bias = bT; break;
        default: X = dv; slot = 10; bias = g_bzero; break;
    }
    if (tid < 128) ((float*)(sm + SM_BIAS))[tid] = bias[tid];
    copy_B(sm, slot, tid);
    float* outp = g_proj[pidx];
    __half* outh = (pidx == 2) ? g_p1h : g_p2h;   // used only when pidx==2||3
    int fp16out = (pidx == 2 || pidx == 3);
    int q = lane >> 2, m = lane & 3;

    for (int t = blockIdx.x / 9; t < NTILE_N; t += nct) {
        int r0 = t * 128;
        __syncthreads();
        stage_full(sm, tid, X, r0, NN);
        // register-free L2 prefetch of next tile's X rows
        {
            int t2 = t + nct;
            if (t2 < NTILE_N) {
                const char* nb = (const char*)(X + (size_t)t2 * 128 * DD);
                int lines = min(128 * 4, (NN - t2 * 128) * 4);
#pragma unroll
                for (int i = 0; i < 2; i++) {
                    int ln = tid + i * 256;
                    if (ln < lines) l2_prefetch(nb + (size_t)ln * 128);
                }
            }
        }
        __syncthreads();

        float acc[2][8][4];
#pragma unroll
        for (int mf = 0; mf < 2; mf++)
#pragma unroll
            for (int j = 0; j < 8; j++)
#pragma unroll
                for (int i = 0; i < 4; i++) acc[mf][j][i] = 0.f;
        gemm(smb, lane, wm, wn, acc);

        // register epilogue (fp32, or fp16 for P1h/P2h which only edgeA reads)
        const float* bias_s = (const float*)(sm + SM_BIAS);
#pragma unroll
        for (int mf = 0; mf < 2; mf++) {
            int r1 = r0 + wm * 32 + mf * 16 + q;
            int r2 = r1 + 8;
#pragma unroll
            for (int j = 0; j < 8; j++) {
                int col = wn * 64 + j * 8 + m * 2;
                float b0 = bias_s[col], b1 = bias_s[col + 1];
                float o00 = acc[mf][j][0] + b0, o01 = acc[mf][j][1] + b1;
                float o10 = acc[mf][j][2] + b0, o11 = acc[mf][j][3] + b1;
                if (fp16out) {
                    if (r1 < NN)
                        *(uint32_t*)&outh[(size_t)r1 * DD + col] =
                            pack2h(__float2half_rn(o00), __float2half_rn(o01));
                    if (r2 < NN)
                        *(uint32_t*)&outh[(size_t)r2 * DD + col] =
                            pack2h(__float2half_rn(o10), __float2half_rn(o11));
                } else {
                    if (r1 < NN)
                        *(float2*)&outp[(size_t)r1 * DD + col] = make_float2(o00, o01);
                    if (r2 < NN)
                        *(float2*)&outp[(size_t)r2 * DD + col] = make_float2(o10, o11);
                }
            }
        }
    }
}

// ================= edge pass A: persistent, resident B, fp16-C epilogue ==========
__global__ void __launch_bounds__(256, 2)
k_edgeA(const float* __restrict__ e_in, const int* __restrict__ src,
        const int* __restrict__ dst, const int* __restrict__ smask,
        const float* __restrict__ bE1, float* __restrict__ e_out) {
    extern __shared__ char sm[];
    uint32_t smb = smem_u32(sm);
    int tid = threadIdx.x, lane = tid & 31, wid = tid >> 5;
    int wm = wid & 3, wn = wid >> 2;
    int q = lane >> 2, m = lane & 3;

    if (tid < 128) ((float*)(sm + SM_BIAS))[tid] = bE1[tid];
    copy_B(sm, 7, tid);

    for (int t = blockIdx.x; t < NTILE_E; t += gridDim.x) {
        int e0 = t * 128;
        __syncthreads();
        if (tid < 128) {
            int eg = e0 + tid;
            int si = src[eg], di = dst[eg];
            ((int*)(sm + SM_ROWA))[tid] = si;
            ((int*)(sm + SM_ROWB))[tid] = di;
            ((int*)(sm + SM_ROWC))[tid] = smask[eg];
            // prefetch gathered fp16 P1/P2 rows (256B each, consumed after GEMM)
            const char* pp1 = (const char*)(g_p1h + (size_t)di * DD);
            const char* pp2 = (const char*)(g_p2h + (size_t)si * DD);
            l2_prefetch(pp1); l2_prefetch(pp1 + 128);
            l2_prefetch(pp2); l2_prefetch(pp2 + 128);
        }
        stage_full(sm, tid, e_in, e0, EE);
        // register-free L2 prefetch of next tile's e_in
        {
            int t2 = t + gridDim.x;
            if (t2 < NTILE_E) {
                const char* nb = (const char*)(e_in + (size_t)t2 * 128 * DD);
#pragma unroll
                for (int i = 0; i < 2; i++)
                    l2_prefetch(nb + (size_t)(tid + i * 256) * 128);
            }
        }
        __syncthreads();

        float acc[2][8][4];
#pragma unroll
        for (int mf = 0; mf < 2; mf++)
#pragma unroll
            for (int j = 0; j < 8; j++)
#pragma unroll
                for (int i = 0; i < 4; i++) acc[mf][j][i] = 0.f;
        gemm(smb, lane, wm, wn, acc);
        // no sync needed — gemm reads AH/BH, C store writes CH (disjoint)

        // store C as fp16 (128 rows x 256B in SM_CH)
#pragma unroll
        for (int mf = 0; mf < 2; mf++) {
            int r1 = wm * 32 + mf * 16 + q;
#pragma unroll
            for (int j = 0; j < 8; j++) {
                int col = wn * 64 + j * 8 + m * 2;
                int gs = col >> 2;
                uint32_t inoff = (uint32_t)((m & 1) * 4);
                *(uint32_t*)(sm + coff16(r1, gs) + inoff) =
                    pack2h(__float2half_rn(acc[mf][j][0]), __float2half_rn(acc[mf][j][1]));
                *(uint32_t*)(sm + coff16(r1 + 8, gs) + inoff) =
                    pack2h(__float2half_rn(acc[mf][j][2]), __float2half_rn(acc[mf][j][3]));
            }
        }
        __syncthreads();

        const float* bias_s = (const float*)(sm + SM_BIAS);
        const int* ssrc = (const int*)(sm + SM_ROWA);
        const int* sdst = (const int*)(sm + SM_ROWB);
        const int* smsk = (const int*)(sm + SM_ROWC);
        for (int u = tid; u < 4096; u += 256) {
            int lr = u >> 5, c4 = u & 31;   // c4 == lane, lr warp-uniform
            int eg = e0 + lr;
            int si = ssrc[lr], di = sdst[lr], msk = smsk[lr];
            uint2 ch16 = *(uint2*)(sm + coff16(lr, c4));
            float2 cc0 = __half22float2(*reinterpret_cast<__half2*>(&ch16.x));
            float2 cc1 = __half22float2(*reinterpret_cast<__half2*>(&ch16.y));
            // ev from the fp16 A tile in smem
            uint2 ah16 = *(uint2*)(sm + SM_AH + soff(lr, c4 * 4));
            float2 ev0 = __half22float2(*reinterpret_cast<__half2*>(&ah16.x));
            float2 ev1 = __half22float2(*reinterpret_cast<__half2*>(&ah16.y));
            float4 bv = *(const float4*)&bias_s[c4 * 4];
            // fp16 P1/P2 gathers (8B per thread)
            uint2 p1h = *(const uint2*)&g_p1h[(size_t)di * DD + c4 * 4];
            uint2 p2h = *(const uint2*)&g_p2h[(size_t)si * DD + c4 * 4];
            float2 p1a = __half22float2(*reinterpret_cast<__half2*>(&p1h.x));
            float2 p1b = __half22float2(*reinterpret_cast<__half2*>(&p1h.y));
            float2 p2a = __half22float2(*reinterpret_cast<__half2*>(&p2h.x));
            float2 p2b = __half22float2(*reinterpret_cast<__half2*>(&p2h.y));
            float4 en;
            en.x = 0.5f * (p1a.x - p2a.x + cc0.x + bv.x);
            en.y = 0.5f * (p1a.y - p2a.y + cc0.y + bv.y);
            en.z = 0.5f * (p1b.x - p2b.x + cc1.x + bv.z);
            en.w = 0.5f * (p1b.y - p2b.y + cc1.y + bv.w);
            float4 o;
            o.x = ev0.x + lrelu(en.x);
            o.y = ev0.y + lrelu(en.y);
            o.z = ev1.x + lrelu(en.z);
            o.w = ev1.y + lrelu(en.w);
            *(float4*)&e_out[(size_t)eg * DD + c4 * 4] = o;
            if (msk) {  // warp-uniform branch: norms + enew only for masked rows
                uint2 eh;
                eh.x = pack2h(__float2half_rn(en.x), __float2half_rn(en.y));
                eh.y = pack2h(__float2half_rn(en.z), __float2half_rn(en.w));
                *(uint2*)&g_enew[(size_t)eg * DD + c4 * 4] = eh;
                float sq = en.x * en.x + en.y * en.y + en.z * en.z + en.w * en.w;
#pragma unroll
                for (int off = 16; off > 0; off >>= 1)
                    sq += __shfl_xor_sync(0xffffffffu, sq, off);
                if (c4 == 0) g_enorm[eg] = sqrtf(sq);
            }
        }
    }
}

// ================= edge pass B: persistent, resident B, masked V GEMM =============
__global__ void __launch_bounds__(256, 2)
k_edgeB(const float* __restrict__ h, const float* __restrict__ bV,
        const int* __restrict__ src, const int* __restrict__ dst) {
    extern __shared__ char sm[];
    uint32_t smb = smem_u32(sm);
    int tid = threadIdx.x, lane = tid & 31, wid = tid >> 5;
    int wm = wid & 3, wn = wid >> 2;
    int q = lane >> 2, m = lane & 3;
    int mc = g_mcount;
    int ntiles = (mc + 127) >> 7;

    if (tid < 128) ((float*)(sm + SM_BIAS))[tid] = bV[tid];
    copy_B(sm, 8, tid);
    int* seid = (int*)(sm + SM_ROWC);
    int* ssrc = (int*)(sm + SM_ROWA);
    int* sdst = (int*)(sm + SM_ROWB);
    const float* bias_s = (const float*)(sm + SM_BIAS);
    float* svb = (float*)(sm + SM_SV);

    for (int t = blockIdx.x; t < ntiles; t += gridDim.x) {
        int base = t * 128;
        int nt = min(128, mc - base);
        __syncthreads();
        if (tid < 128) {
            int eid = (tid < nt) ? g_mlist[base + tid] : -1;
            seid[tid] = eid;
            ssrc[tid] = (eid >= 0) ? src[eid] : 0;
            sdst[tid] = (eid >= 0) ? dst[eid] : 0;
            if (eid >= 0) {   // prefetch enew fp16 row (consumed after GEMM)
                const char* pe = (const char*)(g_enew + (size_t)eid * DD);
                l2_prefetch(pe);
                l2_prefetch(pe + 128);
            }
        }
        __syncthreads();

        // stage full-K A = h[src]*h[dst]
#pragma unroll
        for (int i = 0; i < 8; i++) {
            int u = tid + i * 256;
            int row = u >> 4, ch = u & 15;
            float4 v0 = make_float4(0.f, 0.f, 0.f, 0.f), v1 = v0;
            if (row < nt) {
                float4 hs0 = ((const float4*)h)[(size_t)ssrc[row] * 32 + ch * 2];
                float4 hs1 = ((const float4*)h)[(size_t)ssrc[row] * 32 + ch * 2 + 1];
                float4 hd0 = ((const float4*)h)[(size_t)sdst[row] * 32 + ch * 2];
                float4 hd1 = ((const float4*)h)[(size_t)sdst[row] * 32 + ch * 2 + 1];
                v0.x = hs0.x * hd0.x; v0.y = hs0.y * hd0.y;
                v0.z = hs0.z * hd0.z; v0.w = hs0.w * hd0.w;
                v1.x = hs1.x * hd1.x; v1.y = hs1.y * hd1.y;
                v1.z = hs1.z * hd1.z; v1.w = hs1.w * hd1.w;
            }
            uint4 hi; cvt8s(v0, v1, hi);
            *(uint4*)(sm + SM_AH + soff(row, ch * 8)) = hi;
        }
        __syncthreads();

        float acc[2][8][4];
#pragma unroll
        for (int mf = 0; mf < 2; mf++)
#pragma unroll
            for (int j = 0; j < 8; j++)
#pragma unroll
                for (int i = 0; i < 4; i++) acc[mf][j][i] = 0.f;
        gemm(smb, lane, wm, wn, acc);

        float s0[2] = {0.f, 0.f}, s1[2] = {0.f, 0.f};
#pragma unroll
        for (int mf = 0; mf < 2; mf++)
#pragma unroll
            for (int j = 0; j < 8; j++) {
                float b0 = bias_s[wn * 64 + j * 8 + m * 2];
                float b1 = bias_s[wn * 64 + j * 8 + m * 2 + 1];
                s0[mf] += relu_(acc[mf][j][0] + b0) + relu_(acc[mf][j][1] + b1);
                s1[mf] += relu_(acc[mf][j][2] + b0) + relu_(acc[mf][j][3] + b1);
            }
#pragma unroll
        for (int mf = 0; mf < 2; mf++) {
            s0[mf] += __shfl_xor_sync(0xffffffffu, s0[mf], 1);
            s0[mf] += __shfl_xor_sync(0xffffffffu, s0[mf], 2);
            s1[mf] += __shfl_xor_sync(0xffffffffu, s1[mf], 1);
            s1[mf] += __shfl_xor_sync(0xffffffffu, s1[mf], 2);
        }
        if (m == 0) {
#pragma unroll
            for (int mf = 0; mf < 2; mf++) {
                svb[wn * 128 + wm * 32 + mf * 16 + q] = s0[mf];
                svb[wn * 128 + wm * 32 + mf * 16 + q + 8] = s1[mf];
            }
        }
        __syncthreads();

        // per-edge coefficient into smem
        if (tid < 128) {
            float cf = 0.f;
            if (tid < nt) {
                float sv = svb[tid] + svb[128 + tid];
                float L = g_enorm[seid[tid]];
                if (L > 1e-9f && sv > 0.f) {
                    float r = 0.5f * sqrtf(L);
                    cf = sv * expf(-r / 0.3f) / (1.2f * L * sqrtf(L));
                }
            }
            svb[256 + tid] = cf;
        }
        __syncthreads();

        // cooperative scatter: 256 threads, one float4 chunk each, v4 reductions
        const float* scf = svb + 256;
        for (int u = tid; u < 4096; u += 256) {
            int e = u >> 5, c4 = u & 31;
            float cf = scf[e];
            if (cf != 0.f) {
                int eid = seid[e];
                uint2 eh = *(const uint2*)&g_enew[(size_t)eid * DD + c4 * 4];
                float2 f0 = __half22float2(*reinterpret_cast<__half2*>(&eh.x));
                float2 f1 = __half22float2(*reinterpret_cast<__half2*>(&eh.y));
                float* fp = &g_facc[(size_t)sdst[e] * DD + c4 * 4];
                asm volatile(
                    "red.global.add.v4.f32 [%0], {%1, %2, %3, %4};"
                    :: "l"(fp), "f"(cf * f0.x), "f"(cf * f0.y),
                       "f"(cf * f1.x), "f"(cf * f1.y)
                    : "memory");
            }
        }
    }
}

// ================= node finalize =================
__global__ void k_final(const float* __restrict__ h, const float* __restrict__ p,
                        const float* __restrict__ dv, const float* __restrict__ dt,
                        float* __restrict__ out) {
    int w = threadIdx.x >> 5, l = threadIdx.x & 31;
    int n = blockIdx.x * 8 + w;
    int ix = n * 32 + l;
    const float4* V1 = (const float4*)g_proj[0];
    const float4* V2 = (const float4*)g_proj[1];
    const float4* P3 = (const float4*)g_proj[4];
    const float4* D1 = (const float4*)g_proj[5];
    const float4* D2 = (const float4*)g_proj[6];
    const float4* TA = (const float4*)g_proj[7];
    const float4* TB = (const float4*)g_proj[8];
    const float4* FA = (const float4*)g_facc;

    float4 v1 = V1[ix], v2 = V2[ix], p3 = P3[ix], d1 = D1[ix], d2 = D2[ix];
    float4 ta = TA[ix], tb = TB[ix], fa = FA[ix];
    float cnt = (float)g_cnt0[n];

    float4 th;
    th.x = ta.x + tb.x; th.y = ta.y + tb.y;
    th.z = ta.z + tb.z; th.w = ta.w + tb.w;

    float4 f;
    f.x = (d1.x - v1.x) * (cnt * relu_(th.x)) + fa.x;
    f.y = (d1.y - v1.y) * (cnt * relu_(th.y)) + fa.y;
    f.z = (d1.z - v1.z) * (cnt * relu_(th.z)) + fa.z;
    f.w = (d1.w - v1.w) * (cnt * relu_(th.w)) + fa.w;

    float sq = f.x * f.x + f.y * f.y + f.z * f.z + f.w * f.w;
#pragma unroll
    for (int off = 16; off > 0; off >>= 1) sq += __shfl_xor_sync(0xffffffffu, sq, off);
    float inv = 1.f / (sqrtf(sq) + 1e-9f);

    float dtv = dt[n];
    float dtp = dtv + 0.5f * dtv * dtv;

    float4 hv = ((const float4*)h)[ix];
    float4 pv = ((const float4*)p)[ix];
    float4 dvv = ((const float4*)dv)[ix];

    float4 ho, po, dq;
    ho.x = hv.x + lrelu(v2.x + f.x * dtv);
    ho.y = hv.y + lrelu(v2.y + f.y * dtv);
    ho.z = hv.z + lrelu(v2.z + f.z * dtv);
    ho.w = hv.w + lrelu(v2.w + f.w * dtv);
    po.x = pv.x + lrelu(p3.x + f.x * dtp);
    po.y = pv.y + lrelu(p3.y + f.y * dtp);
    po.z = pv.z + lrelu(p3.z + f.z * dtp);
    po.w = pv.w + lrelu(p3.w + f.w * dtp);
    dq.x = dvv.x + lrelu(d2.x + f.x * inv);
    dq.y = dvv.y + lrelu(d2.y + f.y * inv);
    dq.z = dvv.z + lrelu(d2.z + f.z * inv);
    dq.w = dvv.w + lrelu(d2.w + f.w * inv);

    float4* outH = (float4*)out;
    float4* outP = (float4*)(out + (size_t)NN * DD + (size_t)EE * DD);
    float4* outD = (float4*)(out + 2 * (size_t)NN * DD + (size_t)EE * DD);
    outH[ix] = ho;
    outP[ix] = po;
    outD[ix] = dq;
}

// ================= launch =================
extern "C" void kernel_launch(void* const* d_in, const int* in_sizes, int n_in,
                              void* d_out, int out_size) {
    const float* h   = (const float*)d_in[0];
    const float* e   = (const float*)d_in[1];
    const float* p   = (const float*)d_in[2];
    const float* dv  = (const float*)d_in[3];
    const float* dt  = (const float*)d_in[4];
    const int* smask = (const int*)d_in[5];
    const int* src   = (const int*)d_in[6];
    const int* dst   = (const int*)d_in[7];
    const float* W_V1 = (const float*)d_in[8],  *b_V1 = (const float*)d_in[9];
    const float* W_V2 = (const float*)d_in[10], *b_V2 = (const float*)d_in[11];
    const float* W_E1 = (const float*)d_in[12], *b_E1 = (const float*)d_in[13];
    const float* W_P1 = (const float*)d_in[14], *b_P1 = (const float*)d_in[15];
    const float* W_P2 = (const float*)d_in[16], *b_P2 = (const float*)d_in[17];
    const float* W_P3 = (const float*)d_in[18], *b_P3 = (const float*)d_in[19];
    const float* W_D1 = (const float*)d_in[20], *b_D1 = (const float*)d_in[21];
    const float* W_D2 = (const float*)d_in[22], *b_D2 = (const float*)d_in[23];
    const float* W_V  = (const float*)d_in[24], *b_V  = (const float*)d_in[25];
    const float* W_T  = (const float*)d_in[26], *b_T  = (const float*)d_in[27];
    float* out = (float*)d_out;

    cudaFuncSetAttribute(k_nodeg, cudaFuncAttributeMaxDynamicSharedMemorySize, SM_TOTAL);
    cudaFuncSetAttribute(k_edgeA, cudaFuncAttributeMaxDynamicSharedMemorySize, SM_TOTAL);
    cudaFuncSetAttribute(k_edgeB, cudaFuncAttributeMaxDynamicSharedMemorySize, SM_TOTAL);

    k_prep<<<640, 256>>>(W_V1, W_V2, W_P1, W_P2, W_P3, W_D1, W_D2, W_E1, W_V, W_T);
    k_nodeg<<<GRID_P, 256, SM_TOTAL>>>(h, p, dv, b_V1, b_V2, b_P1, b_P2, b_P3,
                                       b_D1, b_D2, b_T, smask, dst);
    k_edgeA<<<GRID_P, 256, SM_TOTAL>>>(e, src, dst, smask, b_E1, out + (size_t)NN * DD);
    k_edgeB<<<GRID_P, 256, SM_TOTAL>>>(h, b_V, src, dst);
    k_final<<<NN / 8, 256>>>(h, p, dv, dt, out);
}